// round 1
// baseline (speedup 1.0000x reference)
#include <cuda_runtime.h>
#include <math_constants.h>

// Problem constants
#define TT 2048
#define CC 1024
#define HH 16
#define DH 64
#define BB 2

// Scratch (no allocations allowed)
__device__ float g_qkv[(size_t)BB * TT * 3 * CC];   // [B*T, 3C]
__device__ float g_y[(size_t)BB * TT * CC];         // [B*T, C]

// ---------------------------------------------------------------------------
// SGEMM with bias: C[M,N] = A[M,K] @ B[K,N] + bias[N]
// 128x128x16 tile, 256 threads, 8x8 per thread.
// ---------------------------------------------------------------------------
#define GBM 128
#define GBN 128
#define GBK 16

__global__ __launch_bounds__(256) void sgemm_bias(
    const float* __restrict__ A, const float* __restrict__ B,
    const float* __restrict__ bias, float* __restrict__ C,
    int M, int N, int K)
{
    __shared__ float As[GBK][GBM + 4];
    __shared__ float Bs[GBK][GBN];

    const int tid = threadIdx.x;
    const int bm = blockIdx.y * GBM;
    const int bn = blockIdx.x * GBN;
    const int tr = (tid >> 4) << 3;   // 0..120, step 8
    const int tc = (tid & 15) << 3;   // 0..120, step 8

    float acc[8][8];
    #pragma unroll
    for (int i = 0; i < 8; i++)
        #pragma unroll
        for (int j = 0; j < 8; j++)
            acc[i][j] = 0.f;

    const float* Ab = A + (size_t)bm * K;
    const float* Bb = B + bn;

    for (int k0 = 0; k0 < K; k0 += GBK) {
        #pragma unroll
        for (int i = 0; i < 2; i++) {
            int id = tid + i * 256;
            // A tile: 128 rows x 16 cols, float4 along K, store transposed
            int ar = id >> 2;
            int ac = (id & 3) << 2;
            float4 av = *(const float4*)(Ab + (size_t)ar * K + k0 + ac);
            As[ac + 0][ar] = av.x;
            As[ac + 1][ar] = av.y;
            As[ac + 2][ar] = av.z;
            As[ac + 3][ar] = av.w;
            // B tile: 16 rows x 128 cols, contiguous float4
            int br = id >> 5;
            int bc = (id & 31) << 2;
            *(float4*)(&Bs[br][bc]) =
                *(const float4*)(Bb + (size_t)(k0 + br) * N + bc);
        }
        __syncthreads();

        #pragma unroll
        for (int k = 0; k < GBK; k++) {
            float a[8], b[8];
            *(float4*)&a[0] = *(float4*)&As[k][tr];
            *(float4*)&a[4] = *(float4*)&As[k][tr + 4];
            *(float4*)&b[0] = *(float4*)&Bs[k][tc];
            *(float4*)&b[4] = *(float4*)&Bs[k][tc + 4];
            #pragma unroll
            for (int i = 0; i < 8; i++)
                #pragma unroll
                for (int j = 0; j < 8; j++)
                    acc[i][j] += a[i] * b[j];
        }
        __syncthreads();
    }

    #pragma unroll
    for (int i = 0; i < 8; i++) {
        float* Crow = C + (size_t)(bm + tr + i) * N + bn + tc;
        #pragma unroll
        for (int j = 0; j < 8; j++)
            acc[i][j] += bias[bn + tc + j];
        *(float4*)Crow = *(float4*)&acc[i][0];
        *(float4*)(Crow + 4) = *(float4*)&acc[i][4];
    }
}

// ---------------------------------------------------------------------------
// Flash attention (causal), fp32.
// Block = one (b, h, q-tile of 64). 128 threads, each owns 4 q-rows x 8 cols.
// Q,K stored transposed in SMEM ([d][row]) for float4 fragment loads.
// ---------------------------------------------------------------------------
#define BQ 64
#define BKV 64
#define QS 68   // stride of qst rows [DH][QS]
#define KS 68   // stride of kst rows [DH][KS]
#define VS 68   // stride of vsm rows [BKV][VS]
#define PS 65   // stride of pst rows [BKV][PS] (odd-ish: conflict-free scalar reads)

#define ATTN_SMEM_FLOATS (DH * QS + DH * KS + BKV * VS + BKV * PS)

__global__ __launch_bounds__(128) void attn_kernel(
    const float* __restrict__ qkv, float* __restrict__ y)
{
    extern __shared__ float sm[];
    float* qst = sm;                  // [DH][QS]  q transposed
    float* kst = qst + DH * QS;       // [DH][KS]  k transposed
    float* vsm = kst + DH * KS;       // [BKV][VS] v natural
    float* pst = vsm + BKV * VS;      // [BKV][PS] p transposed

    const int qt = blockIdx.x;
    const int h  = blockIdx.y;
    const int b  = blockIdx.z;
    const int tid = threadIdx.x;
    const int rg = (tid >> 3) << 2;   // row base 0..60
    const int cg = (tid & 7) << 3;    // col base 0..56

    const float scale = 0.125f;       // 1/sqrt(64)
    const int rowstride = 3 * CC;
    const float* qbase = qkv + (size_t)b * TT * rowstride + h * DH;
    const float* kbase = qbase + CC;
    const float* vbase = qbase + 2 * CC;

    // Load Q tile transposed: qst[d][r]
    for (int i = tid; i < BQ * DH / 4; i += 128) {
        int rr = i & 63;
        int d4 = (i >> 6) << 2;
        float4 v4 = *(const float4*)(qbase + (size_t)(qt * BQ + rr) * rowstride + d4);
        qst[(d4 + 0) * QS + rr] = v4.x;
        qst[(d4 + 1) * QS + rr] = v4.y;
        qst[(d4 + 2) * QS + rr] = v4.z;
        qst[(d4 + 3) * QS + rr] = v4.w;
    }

    float m[4], l[4], o[4][8];
    #pragma unroll
    for (int i = 0; i < 4; i++) {
        m[i] = -CUDART_INF_F;
        l[i] = 0.f;
        #pragma unroll
        for (int j = 0; j < 8; j++) o[i][j] = 0.f;
    }
    __syncthreads();

    for (int kt = 0; kt <= qt; kt++) {
        // Load K transposed
        for (int i = tid; i < BKV * DH / 4; i += 128) {
            int rr = i & 63;
            int d4 = (i >> 6) << 2;
            float4 v4 = *(const float4*)(kbase + (size_t)(kt * BKV + rr) * rowstride + d4);
            kst[(d4 + 0) * KS + rr] = v4.x;
            kst[(d4 + 1) * KS + rr] = v4.y;
            kst[(d4 + 2) * KS + rr] = v4.z;
            kst[(d4 + 3) * KS + rr] = v4.w;
        }
        // Load V natural (coalesced)
        for (int i = tid; i < BKV * DH / 4; i += 128) {
            int rr = i >> 4;
            int d4 = (i & 15) << 2;
            *(float4*)(vsm + rr * VS + d4) =
                *(const float4*)(vbase + (size_t)(kt * BKV + rr) * rowstride + d4);
        }
        __syncthreads();

        // S = Q K^T (4x8 micro-tile per thread)
        float s[4][8];
        #pragma unroll
        for (int i = 0; i < 4; i++)
            #pragma unroll
            for (int j = 0; j < 8; j++) s[i][j] = 0.f;

        #pragma unroll 4
        for (int d = 0; d < DH; d++) {
            float4 a4 = *(float4*)(qst + d * QS + rg);
            float4 b0 = *(float4*)(kst + d * KS + cg);
            float4 b1 = *(float4*)(kst + d * KS + cg + 4);
            float aa[4] = {a4.x, a4.y, a4.z, a4.w};
            float bb[8] = {b0.x, b0.y, b0.z, b0.w, b1.x, b1.y, b1.z, b1.w};
            #pragma unroll
            for (int i = 0; i < 4; i++)
                #pragma unroll
                for (int j = 0; j < 8; j++)
                    s[i][j] += aa[i] * bb[j];
        }

        // Scale + causal mask (only the diagonal tile needs masking)
        const bool diag = (kt == qt);
        #pragma unroll
        for (int i = 0; i < 4; i++)
            #pragma unroll
            for (int j = 0; j < 8; j++) {
                s[i][j] *= scale;
                if (diag && (cg + j > rg + i)) s[i][j] = -CUDART_INF_F;
            }

        // Online softmax per row (8 lanes share a row: shfl_xor 1,2,4)
        #pragma unroll
        for (int i = 0; i < 4; i++) {
            float mx = s[i][0];
            #pragma unroll
            for (int j = 1; j < 8; j++) mx = fmaxf(mx, s[i][j]);
            mx = fmaxf(mx, __shfl_xor_sync(0xffffffffu, mx, 1));
            mx = fmaxf(mx, __shfl_xor_sync(0xffffffffu, mx, 2));
            mx = fmaxf(mx, __shfl_xor_sync(0xffffffffu, mx, 4));
            float mnew = fmaxf(m[i], mx);
            float alpha = __expf(m[i] - mnew);
            float psum = 0.f;
            #pragma unroll
            for (int j = 0; j < 8; j++) {
                float p = __expf(s[i][j] - mnew);
                s[i][j] = p;
                psum += p;
            }
            psum += __shfl_xor_sync(0xffffffffu, psum, 1);
            psum += __shfl_xor_sync(0xffffffffu, psum, 2);
            psum += __shfl_xor_sync(0xffffffffu, psum, 4);
            l[i] = l[i] * alpha + psum;
            m[i] = mnew;
            #pragma unroll
            for (int j = 0; j < 8; j++) o[i][j] *= alpha;
        }

        // Stage P transposed: pst[c][r]
        #pragma unroll
        for (int j = 0; j < 8; j++)
            #pragma unroll
            for (int i = 0; i < 4; i++)
                pst[(cg + j) * PS + rg + i] = s[i][j];
        __syncthreads();

        // O += P V (4x8 micro-tile per thread)
        #pragma unroll 2
        for (int c = 0; c < BKV; c++) {
            float p0 = pst[c * PS + rg + 0];
            float p1 = pst[c * PS + rg + 1];
            float p2 = pst[c * PS + rg + 2];
            float p3 = pst[c * PS + rg + 3];
            float4 v0 = *(float4*)(vsm + c * VS + cg);
            float4 v1 = *(float4*)(vsm + c * VS + cg + 4);
            float vv[8] = {v0.x, v0.y, v0.z, v0.w, v1.x, v1.y, v1.z, v1.w};
            #pragma unroll
            for (int j = 0; j < 8; j++) {
                o[0][j] += p0 * vv[j];
                o[1][j] += p1 * vv[j];
                o[2][j] += p2 * vv[j];
                o[3][j] += p3 * vv[j];
            }
        }
        __syncthreads();
    }

    // Epilogue: y[b][t][h*64 + d] = o / l
    float* ybase = g_y + ((size_t)b * TT) * CC + h * DH;
    #pragma unroll
    for (int i = 0; i < 4; i++) {
        float inv = 1.f / l[i];
        float out8[8];
        #pragma unroll
        for (int j = 0; j < 8; j++) out8[j] = o[i][j] * inv;
        float* yrow = ybase + (size_t)(qt * BQ + rg + i) * CC + cg;
        *(float4*)yrow = *(float4*)&out8[0];
        *(float4*)(yrow + 4) = *(float4*)&out8[4];
    }
    (void)y;
}

// ---------------------------------------------------------------------------
extern "C" void kernel_launch(void* const* d_in, const int* in_sizes, int n_in,
                              void* d_out, int out_size)
{
    const float* x      = (const float*)d_in[0];
    const float* W_attn = (const float*)d_in[1];
    const float* b_attn = (const float*)d_in[2];
    const float* W_proj = (const float*)d_in[3];
    const float* b_proj = (const float*)d_in[4];
    float* out = (float*)d_out;

    float* qkv = nullptr;
    float* yb  = nullptr;
    cudaGetSymbolAddress((void**)&qkv, g_qkv);
    cudaGetSymbolAddress((void**)&yb, g_y);

    const int M = BB * TT;       // 4096
    const int N1 = 3 * CC;       // 3072
    const int N2 = CC;           // 1024
    const int K = CC;            // 1024

    // 1) QKV = x @ W_attn + b_attn
    {
        dim3 grid(N1 / GBN, M / GBM);
        sgemm_bias<<<grid, 256>>>(x, W_attn, b_attn, qkv, M, N1, K);
    }

    // 2) Flash attention
    {
        int smem_bytes = ATTN_SMEM_FLOATS * (int)sizeof(float);
        cudaFuncSetAttribute(attn_kernel,
                             cudaFuncAttributeMaxDynamicSharedMemorySize,
                             smem_bytes);
        dim3 grid(TT / BQ, HH, BB);
        attn_kernel<<<grid, 128, smem_bytes>>>(qkv, yb);
    }

    // 3) out = y @ W_proj + b_proj
    {
        dim3 grid(N2 / GBN, M / GBM);
        sgemm_bias<<<grid, 256>>>(yb, W_proj, b_proj, out, M, N2, K);
    }
}

// round 2
// speedup vs baseline: 1.0069x; 1.0069x over previous
#include <cuda_runtime.h>
#include <math_constants.h>

// Problem constants
#define TT 2048
#define CC 1024
#define HH 16
#define DH 64
#define BB 2

typedef unsigned long long u64;
struct __align__(16) u64x2 { u64 a, b; };

__device__ __forceinline__ u64 pack2(float lo, float hi) {
    u64 r;
    asm("mov.b64 %0, {%1, %2};" : "=l"(r) : "f"(lo), "f"(hi));
    return r;
}
__device__ __forceinline__ u64 dup2(float x) { return pack2(x, x); }
__device__ __forceinline__ void ffma2(u64 &d, u64 a, u64 b) {
    asm("fma.rn.f32x2 %0, %1, %2, %3;" : "=l"(d) : "l"(a), "l"(b), "l"(d));
}
__device__ __forceinline__ void fmul2(u64 &d, u64 a) {
    asm("mul.rn.f32x2 %0, %1, %2;" : "=l"(d) : "l"(d), "l"(a));
}
__device__ __forceinline__ void fadd2(u64 &d, u64 a) {
    asm("add.rn.f32x2 %0, %1, %2;" : "=l"(d) : "l"(d), "l"(a));
}
__device__ __forceinline__ float2 unpack2(u64 v) {
    float2 r;
    asm("mov.b64 {%0, %1}, %2;" : "=f"(r.x), "=f"(r.y) : "l"(v));
    return r;
}

// Scratch (no allocations allowed)
__device__ float g_qkv[(size_t)BB * TT * 3 * CC];   // [B*T, 3C]
__device__ float g_y[(size_t)BB * TT * CC];         // [B*T, C]

// ---------------------------------------------------------------------------
// SGEMM with bias: C[M,N] = A[M,K] @ B[K,N] + bias[N]
// 128x128x16 tile, 256 threads, 8x8 per thread, packed f32x2 FMA.
// ---------------------------------------------------------------------------
#define GBM 128
#define GBN 128
#define GBK 16

__global__ __launch_bounds__(256) void sgemm_bias(
    const float* __restrict__ A, const float* __restrict__ B,
    const float* __restrict__ bias, float* __restrict__ C,
    int M, int N, int K)
{
    __shared__ float As[GBK][GBM + 4];
    __shared__ float Bs[GBK][GBN];

    const int tid = threadIdx.x;
    const int bm = blockIdx.y * GBM;
    const int bn = blockIdx.x * GBN;
    const int tr = (tid >> 4) << 3;   // 0..120, step 8
    const int tc = (tid & 15) << 3;   // 0..120, step 8

    u64 acc[8][4];
    #pragma unroll
    for (int i = 0; i < 8; i++)
        #pragma unroll
        for (int p = 0; p < 4; p++)
            acc[i][p] = 0ULL;

    const float* Ab = A + (size_t)bm * K;
    const float* Bb = B + bn;

    for (int k0 = 0; k0 < K; k0 += GBK) {
        #pragma unroll
        for (int i = 0; i < 2; i++) {
            int id = tid + i * 256;
            // A tile: 128 rows x 16 cols, float4 along K, store transposed
            int ar = id >> 2;
            int ac = (id & 3) << 2;
            float4 av = *(const float4*)(Ab + (size_t)ar * K + k0 + ac);
            As[ac + 0][ar] = av.x;
            As[ac + 1][ar] = av.y;
            As[ac + 2][ar] = av.z;
            As[ac + 3][ar] = av.w;
            // B tile: 16 rows x 128 cols, contiguous float4
            int br = id >> 5;
            int bc = (id & 31) << 2;
            *(float4*)(&Bs[br][bc]) =
                *(const float4*)(Bb + (size_t)(k0 + br) * N + bc);
        }
        __syncthreads();

        #pragma unroll
        for (int k = 0; k < GBK; k++) {
            float4 a0 = *(const float4*)&As[k][tr];
            float4 a1 = *(const float4*)&As[k][tr + 4];
            u64x2 b0 = *(const u64x2*)&Bs[k][tc];
            u64x2 b1 = *(const u64x2*)&Bs[k][tc + 4];
            u64 ad[8];
            ad[0] = dup2(a0.x); ad[1] = dup2(a0.y);
            ad[2] = dup2(a0.z); ad[3] = dup2(a0.w);
            ad[4] = dup2(a1.x); ad[5] = dup2(a1.y);
            ad[6] = dup2(a1.z); ad[7] = dup2(a1.w);
            u64 bp[4] = {b0.a, b0.b, b1.a, b1.b};
            #pragma unroll
            for (int i = 0; i < 8; i++)
                #pragma unroll
                for (int p = 0; p < 4; p++)
                    ffma2(acc[i][p], ad[i], bp[p]);
        }
        __syncthreads();
    }

    // bias (packed) + store
    u64x2 bi0 = *(const u64x2*)(bias + bn + tc);
    u64x2 bi1 = *(const u64x2*)(bias + bn + tc + 4);
    u64 bp[4] = {bi0.a, bi0.b, bi1.a, bi1.b};
    #pragma unroll
    for (int i = 0; i < 8; i++) {
        #pragma unroll
        for (int p = 0; p < 4; p++)
            fadd2(acc[i][p], bp[p]);
        float* Crow = C + (size_t)(bm + tr + i) * N + bn + tc;
        u64x2 lo = {acc[i][0], acc[i][1]};
        u64x2 hi = {acc[i][2], acc[i][3]};
        *(u64x2*)Crow = lo;
        *(u64x2*)(Crow + 4) = hi;
    }
}

// ---------------------------------------------------------------------------
// Flash attention (causal), fp32, packed f32x2 FMA.
// Block = one (b, h, q-tile of 64). 128 threads, each owns 4 q-rows x 8 cols.
// ---------------------------------------------------------------------------
#define BQ 64
#define BKV 64
#define QS 68
#define KS 68
#define VS 68
#define PS 65

#define ATTN_SMEM_FLOATS (DH * QS + DH * KS + BKV * VS + BKV * PS)

__global__ __launch_bounds__(128) void attn_kernel(
    const float* __restrict__ qkv, float* __restrict__ y)
{
    extern __shared__ float sm[];
    float* qst = sm;                  // [DH][QS]  q transposed
    float* kst = qst + DH * QS;       // [DH][KS]  k transposed
    float* vsm = kst + DH * KS;       // [BKV][VS] v natural
    float* pst = vsm + BKV * VS;      // [BKV][PS] p transposed

    const int qt = gridDim.x - 1 - blockIdx.x;  // longest blocks first
    const int h  = blockIdx.y;
    const int b  = blockIdx.z;
    const int tid = threadIdx.x;
    const int rg = (tid >> 3) << 2;   // row base 0..60
    const int cg = (tid & 7) << 3;    // col base 0..56

    const float scale = 0.125f;       // 1/sqrt(64)
    const int rowstride = 3 * CC;
    const float* qbase = qkv + (size_t)b * TT * rowstride + h * DH;
    const float* kbase = qbase + CC;
    const float* vbase = qbase + 2 * CC;

    // Load Q tile transposed: qst[d][r]
    for (int i = tid; i < BQ * DH / 4; i += 128) {
        int rr = i & 63;
        int d4 = (i >> 6) << 2;
        float4 v4 = *(const float4*)(qbase + (size_t)(qt * BQ + rr) * rowstride + d4);
        qst[(d4 + 0) * QS + rr] = v4.x;
        qst[(d4 + 1) * QS + rr] = v4.y;
        qst[(d4 + 2) * QS + rr] = v4.z;
        qst[(d4 + 3) * QS + rr] = v4.w;
    }

    float m[4], l[4];
    u64 o2[4][4];
    #pragma unroll
    for (int i = 0; i < 4; i++) {
        m[i] = -CUDART_INF_F;
        l[i] = 0.f;
        #pragma unroll
        for (int p = 0; p < 4; p++) o2[i][p] = 0ULL;
    }
    __syncthreads();

    for (int kt = 0; kt <= qt; kt++) {
        // Load K transposed
        for (int i = tid; i < BKV * DH / 4; i += 128) {
            int rr = i & 63;
            int d4 = (i >> 6) << 2;
            float4 v4 = *(const float4*)(kbase + (size_t)(kt * BKV + rr) * rowstride + d4);
            kst[(d4 + 0) * KS + rr] = v4.x;
            kst[(d4 + 1) * KS + rr] = v4.y;
            kst[(d4 + 2) * KS + rr] = v4.z;
            kst[(d4 + 3) * KS + rr] = v4.w;
        }
        // Load V natural (coalesced)
        for (int i = tid; i < BKV * DH / 4; i += 128) {
            int rr = i >> 4;
            int d4 = (i & 15) << 2;
            *(float4*)(vsm + rr * VS + d4) =
                *(const float4*)(vbase + (size_t)(kt * BKV + rr) * rowstride + d4);
        }
        __syncthreads();

        // S = Q K^T (packed: 4 rows x 4 col-pairs per thread)
        u64 s2[4][4];
        #pragma unroll
        for (int i = 0; i < 4; i++)
            #pragma unroll
            for (int p = 0; p < 4; p++) s2[i][p] = 0ULL;

        #pragma unroll 4
        for (int d = 0; d < DH; d++) {
            float4 a4 = *(const float4*)(qst + d * QS + rg);
            u64x2 k0 = *(const u64x2*)(kst + d * KS + cg);
            u64x2 k1 = *(const u64x2*)(kst + d * KS + cg + 4);
            u64 ad[4];
            ad[0] = dup2(a4.x); ad[1] = dup2(a4.y);
            ad[2] = dup2(a4.z); ad[3] = dup2(a4.w);
            u64 kp[4] = {k0.a, k0.b, k1.a, k1.b};
            #pragma unroll
            for (int i = 0; i < 4; i++)
                #pragma unroll
                for (int p = 0; p < 4; p++)
                    ffma2(s2[i][p], ad[i], kp[p]);
        }

        // Unpack S
        float s[4][8];
        #pragma unroll
        for (int i = 0; i < 4; i++)
            #pragma unroll
            for (int p = 0; p < 4; p++) {
                float2 f = unpack2(s2[i][p]);
                s[i][2*p]   = f.x;
                s[i][2*p+1] = f.y;
            }

        // Scale + causal mask (only the diagonal tile needs masking)
        const bool diag = (kt == qt);
        #pragma unroll
        for (int i = 0; i < 4; i++)
            #pragma unroll
            for (int j = 0; j < 8; j++) {
                s[i][j] *= scale;
                if (diag && (cg + j > rg + i)) s[i][j] = -CUDART_INF_F;
            }

        // Online softmax per row (8 lanes share a row: shfl_xor 1,2,4)
        #pragma unroll
        for (int i = 0; i < 4; i++) {
            float mx = s[i][0];
            #pragma unroll
            for (int j = 1; j < 8; j++) mx = fmaxf(mx, s[i][j]);
            mx = fmaxf(mx, __shfl_xor_sync(0xffffffffu, mx, 1));
            mx = fmaxf(mx, __shfl_xor_sync(0xffffffffu, mx, 2));
            mx = fmaxf(mx, __shfl_xor_sync(0xffffffffu, mx, 4));
            float mnew = fmaxf(m[i], mx);
            float alpha = __expf(m[i] - mnew);
            float psum = 0.f;
            #pragma unroll
            for (int j = 0; j < 8; j++) {
                float p = __expf(s[i][j] - mnew);
                s[i][j] = p;
                psum += p;
            }
            psum += __shfl_xor_sync(0xffffffffu, psum, 1);
            psum += __shfl_xor_sync(0xffffffffu, psum, 2);
            psum += __shfl_xor_sync(0xffffffffu, psum, 4);
            l[i] = l[i] * alpha + psum;
            m[i] = mnew;
            u64 al = dup2(alpha);
            #pragma unroll
            for (int p = 0; p < 4; p++) fmul2(o2[i][p], al);
        }

        // Stage P transposed: pst[c][r]
        #pragma unroll
        for (int j = 0; j < 8; j++)
            #pragma unroll
            for (int i = 0; i < 4; i++)
                pst[(cg + j) * PS + rg + i] = s[i][j];
        __syncthreads();

        // O += P V (packed)
        #pragma unroll 2
        for (int c = 0; c < BKV; c++) {
            u64 p0 = dup2(pst[c * PS + rg + 0]);
            u64 p1 = dup2(pst[c * PS + rg + 1]);
            u64 p2 = dup2(pst[c * PS + rg + 2]);
            u64 p3 = dup2(pst[c * PS + rg + 3]);
            u64x2 v0 = *(const u64x2*)(vsm + c * VS + cg);
            u64x2 v1 = *(const u64x2*)(vsm + c * VS + cg + 4);
            u64 vp[4] = {v0.a, v0.b, v1.a, v1.b};
            #pragma unroll
            for (int p = 0; p < 4; p++) {
                ffma2(o2[0][p], p0, vp[p]);
                ffma2(o2[1][p], p1, vp[p]);
                ffma2(o2[2][p], p2, vp[p]);
                ffma2(o2[3][p], p3, vp[p]);
            }
        }
        __syncthreads();
    }

    // Epilogue: y[b][t][h*64 + d] = o / l
    float* ybase = g_y + ((size_t)b * TT) * CC + h * DH;
    #pragma unroll
    for (int i = 0; i < 4; i++) {
        float inv = 1.f / l[i];
        u64 iv = dup2(inv);
        u64 r[4];
        #pragma unroll
        for (int p = 0; p < 4; p++) { r[p] = o2[i][p]; fmul2(r[p], iv); }
        float* yrow = ybase + (size_t)(qt * BQ + rg + i) * CC + cg;
        u64x2 lo = {r[0], r[1]};
        u64x2 hi = {r[2], r[3]};
        *(u64x2*)yrow = lo;
        *(u64x2*)(yrow + 4) = hi;
    }
    (void)y;
}

// ---------------------------------------------------------------------------
extern "C" void kernel_launch(void* const* d_in, const int* in_sizes, int n_in,
                              void* d_out, int out_size)
{
    const float* x      = (const float*)d_in[0];
    const float* W_attn = (const float*)d_in[1];
    const float* b_attn = (const float*)d_in[2];
    const float* W_proj = (const float*)d_in[3];
    const float* b_proj = (const float*)d_in[4];
    float* out = (float*)d_out;

    float* qkv = nullptr;
    float* yb  = nullptr;
    cudaGetSymbolAddress((void**)&qkv, g_qkv);
    cudaGetSymbolAddress((void**)&yb, g_y);

    const int M = BB * TT;       // 4096
    const int N1 = 3 * CC;       // 3072
    const int N2 = CC;           // 1024
    const int K = CC;            // 1024

    // 1) QKV = x @ W_attn + b_attn
    {
        dim3 grid(N1 / GBN, M / GBM);
        sgemm_bias<<<grid, 256>>>(x, W_attn, b_attn, qkv, M, N1, K);
    }

    // 2) Flash attention
    {
        int smem_bytes = ATTN_SMEM_FLOATS * (int)sizeof(float);
        cudaFuncSetAttribute(attn_kernel,
                             cudaFuncAttributeMaxDynamicSharedMemorySize,
                             smem_bytes);
        dim3 grid(TT / BQ, HH, BB);
        attn_kernel<<<grid, 128, smem_bytes>>>(qkv, yb);
    }

    // 3) out = y @ W_proj + b_proj
    {
        dim3 grid(N2 / GBN, M / GBM);
        sgemm_bias<<<grid, 256>>>(yb, W_proj, b_proj, out, M, N2, K);
    }
}

// round 4
// speedup vs baseline: 2.2276x; 2.2123x over previous
#include <cuda_runtime.h>
#include <cuda_bf16.h>
#include <math_constants.h>
#include <cstdint>

// Problem constants
#define TT 2048
#define CC 1024
#define HH 16
#define DH 64
#define BB 2

#define SW(off) ((uint32_t)(off) ^ ((((uint32_t)(off)) >> 3) & 0x70u))

// ---------------------------------------------------------------------------
// PTX helpers (all base-target sm_103 safe: no tcgen05/TMEM)
// ---------------------------------------------------------------------------
__device__ __forceinline__ uint32_t smem_u32(const void* p) {
    uint32_t a;
    asm("{ .reg .u64 t; cvta.to.shared.u64 t, %1; cvt.u32.u64 %0, t; }"
        : "=r"(a) : "l"(p));
    return a;
}
__device__ __forceinline__ void ldsm_x4(uint32_t addr, uint32_t &r0, uint32_t &r1,
                                        uint32_t &r2, uint32_t &r3) {
    asm volatile("ldmatrix.sync.aligned.m8n8.x4.shared.b16 {%0,%1,%2,%3}, [%4];"
                 : "=r"(r0), "=r"(r1), "=r"(r2), "=r"(r3) : "r"(addr));
}
__device__ __forceinline__ void ldsm_x2(uint32_t addr, uint32_t &r0, uint32_t &r1) {
    asm volatile("ldmatrix.sync.aligned.m8n8.x2.shared.b16 {%0,%1}, [%2];"
                 : "=r"(r0), "=r"(r1) : "r"(addr));
}
__device__ __forceinline__ void ldsm_x2t(uint32_t addr, uint32_t &r0, uint32_t &r1) {
    asm volatile("ldmatrix.sync.aligned.m8n8.x2.trans.shared.b16 {%0,%1}, [%2];"
                 : "=r"(r0), "=r"(r1) : "r"(addr));
}
__device__ __forceinline__ void mma_bf16(float* c, uint32_t a0, uint32_t a1,
                                         uint32_t a2, uint32_t a3,
                                         uint32_t b0, uint32_t b1) {
    asm volatile("mma.sync.aligned.m16n8k16.row.col.f32.bf16.bf16.f32 "
                 "{%0,%1,%2,%3}, {%4,%5,%6,%7}, {%8,%9}, {%0,%1,%2,%3};"
                 : "+f"(c[0]), "+f"(c[1]), "+f"(c[2]), "+f"(c[3])
                 : "r"(a0), "r"(a1), "r"(a2), "r"(a3), "r"(b0), "r"(b1));
}
__device__ __forceinline__ void cp_async16(uint32_t dst, const void* src) {
    asm volatile("cp.async.cg.shared.global [%0], [%1], 16;"
                 :: "r"(dst), "l"(src) : "memory");
}
#define CP_COMMIT() asm volatile("cp.async.commit_group;" ::: "memory")
#define CP_WAIT0()  asm volatile("cp.async.wait_group 0;" ::: "memory")

// pack two f32 into bf16x2 reg: low half = lo, high half = hi
__device__ __forceinline__ uint32_t pack_bf16x2(float lo, float hi) {
    uint32_t d;
    asm("cvt.rn.bf16x2.f32 %0, %1, %2;" : "=r"(d) : "f"(hi), "f"(lo));
    return d;
}
// residual of (a,b) vs packed-bf16x2 hp, re-packed to bf16x2
__device__ __forceinline__ uint32_t residual_pack(float a, float b, uint32_t hp) {
    float ra = a - __uint_as_float(hp << 16);
    float rb = b - __uint_as_float(hp & 0xFFFF0000u);
    return pack_bf16x2(ra, rb);
}
__device__ __forceinline__ void store_split(__nv_bfloat16* H, __nv_bfloat16* L,
                                            size_t off, float a, float b) {
    __nv_bfloat16 ha = __float2bfloat16(a), hb = __float2bfloat16(b);
    float ra = a - __bfloat162float(ha), rb = b - __bfloat162float(hb);
    *(__nv_bfloat162*)(H + off) = __halves2bfloat162(ha, hb);
    *(__nv_bfloat162*)(L + off) =
        __halves2bfloat162(__float2bfloat16(ra), __float2bfloat16(rb));
}

// ---------------------------------------------------------------------------
// Scratch (no allocations allowed)
// ---------------------------------------------------------------------------
__device__ __nv_bfloat16 g_xh[(size_t)BB * TT * CC];
__device__ __nv_bfloat16 g_xl[(size_t)BB * TT * CC];
__device__ __nv_bfloat16 g_qkvh[(size_t)BB * TT * 3 * CC];
__device__ __nv_bfloat16 g_qkvl[(size_t)BB * TT * 3 * CC];
__device__ __nv_bfloat16 g_yh[(size_t)BB * TT * CC];
__device__ __nv_bfloat16 g_yl[(size_t)BB * TT * CC];
__device__ __nv_bfloat16 g_wah[(size_t)3 * CC * CC];  // W_attn^T [3C, C]
__device__ __nv_bfloat16 g_wal[(size_t)3 * CC * CC];
__device__ __nv_bfloat16 g_wph[(size_t)CC * CC];      // W_proj^T [C, C]
__device__ __nv_bfloat16 g_wpl[(size_t)CC * CC];

// ---------------------------------------------------------------------------
// fp32 -> bf16 hi/lo split (no transpose)
// ---------------------------------------------------------------------------
__global__ __launch_bounds__(256) void cvt_split(
    const float* __restrict__ in, __nv_bfloat16* __restrict__ h,
    __nv_bfloat16* __restrict__ l, int n2)
{
    int i = blockIdx.x * 256 + threadIdx.x;
    if (i >= n2) return;
    float2 v = ((const float2*)in)[i];
    __nv_bfloat16 h0 = __float2bfloat16(v.x);
    __nv_bfloat16 h1 = __float2bfloat16(v.y);
    __nv_bfloat16 l0 = __float2bfloat16(v.x - __bfloat162float(h0));
    __nv_bfloat16 l1 = __float2bfloat16(v.y - __bfloat162float(h1));
    ((__nv_bfloat162*)h)[i] = __halves2bfloat162(h0, h1);
    ((__nv_bfloat162*)l)[i] = __halves2bfloat162(l0, l1);
}

// ---------------------------------------------------------------------------
// fp32 [K,N] -> bf16 hi/lo transposed [N,K]
// ---------------------------------------------------------------------------
__global__ __launch_bounds__(256) void cvt_split_t(
    const float* __restrict__ in, __nv_bfloat16* __restrict__ h,
    __nv_bfloat16* __restrict__ l, int K, int N)
{
    __shared__ float ts[32][33];
    int tx = threadIdx.x, ty = threadIdx.y;   // (32, 8)
    int bx = blockIdx.x, by = blockIdx.y;
    #pragma unroll
    for (int j = 0; j < 4; j++) {
        int k = by * 32 + ty + j * 8;
        ts[ty + j * 8][tx] = in[(size_t)k * N + bx * 32 + tx];
    }
    __syncthreads();
    #pragma unroll
    for (int j = 0; j < 4; j++) {
        int nrow = bx * 32 + ty + j * 8;
        float v = ts[tx][ty + j * 8];
        __nv_bfloat16 hv = __float2bfloat16(v);
        __nv_bfloat16 lv = __float2bfloat16(v - __bfloat162float(hv));
        h[(size_t)nrow * K + by * 32 + tx] = hv;
        l[(size_t)nrow * K + by * 32 + tx] = lv;
    }
}

// ---------------------------------------------------------------------------
// Tensor-core GEMM (mma.sync bf16 hi/lo 3-combo, fp32 accum):
//   C[M,N] = A[M,K] @ B[N,K]^T + bias[N]
// CTA 128x128, 8 warps (64x32 each), k-chunk 64, cp.async double buffer.
// SPLIT=true: write bf16 hi/lo pair; else fp32.
// ---------------------------------------------------------------------------
#define GSMEM (1024 + 2 * 65536)

template<bool SPLIT>
__global__ __launch_bounds__(256) void gemm_mma(
    const __nv_bfloat16* __restrict__ Ah, const __nv_bfloat16* __restrict__ Al,
    const __nv_bfloat16* __restrict__ Bh, const __nv_bfloat16* __restrict__ Bl,
    const float* __restrict__ bias, float* __restrict__ Cf,
    __nv_bfloat16* __restrict__ Ch, __nv_bfloat16* __restrict__ Cl,
    int Ncols, int K)
{
    extern __shared__ char dsm[];
    const uint32_t sb = (smem_u32(dsm) + 1023u) & ~1023u;

    const int tid = threadIdx.x;
    const int lid = tid & 31;
    const int wid = tid >> 5;
    const int wm = (wid >> 2) * 64;
    const int wn = (wid & 3) * 32;
    const int bm = blockIdx.y * 128;
    const int bn = blockIdx.x * 128;

    float c[4][4][4];
    #pragma unroll
    for (int mt = 0; mt < 4; mt++)
        #pragma unroll
        for (int nt = 0; nt < 4; nt++)
            #pragma unroll
            for (int e = 0; e < 4; e++) c[mt][nt][e] = 0.f;

    // async-load one k64 chunk into buffer `buf` (regions: AH,AL,BH,BL @16KB)
    auto load_chunk = [&](int ch, int buf) {
        const int k0 = ch << 6;
        #pragma unroll
        for (int j = 0; j < 4; j++) {
            int idx = tid + j * 256;          // 0..1023
            int row = idx >> 3, c16 = idx & 7;
            uint32_t dst = sb + (uint32_t)(buf * 65536) + SW(row * 128 + c16 * 16);
            size_t ga = (size_t)(bm + row) * K + k0 + c16 * 8;
            size_t gb = (size_t)(bn + row) * K + k0 + c16 * 8;
            cp_async16(dst,         Ah + ga);
            cp_async16(dst + 16384, Al + ga);
            cp_async16(dst + 32768, Bh + gb);
            cp_async16(dst + 49152, Bl + gb);
        }
    };

    auto compute = [&](int buf) {
        const uint32_t tb = sb + (uint32_t)(buf * 65536);
        #pragma unroll
        for (int ks = 0; ks < 4; ks++) {
            uint32_t ah[4][4], al[4][4];
            #pragma unroll
            for (int mt = 0; mt < 4; mt++) {
                int row = wm + mt * 16 + (lid & 15);
                uint32_t off = SW(row * 128 + ks * 32 + ((lid >> 4) << 4));
                ldsm_x4(tb + off, ah[mt][0], ah[mt][1], ah[mt][2], ah[mt][3]);
                ldsm_x4(tb + 16384 + off, al[mt][0], al[mt][1], al[mt][2], al[mt][3]);
            }
            #pragma unroll
            for (int nt = 0; nt < 4; nt++) {
                int rowb = wn + nt * 8 + (lid & 7);
                uint32_t offb = SW(rowb * 128 + ks * 32 + (((lid >> 3) & 1) << 4));
                uint32_t bh0, bh1, bl0, bl1;
                ldsm_x2(tb + 32768 + offb, bh0, bh1);
                ldsm_x2(tb + 49152 + offb, bl0, bl1);
                #pragma unroll
                for (int mt = 0; mt < 4; mt++) {
                    mma_bf16(c[mt][nt], ah[mt][0], ah[mt][1], ah[mt][2], ah[mt][3], bh0, bh1);
                    mma_bf16(c[mt][nt], ah[mt][0], ah[mt][1], ah[mt][2], ah[mt][3], bl0, bl1);
                    mma_bf16(c[mt][nt], al[mt][0], al[mt][1], al[mt][2], al[mt][3], bh0, bh1);
                }
            }
        }
    };

    const int nch = K >> 6;
    load_chunk(0, 0);
    CP_COMMIT();
    CP_WAIT0();
    __syncthreads();

    int buf = 0;
    for (int ch = 0; ch < nch; ch++) {
        if (ch + 1 < nch) { load_chunk(ch + 1, buf ^ 1); CP_COMMIT(); }
        compute(buf);
        CP_WAIT0();
        __syncthreads();
        buf ^= 1;
    }

    // Epilogue
    #pragma unroll
    for (int mt = 0; mt < 4; mt++) {
        #pragma unroll
        for (int nt = 0; nt < 4; nt++) {
            int m0 = bm + wm + mt * 16 + (lid >> 2);
            int n  = bn + wn + nt * 8 + ((lid & 3) << 1);
            float b0 = bias[n], b1 = bias[n + 1];
            float v00 = c[mt][nt][0] + b0, v01 = c[mt][nt][1] + b1;
            float v10 = c[mt][nt][2] + b0, v11 = c[mt][nt][3] + b1;
            if (SPLIT) {
                store_split(Ch, Cl, (size_t)m0 * Ncols + n, v00, v01);
                store_split(Ch, Cl, (size_t)(m0 + 8) * Ncols + n, v10, v11);
            } else {
                float2 p0 = {v00, v01}, p1 = {v10, v11};
                *(float2*)(Cf + (size_t)m0 * Ncols + n) = p0;
                *(float2*)(Cf + (size_t)(m0 + 8) * Ncols + n) = p1;
            }
        }
    }
}

// ---------------------------------------------------------------------------
// Flash attention (causal) on mma.sync bf16 hi/lo.
// Block = (b, h, q-tile 64). 4 warps; warp w owns q rows w*16..w*16+15.
// S = QK^T (3-combo), online softmax, P hi/lo rebuilt in registers, PV via
// ldmatrix.trans on V (3-combo). Output written pre-split to yh/yl.
// ---------------------------------------------------------------------------
__global__ __launch_bounds__(128) void attn_mma(
    const __nv_bfloat16* __restrict__ qkvh, const __nv_bfloat16* __restrict__ qkvl,
    __nv_bfloat16* __restrict__ yh, __nv_bfloat16* __restrict__ yl)
{
    __shared__ __align__(1024) char smem[32768];  // KH 0 | KL 8K | VH 16K | VL 24K
    const uint32_t sb = smem_u32(smem);

    const int tid = threadIdx.x;
    const int lid = tid & 31;
    const int w = tid >> 5;
    const int qt = gridDim.x - 1 - blockIdx.x;    // longest first
    const int h = blockIdx.y;
    const int b = blockIdx.z;
    const size_t bT = (size_t)b * TT;
    const int RS = 3 * CC;

    // ---- stage Q (hi/lo) into KH/KL regions, extract fragments
    {
        const __nv_bfloat16* qbh = qkvh + (bT + qt * 64) * RS + h * DH;
        const __nv_bfloat16* qbl = qkvl + (bT + qt * 64) * RS + h * DH;
        #pragma unroll
        for (int j = 0; j < 4; j++) {
            int idx = tid + j * 128;              // 0..511
            int row = idx >> 3, c16 = idx & 7;
            uint32_t sw = SW(row * 128 + c16 * 16);
            size_t g = (size_t)row * RS + c16 * 8;
            *(uint4*)(smem + sw)        = *(const uint4*)(qbh + g);
            *(uint4*)(smem + 8192 + sw) = *(const uint4*)(qbl + g);
        }
    }
    __syncthreads();
    uint32_t qh[4][4], ql[4][4];
    #pragma unroll
    for (int ks = 0; ks < 4; ks++) {
        int row = w * 16 + (lid & 15);
        uint32_t off = SW(row * 128 + ks * 32 + ((lid >> 4) << 4));
        ldsm_x4(sb + off, qh[ks][0], qh[ks][1], qh[ks][2], qh[ks][3]);
        ldsm_x4(sb + 8192 + off, ql[ks][0], ql[ks][1], ql[ks][2], ql[ks][3]);
    }
    __syncthreads();

    float o[8][4];
    #pragma unroll
    for (int nt = 0; nt < 8; nt++)
        #pragma unroll
        for (int e = 0; e < 4; e++) o[nt][e] = 0.f;
    float m0 = -CUDART_INF_F, m1 = -CUDART_INF_F, l0 = 0.f, l1 = 0.f;
    const int r0 = w * 16 + (lid >> 2);           // local q row (second = r0+8)
    const int cbase = (lid & 3) << 1;             // local col pair base

    for (int kt = 0; kt <= qt; kt++) {
        // load K/V hi/lo tiles (64 x 64 bf16 each)
        {
            const __nv_bfloat16* kh_g = qkvh + (bT + kt * 64) * RS + CC + h * DH;
            const __nv_bfloat16* kl_g = qkvl + (bT + kt * 64) * RS + CC + h * DH;
            const __nv_bfloat16* vh_g = qkvh + (bT + kt * 64) * RS + 2 * CC + h * DH;
            const __nv_bfloat16* vl_g = qkvl + (bT + kt * 64) * RS + 2 * CC + h * DH;
            #pragma unroll
            for (int j = 0; j < 4; j++) {
                int idx = tid + j * 128;
                int row = idx >> 3, c16 = idx & 7;
                uint32_t sw = SW(row * 128 + c16 * 16);
                size_t g = (size_t)row * RS + c16 * 8;
                *(uint4*)(smem + sw)         = *(const uint4*)(kh_g + g);
                *(uint4*)(smem + 8192 + sw)  = *(const uint4*)(kl_g + g);
                *(uint4*)(smem + 16384 + sw) = *(const uint4*)(vh_g + g);
                *(uint4*)(smem + 24576 + sw) = *(const uint4*)(vl_g + g);
            }
        }
        __syncthreads();

        // S = Q K^T  (16 x 64 per warp)
        float s[8][4];
        #pragma unroll
        for (int nt = 0; nt < 8; nt++)
            #pragma unroll
            for (int e = 0; e < 4; e++) s[nt][e] = 0.f;

        #pragma unroll
        for (int ks = 0; ks < 4; ks++) {
            #pragma unroll
            for (int nt = 0; nt < 8; nt++) {
                int rowb = nt * 8 + (lid & 7);
                uint32_t offb = SW(rowb * 128 + ks * 32 + (((lid >> 3) & 1) << 4));
                uint32_t kh0, kh1, kl0, kl1;
                ldsm_x2(sb + offb, kh0, kh1);
                ldsm_x2(sb + 8192 + offb, kl0, kl1);
                mma_bf16(s[nt], qh[ks][0], qh[ks][1], qh[ks][2], qh[ks][3], kh0, kh1);
                mma_bf16(s[nt], qh[ks][0], qh[ks][1], qh[ks][2], qh[ks][3], kl0, kl1);
                mma_bf16(s[nt], ql[ks][0], ql[ks][1], ql[ks][2], ql[ks][3], kh0, kh1);
            }
        }

        // scale + causal mask (diagonal tile only)
        #pragma unroll
        for (int nt = 0; nt < 8; nt++)
            #pragma unroll
            for (int e = 0; e < 4; e++) s[nt][e] *= 0.125f;
        if (kt == qt) {
            #pragma unroll
            for (int nt = 0; nt < 8; nt++) {
                int cc0 = nt * 8 + cbase;
                if (cc0     > r0)     s[nt][0] = -CUDART_INF_F;
                if (cc0 + 1 > r0)     s[nt][1] = -CUDART_INF_F;
                if (cc0     > r0 + 8) s[nt][2] = -CUDART_INF_F;
                if (cc0 + 1 > r0 + 8) s[nt][3] = -CUDART_INF_F;
            }
        }

        // online softmax (2 rows per thread; quad = 4 lanes share a row)
        float mx0 = -CUDART_INF_F, mx1 = -CUDART_INF_F;
        #pragma unroll
        for (int nt = 0; nt < 8; nt++) {
            mx0 = fmaxf(mx0, fmaxf(s[nt][0], s[nt][1]));
            mx1 = fmaxf(mx1, fmaxf(s[nt][2], s[nt][3]));
        }
        mx0 = fmaxf(mx0, __shfl_xor_sync(0xffffffffu, mx0, 1));
        mx0 = fmaxf(mx0, __shfl_xor_sync(0xffffffffu, mx0, 2));
        mx1 = fmaxf(mx1, __shfl_xor_sync(0xffffffffu, mx1, 1));
        mx1 = fmaxf(mx1, __shfl_xor_sync(0xffffffffu, mx1, 2));
        float mn0 = fmaxf(m0, mx0), mn1 = fmaxf(m1, mx1);
        float a0 = __expf(m0 - mn0), a1 = __expf(m1 - mn1);
        float su0 = 0.f, su1 = 0.f;
        #pragma unroll
        for (int nt = 0; nt < 8; nt++) {
            s[nt][0] = __expf(s[nt][0] - mn0);
            s[nt][1] = __expf(s[nt][1] - mn0);
            s[nt][2] = __expf(s[nt][2] - mn1);
            s[nt][3] = __expf(s[nt][3] - mn1);
            su0 += s[nt][0] + s[nt][1];
            su1 += s[nt][2] + s[nt][3];
        }
        su0 += __shfl_xor_sync(0xffffffffu, su0, 1);
        su0 += __shfl_xor_sync(0xffffffffu, su0, 2);
        su1 += __shfl_xor_sync(0xffffffffu, su1, 1);
        su1 += __shfl_xor_sync(0xffffffffu, su1, 2);
        l0 = l0 * a0 + su0;  l1 = l1 * a1 + su1;
        m0 = mn0;  m1 = mn1;
        #pragma unroll
        for (int nt = 0; nt < 8; nt++) {
            o[nt][0] *= a0; o[nt][1] *= a0;
            o[nt][2] *= a1; o[nt][3] *= a1;
        }

        // PV: P fragments from S registers (hi + residual), V via ldmatrix.trans
        #pragma unroll
        for (int ks = 0; ks < 4; ks++) {
            const int t0 = ks * 2, t1 = ks * 2 + 1;
            uint32_t ph0 = pack_bf16x2(s[t0][0], s[t0][1]);
            uint32_t ph1 = pack_bf16x2(s[t0][2], s[t0][3]);
            uint32_t ph2 = pack_bf16x2(s[t1][0], s[t1][1]);
            uint32_t ph3 = pack_bf16x2(s[t1][2], s[t1][3]);
            uint32_t pl0 = residual_pack(s[t0][0], s[t0][1], ph0);
            uint32_t pl1 = residual_pack(s[t0][2], s[t0][3], ph1);
            uint32_t pl2 = residual_pack(s[t1][0], s[t1][1], ph2);
            uint32_t pl3 = residual_pack(s[t1][2], s[t1][3], ph3);
            int rowv = ks * 16 + (lid & 15);
            #pragma unroll
            for (int nt = 0; nt < 8; nt++) {
                uint32_t offv = SW(rowv * 128 + nt * 16);
                uint32_t vh0, vh1, vl0, vl1;
                ldsm_x2t(sb + 16384 + offv, vh0, vh1);
                ldsm_x2t(sb + 24576 + offv, vl0, vl1);
                mma_bf16(o[nt], ph0, ph1, ph2, ph3, vh0, vh1);
                mma_bf16(o[nt], ph0, ph1, ph2, ph3, vl0, vl1);
                mma_bf16(o[nt], pl0, pl1, pl2, pl3, vh0, vh1);
            }
        }
        __syncthreads();
    }

    // Epilogue: normalize, split to bf16 hi/lo for proj GEMM
    float i0 = 1.f / l0, i1 = 1.f / l1;
    size_t row0 = (bT + (size_t)qt * 64 + r0) * CC + h * DH;
    size_t row1 = row0 + (size_t)8 * CC;
    #pragma unroll
    for (int nt = 0; nt < 8; nt++) {
        int n = nt * 8 + cbase;
        store_split(yh, yl, row0 + n, o[nt][0] * i0, o[nt][1] * i0);
        store_split(yh, yl, row1 + n, o[nt][2] * i1, o[nt][3] * i1);
    }
}

// ---------------------------------------------------------------------------
extern "C" void kernel_launch(void* const* d_in, const int* in_sizes, int n_in,
                              void* d_out, int out_size)
{
    const float* x      = (const float*)d_in[0];
    const float* W_attn = (const float*)d_in[1];
    const float* b_attn = (const float*)d_in[2];
    const float* W_proj = (const float*)d_in[3];
    const float* b_proj = (const float*)d_in[4];
    float* out = (float*)d_out;

    __nv_bfloat16 *xh, *xl, *qkvh, *qkvl, *yh, *yl, *wah, *wal, *wph, *wpl;
    cudaGetSymbolAddress((void**)&xh, g_xh);
    cudaGetSymbolAddress((void**)&xl, g_xl);
    cudaGetSymbolAddress((void**)&qkvh, g_qkvh);
    cudaGetSymbolAddress((void**)&qkvl, g_qkvl);
    cudaGetSymbolAddress((void**)&yh, g_yh);
    cudaGetSymbolAddress((void**)&yl, g_yl);
    cudaGetSymbolAddress((void**)&wah, g_wah);
    cudaGetSymbolAddress((void**)&wal, g_wal);
    cudaGetSymbolAddress((void**)&wph, g_wph);
    cudaGetSymbolAddress((void**)&wpl, g_wpl);

    const int M = BB * TT;       // 4096
    const int N1 = 3 * CC;       // 3072
    const int N2 = CC;           // 1024
    const int K = CC;            // 1024

    cudaFuncSetAttribute(gemm_mma<true>,
                         cudaFuncAttributeMaxDynamicSharedMemorySize, GSMEM);
    cudaFuncSetAttribute(gemm_mma<false>,
                         cudaFuncAttributeMaxDynamicSharedMemorySize, GSMEM);

    // Prep: split x, transpose+split weights
    cvt_split<<<(M * K / 2 + 255) / 256, 256>>>(x, xh, xl, M * K / 2);
    {
        dim3 grid(N1 / 32, K / 32), blk(32, 8);
        cvt_split_t<<<grid, blk>>>(W_attn, wah, wal, K, N1);
    }
    {
        dim3 grid(N2 / 32, K / 32), blk(32, 8);
        cvt_split_t<<<grid, blk>>>(W_proj, wph, wpl, K, N2);
    }

    // 1) qkv(h/l) = split(x @ W_attn + b_attn)
    {
        dim3 grid(N1 / 128, M / 128);
        gemm_mma<true><<<grid, 256, GSMEM>>>(xh, xl, wah, wal, b_attn,
                                             nullptr, qkvh, qkvl, N1, K);
    }

    // 2) Flash attention -> y(h/l)
    {
        dim3 grid(TT / 64, HH, BB);
        attn_mma<<<grid, 128>>>(qkvh, qkvl, yh, yl);
    }

    // 3) out = y @ W_proj + b_proj (fp32)
    {
        dim3 grid(N2 / 128, M / 128);
        gemm_mma<false><<<grid, 256, GSMEM>>>(yh, yl, wph, wpl, b_proj,
                                              out, nullptr, nullptr, N2, K);
    }
}

// round 5
// speedup vs baseline: 3.2682x; 1.4671x over previous
#include <cuda_runtime.h>
#include <cuda_bf16.h>
#include <math_constants.h>
#include <cstdint>

// Problem constants
#define TT 2048
#define CC 1024
#define HH 16
#define DH 64
#define BB 2

#define SW(off) ((uint32_t)(off) ^ ((((uint32_t)(off)) >> 3) & 0x70u))

// ---------------------------------------------------------------------------
// PTX helpers (base-target safe: no tcgen05/TMEM)
// ---------------------------------------------------------------------------
__device__ __forceinline__ uint32_t smem_u32(const void* p) {
    uint32_t a;
    asm("{ .reg .u64 t; cvta.to.shared.u64 t, %1; cvt.u32.u64 %0, t; }"
        : "=r"(a) : "l"(p));
    return a;
}
__device__ __forceinline__ void ldsm_x4(uint32_t addr, uint32_t &r0, uint32_t &r1,
                                        uint32_t &r2, uint32_t &r3) {
    asm volatile("ldmatrix.sync.aligned.m8n8.x4.shared.b16 {%0,%1,%2,%3}, [%4];"
                 : "=r"(r0), "=r"(r1), "=r"(r2), "=r"(r3) : "r"(addr));
}
__device__ __forceinline__ void ldsm_x2t(uint32_t addr, uint32_t &r0, uint32_t &r1) {
    asm volatile("ldmatrix.sync.aligned.m8n8.x2.trans.shared.b16 {%0,%1}, [%2];"
                 : "=r"(r0), "=r"(r1) : "r"(addr));
}
__device__ __forceinline__ void mma_bf16(float* c, uint32_t a0, uint32_t a1,
                                         uint32_t a2, uint32_t a3,
                                         uint32_t b0, uint32_t b1) {
    asm volatile("mma.sync.aligned.m16n8k16.row.col.f32.bf16.bf16.f32 "
                 "{%0,%1,%2,%3}, {%4,%5,%6,%7}, {%8,%9}, {%0,%1,%2,%3};"
                 : "+f"(c[0]), "+f"(c[1]), "+f"(c[2]), "+f"(c[3])
                 : "r"(a0), "r"(a1), "r"(a2), "r"(a3), "r"(b0), "r"(b1));
}
__device__ __forceinline__ void cp_async16(uint32_t dst, const void* src) {
    asm volatile("cp.async.cg.shared.global [%0], [%1], 16;"
                 :: "r"(dst), "l"(src) : "memory");
}
#define CP_COMMIT() asm volatile("cp.async.commit_group;" ::: "memory")
#define CP_WAIT0()  asm volatile("cp.async.wait_group 0;" ::: "memory")
#define CP_WAIT1()  asm volatile("cp.async.wait_group 1;" ::: "memory")

__device__ __forceinline__ uint32_t pack_bf16x2(float lo, float hi) {
    uint32_t d;
    asm("cvt.rn.bf16x2.f32 %0, %1, %2;" : "=r"(d) : "f"(hi), "f"(lo));
    return d;
}
__device__ __forceinline__ uint32_t residual_pack(float a, float b, uint32_t hp) {
    float ra = a - __uint_as_float(hp << 16);
    float rb = b - __uint_as_float(hp & 0xFFFF0000u);
    return pack_bf16x2(ra, rb);
}
__device__ __forceinline__ void store_split(__nv_bfloat16* H, __nv_bfloat16* L,
                                            size_t off, float a, float b) {
    __nv_bfloat16 ha = __float2bfloat16(a), hb = __float2bfloat16(b);
    float ra = a - __bfloat162float(ha), rb = b - __bfloat162float(hb);
    *(__nv_bfloat162*)(H + off) = __halves2bfloat162(ha, hb);
    *(__nv_bfloat162*)(L + off) =
        __halves2bfloat162(__float2bfloat16(ra), __float2bfloat16(rb));
}

// ---------------------------------------------------------------------------
// Scratch
// ---------------------------------------------------------------------------
__device__ __nv_bfloat16 g_xh[(size_t)BB * TT * CC];
__device__ __nv_bfloat16 g_xl[(size_t)BB * TT * CC];
__device__ __nv_bfloat16 g_qkvh[(size_t)BB * TT * 3 * CC];
__device__ __nv_bfloat16 g_qkvl[(size_t)BB * TT * 3 * CC];
__device__ __nv_bfloat16 g_yh[(size_t)BB * TT * CC];
__device__ __nv_bfloat16 g_yl[(size_t)BB * TT * CC];
__device__ __nv_bfloat16 g_wah[(size_t)3 * CC * CC];  // W_attn^T [3C, C]
__device__ __nv_bfloat16 g_wal[(size_t)3 * CC * CC];
__device__ __nv_bfloat16 g_wph[(size_t)CC * CC];      // W_proj^T [C, C]
__device__ __nv_bfloat16 g_wpl[(size_t)CC * CC];

// ---------------------------------------------------------------------------
// fp32 -> bf16 hi/lo split (no transpose)
// ---------------------------------------------------------------------------
__global__ __launch_bounds__(256) void cvt_split(
    const float* __restrict__ in, __nv_bfloat16* __restrict__ h,
    __nv_bfloat16* __restrict__ l, int n2)
{
    int i = blockIdx.x * 256 + threadIdx.x;
    if (i >= n2) return;
    float2 v = ((const float2*)in)[i];
    __nv_bfloat16 h0 = __float2bfloat16(v.x);
    __nv_bfloat16 h1 = __float2bfloat16(v.y);
    __nv_bfloat16 l0 = __float2bfloat16(v.x - __bfloat162float(h0));
    __nv_bfloat16 l1 = __float2bfloat16(v.y - __bfloat162float(h1));
    ((__nv_bfloat162*)h)[i] = __halves2bfloat162(h0, h1);
    ((__nv_bfloat162*)l)[i] = __halves2bfloat162(l0, l1);
}

// ---------------------------------------------------------------------------
// fp32 [K,N] -> bf16 hi/lo transposed [N,K]
// ---------------------------------------------------------------------------
__global__ __launch_bounds__(256) void cvt_split_t(
    const float* __restrict__ in, __nv_bfloat16* __restrict__ h,
    __nv_bfloat16* __restrict__ l, int K, int N)
{
    __shared__ float ts[32][33];
    int tx = threadIdx.x, ty = threadIdx.y;   // (32, 8)
    int bx = blockIdx.x, by = blockIdx.y;
    #pragma unroll
    for (int j = 0; j < 4; j++) {
        int k = by * 32 + ty + j * 8;
        ts[ty + j * 8][tx] = in[(size_t)k * N + bx * 32 + tx];
    }
    __syncthreads();
    #pragma unroll
    for (int j = 0; j < 4; j++) {
        int nrow = bx * 32 + ty + j * 8;
        float v = ts[tx][ty + j * 8];
        __nv_bfloat16 hv = __float2bfloat16(v);
        __nv_bfloat16 lv = __float2bfloat16(v - __bfloat162float(hv));
        h[(size_t)nrow * K + by * 32 + tx] = hv;
        l[(size_t)nrow * K + by * 32 + tx] = lv;
    }
}

// ---------------------------------------------------------------------------
// Tensor-core GEMM (mma.sync bf16 hi/lo 3-combo, fp32 accum):
//   C[M,N] = A[M,K] @ B[N,K]^T + bias[N]
// CTA 128x128, 8 warps (64x32 each). k32 chunks, hi/lo packed in 128B rows,
// 3-stage cp.async pipeline, 2 CTAs/SM.
// Chunk buffer (32KB): A rows [hi 64B | lo 64B] 16KB @0, B same @16384.
// ---------------------------------------------------------------------------
#define STG_BYTES 32768
#define GSMEM (1024 + 3 * STG_BYTES)

template<bool SPLIT>
__global__ __launch_bounds__(256, 2) void gemm_mma(
    const __nv_bfloat16* __restrict__ Ah, const __nv_bfloat16* __restrict__ Al,
    const __nv_bfloat16* __restrict__ Bh, const __nv_bfloat16* __restrict__ Bl,
    const float* __restrict__ bias, float* __restrict__ Cf,
    __nv_bfloat16* __restrict__ Ch, __nv_bfloat16* __restrict__ Cl,
    int Ncols, int K)
{
    extern __shared__ char dsm[];
    const uint32_t sb = (smem_u32(dsm) + 1023u) & ~1023u;

    const int tid = threadIdx.x;
    const int lid = tid & 31;
    const int wid = tid >> 5;
    const int wm = (wid >> 2) * 64;
    const int wn = (wid & 3) * 32;
    const int bm = blockIdx.y * 128;
    const int bn = blockIdx.x * 128;

    float c[4][4][4];
    #pragma unroll
    for (int mt = 0; mt < 4; mt++)
        #pragma unroll
        for (int nt = 0; nt < 4; nt++)
            #pragma unroll
            for (int e = 0; e < 4; e++) c[mt][nt][e] = 0.f;

    // load one k32 chunk: 2048 x 16B. idx>>10: 0=A,1=B. c16 0-3 hi, 4-7 lo.
    auto load_chunk = [&](int ch, int stg) {
        const int k0 = ch << 5;
        const uint32_t base = sb + (uint32_t)(stg * STG_BYTES);
        #pragma unroll
        for (int j = 0; j < 8; j++) {
            int idx = tid + j * 256;
            int reg = idx >> 10;
            int row = (idx >> 3) & 127;
            int c16 = idx & 7;
            uint32_t dst = base + (uint32_t)(reg << 14) + SW(row * 128 + c16 * 16);
            int kc = k0 + ((c16 & 3) << 3);
            if (reg == 0) {
                size_t g = (size_t)(bm + row) * K + kc;
                cp_async16(dst, (c16 < 4 ? Ah : Al) + g);
            } else {
                size_t g = (size_t)(bn + row) * K + kc;
                cp_async16(dst, (c16 < 4 ? Bh : Bl) + g);
            }
        }
    };

    auto compute = [&](int stg) {
        const uint32_t tb = sb + (uint32_t)(stg * STG_BYTES);
        #pragma unroll
        for (int ks = 0; ks < 2; ks++) {
            uint32_t ah[4][4], al[4][4];
            #pragma unroll
            for (int mt = 0; mt < 4; mt++) {
                int row = wm + mt * 16 + (lid & 15);
                int colh = ks * 32 + ((lid >> 4) << 4);
                ldsm_x4(tb + SW(row * 128 + colh),
                        ah[mt][0], ah[mt][1], ah[mt][2], ah[mt][3]);
                ldsm_x4(tb + SW(row * 128 + 64 + colh),
                        al[mt][0], al[mt][1], al[mt][2], al[mt][3]);
            }
            #pragma unroll
            for (int ntp = 0; ntp < 2; ntp++) {
                int rowb = wn + ntp * 16 + ((lid >> 4) << 3) + (lid & 7);
                int colb = ks * 32 + (((lid >> 3) & 1) << 4);
                uint32_t bh[4], bl[4];
                ldsm_x4(tb + 16384 + SW(rowb * 128 + colb),
                        bh[0], bh[1], bh[2], bh[3]);
                ldsm_x4(tb + 16384 + SW(rowb * 128 + 64 + colb),
                        bl[0], bl[1], bl[2], bl[3]);
                #pragma unroll
                for (int half = 0; half < 2; half++) {
                    int nt = ntp * 2 + half;
                    uint32_t b0 = bh[half * 2], b1 = bh[half * 2 + 1];
                    uint32_t l0 = bl[half * 2], l1 = bl[half * 2 + 1];
                    #pragma unroll
                    for (int mt = 0; mt < 4; mt++) {
                        mma_bf16(c[mt][nt], ah[mt][0], ah[mt][1], ah[mt][2], ah[mt][3], b0, b1);
                        mma_bf16(c[mt][nt], ah[mt][0], ah[mt][1], ah[mt][2], ah[mt][3], l0, l1);
                        mma_bf16(c[mt][nt], al[mt][0], al[mt][1], al[mt][2], al[mt][3], b0, b1);
                    }
                }
            }
        }
    };

    const int nch = K >> 5;                 // 32 chunks for K=1024
    load_chunk(0, 0); CP_COMMIT();
    load_chunk(1, 1); CP_COMMIT();

    int stg = 0;
    for (int ch = 0; ch < nch; ch++) {
        if (ch + 2 < nch) CP_WAIT1(); else CP_WAIT0();
        __syncthreads();
        if (ch + 2 < nch) {
            load_chunk(ch + 2, (stg + 2) % 3);
            CP_COMMIT();
        }
        compute(stg);
        stg = (stg + 1) % 3;
    }

    // Epilogue
    #pragma unroll
    for (int mt = 0; mt < 4; mt++) {
        #pragma unroll
        for (int nt = 0; nt < 4; nt++) {
            int m0 = bm + wm + mt * 16 + (lid >> 2);
            int n  = bn + wn + nt * 8 + ((lid & 3) << 1);
            float b0 = bias[n], b1 = bias[n + 1];
            float v00 = c[mt][nt][0] + b0, v01 = c[mt][nt][1] + b1;
            float v10 = c[mt][nt][2] + b0, v11 = c[mt][nt][3] + b1;
            if (SPLIT) {
                store_split(Ch, Cl, (size_t)m0 * Ncols + n, v00, v01);
                store_split(Ch, Cl, (size_t)(m0 + 8) * Ncols + n, v10, v11);
            } else {
                float2 p0 = {v00, v01}, p1 = {v10, v11};
                *(float2*)(Cf + (size_t)m0 * Ncols + n) = p0;
                *(float2*)(Cf + (size_t)(m0 + 8) * Ncols + n) = p1;
            }
        }
    }
}

// ---------------------------------------------------------------------------
// Flash attention (causal) mma.sync bf16 hi/lo, cp.async double-buffered K/V.
// Block = (b, h, q-tile 64). 4 warps; warp w owns q rows w*16..w*16+15.
// Buffer (32KB): KH 0 | KL 8K | VH 16K | VL 24K. Two buffers.
// ---------------------------------------------------------------------------
#define ATT_SMEM (1024 + 2 * 32768)

__global__ __launch_bounds__(128) void attn_mma(
    const __nv_bfloat16* __restrict__ qkvh, const __nv_bfloat16* __restrict__ qkvl,
    __nv_bfloat16* __restrict__ yh, __nv_bfloat16* __restrict__ yl)
{
    extern __shared__ char asm_[];
    const uint32_t sb = (smem_u32(asm_) + 1023u) & ~1023u;
    char* smem = (char*)((uintptr_t)asm_ + (sb - smem_u32(asm_)));

    const int tid = threadIdx.x;
    const int lid = tid & 31;
    const int w = tid >> 5;
    const int qt = gridDim.x - 1 - blockIdx.x;    // longest first
    const int h = blockIdx.y;
    const int b = blockIdx.z;
    const size_t bT = (size_t)b * TT;
    const int RS = 3 * CC;

    // ---- stage Q (hi/lo) into buffer0 K regions, extract fragments
    {
        const __nv_bfloat16* qbh = qkvh + (bT + qt * 64) * RS + h * DH;
        const __nv_bfloat16* qbl = qkvl + (bT + qt * 64) * RS + h * DH;
        #pragma unroll
        for (int j = 0; j < 4; j++) {
            int idx = tid + j * 128;              // 0..511
            int row = idx >> 3, c16 = idx & 7;
            uint32_t sw = SW(row * 128 + c16 * 16);
            size_t g = (size_t)row * RS + c16 * 8;
            *(uint4*)(smem + sw)        = *(const uint4*)(qbh + g);
            *(uint4*)(smem + 8192 + sw) = *(const uint4*)(qbl + g);
        }
    }
    __syncthreads();
    uint32_t qh[4][4], ql[4][4];
    #pragma unroll
    for (int ks = 0; ks < 4; ks++) {
        int row = w * 16 + (lid & 15);
        uint32_t off = SW(row * 128 + ks * 32 + ((lid >> 4) << 4));
        ldsm_x4(sb + off, qh[ks][0], qh[ks][1], qh[ks][2], qh[ks][3]);
        ldsm_x4(sb + 8192 + off, ql[ks][0], ql[ks][1], ql[ks][2], ql[ks][3]);
    }
    __syncthreads();

    // async-load K/V hi/lo tiles for iteration kt into buffer `buf`
    auto load_kv = [&](int kt, int buf) {
        const __nv_bfloat16* base_h = qkvh + (bT + kt * 64) * RS + h * DH;
        const __nv_bfloat16* base_l = qkvl + (bT + kt * 64) * RS + h * DH;
        const uint32_t dbase = sb + (uint32_t)(buf * 32768);
        #pragma unroll
        for (int j = 0; j < 4; j++) {
            int idx = tid + j * 128;              // 0..511
            int row = idx >> 3, c16 = idx & 7;
            uint32_t sw = SW(row * 128 + c16 * 16);
            size_t gk = (size_t)row * RS + CC + c16 * 8;
            size_t gv = (size_t)row * RS + 2 * CC + c16 * 8;
            cp_async16(dbase + sw,         base_h + gk);
            cp_async16(dbase + 8192 + sw,  base_l + gk);
            cp_async16(dbase + 16384 + sw, base_h + gv);
            cp_async16(dbase + 24576 + sw, base_l + gv);
        }
    };

    float o[8][4];
    #pragma unroll
    for (int nt = 0; nt < 8; nt++)
        #pragma unroll
        for (int e = 0; e < 4; e++) o[nt][e] = 0.f;
    float m0 = -CUDART_INF_F, m1 = -CUDART_INF_F, l0 = 0.f, l1 = 0.f;
    const int r0 = w * 16 + (lid >> 2);
    const int cbase = (lid & 3) << 1;

    load_kv(0, 0); CP_COMMIT();

    for (int kt = 0; kt <= qt; kt++) {
        const int buf = kt & 1;
        const uint32_t tb = sb + (uint32_t)(buf * 32768);
        CP_WAIT0();
        __syncthreads();
        if (kt < qt) { load_kv(kt + 1, buf ^ 1); CP_COMMIT(); }

        // S = Q K^T  (16 x 64 per warp)
        float s[8][4];
        #pragma unroll
        for (int nt = 0; nt < 8; nt++)
            #pragma unroll
            for (int e = 0; e < 4; e++) s[nt][e] = 0.f;

        #pragma unroll
        for (int ks = 0; ks < 4; ks++) {
            #pragma unroll
            for (int ntp = 0; ntp < 4; ntp++) {
                int rowb = ntp * 16 + ((lid >> 4) << 3) + (lid & 7);
                uint32_t offb = SW(rowb * 128 + ks * 32 + (((lid >> 3) & 1) << 4));
                uint32_t kh[4], kl[4];
                ldsm_x4(tb + offb, kh[0], kh[1], kh[2], kh[3]);
                ldsm_x4(tb + 8192 + offb, kl[0], kl[1], kl[2], kl[3]);
                #pragma unroll
                for (int half = 0; half < 2; half++) {
                    int nt = ntp * 2 + half;
                    mma_bf16(s[nt], qh[ks][0], qh[ks][1], qh[ks][2], qh[ks][3],
                             kh[half * 2], kh[half * 2 + 1]);
                    mma_bf16(s[nt], qh[ks][0], qh[ks][1], qh[ks][2], qh[ks][3],
                             kl[half * 2], kl[half * 2 + 1]);
                    mma_bf16(s[nt], ql[ks][0], ql[ks][1], ql[ks][2], ql[ks][3],
                             kh[half * 2], kh[half * 2 + 1]);
                }
            }
        }

        // scale + causal mask (diagonal tile only)
        #pragma unroll
        for (int nt = 0; nt < 8; nt++)
            #pragma unroll
            for (int e = 0; e < 4; e++) s[nt][e] *= 0.125f;
        if (kt == qt) {
            #pragma unroll
            for (int nt = 0; nt < 8; nt++) {
                int cc0 = nt * 8 + cbase;
                if (cc0     > r0)     s[nt][0] = -CUDART_INF_F;
                if (cc0 + 1 > r0)     s[nt][1] = -CUDART_INF_F;
                if (cc0     > r0 + 8) s[nt][2] = -CUDART_INF_F;
                if (cc0 + 1 > r0 + 8) s[nt][3] = -CUDART_INF_F;
            }
        }

        // online softmax (2 rows per thread; quad shares a row)
        float mx0 = -CUDART_INF_F, mx1 = -CUDART_INF_F;
        #pragma unroll
        for (int nt = 0; nt < 8; nt++) {
            mx0 = fmaxf(mx0, fmaxf(s[nt][0], s[nt][1]));
            mx1 = fmaxf(mx1, fmaxf(s[nt][2], s[nt][3]));
        }
        mx0 = fmaxf(mx0, __shfl_xor_sync(0xffffffffu, mx0, 1));
        mx0 = fmaxf(mx0, __shfl_xor_sync(0xffffffffu, mx0, 2));
        mx1 = fmaxf(mx1, __shfl_xor_sync(0xffffffffu, mx1, 1));
        mx1 = fmaxf(mx1, __shfl_xor_sync(0xffffffffu, mx1, 2));
        float mn0 = fmaxf(m0, mx0), mn1 = fmaxf(m1, mx1);
        float a0 = __expf(m0 - mn0), a1 = __expf(m1 - mn1);
        float su0 = 0.f, su1 = 0.f;
        #pragma unroll
        for (int nt = 0; nt < 8; nt++) {
            s[nt][0] = __expf(s[nt][0] - mn0);
            s[nt][1] = __expf(s[nt][1] - mn0);
            s[nt][2] = __expf(s[nt][2] - mn1);
            s[nt][3] = __expf(s[nt][3] - mn1);
            su0 += s[nt][0] + s[nt][1];
            su1 += s[nt][2] + s[nt][3];
        }
        su0 += __shfl_xor_sync(0xffffffffu, su0, 1);
        su0 += __shfl_xor_sync(0xffffffffu, su0, 2);
        su1 += __shfl_xor_sync(0xffffffffu, su1, 1);
        su1 += __shfl_xor_sync(0xffffffffu, su1, 2);
        l0 = l0 * a0 + su0;  l1 = l1 * a1 + su1;
        m0 = mn0;  m1 = mn1;
        #pragma unroll
        for (int nt = 0; nt < 8; nt++) {
            o[nt][0] *= a0; o[nt][1] *= a0;
            o[nt][2] *= a1; o[nt][3] *= a1;
        }

        // PV: P fragments from S regs (hi + residual), V via ldmatrix.trans
        #pragma unroll
        for (int ks = 0; ks < 4; ks++) {
            const int t0 = ks * 2, t1 = ks * 2 + 1;
            uint32_t ph0 = pack_bf16x2(s[t0][0], s[t0][1]);
            uint32_t ph1 = pack_bf16x2(s[t0][2], s[t0][3]);
            uint32_t ph2 = pack_bf16x2(s[t1][0], s[t1][1]);
            uint32_t ph3 = pack_bf16x2(s[t1][2], s[t1][3]);
            uint32_t pl0 = residual_pack(s[t0][0], s[t0][1], ph0);
            uint32_t pl1 = residual_pack(s[t0][2], s[t0][3], ph1);
            uint32_t pl2 = residual_pack(s[t1][0], s[t1][1], ph2);
            uint32_t pl3 = residual_pack(s[t1][2], s[t1][3], ph3);
            int rowv = ks * 16 + (lid & 15);
            #pragma unroll
            for (int nt = 0; nt < 8; nt++) {
                uint32_t offv = SW(rowv * 128 + nt * 16);
                uint32_t vh0, vh1, vl0, vl1;
                ldsm_x2t(tb + 16384 + offv, vh0, vh1);
                ldsm_x2t(tb + 24576 + offv, vl0, vl1);
                mma_bf16(o[nt], ph0, ph1, ph2, ph3, vh0, vh1);
                mma_bf16(o[nt], ph0, ph1, ph2, ph3, vl0, vl1);
                mma_bf16(o[nt], pl0, pl1, pl2, pl3, vh0, vh1);
            }
        }
        __syncthreads();
    }

    // Epilogue: normalize, split to bf16 hi/lo for proj GEMM
    float i0 = 1.f / l0, i1 = 1.f / l1;
    size_t row0 = (bT + (size_t)qt * 64 + r0) * CC + h * DH;
    size_t row1 = row0 + (size_t)8 * CC;
    #pragma unroll
    for (int nt = 0; nt < 8; nt++) {
        int n = nt * 8 + cbase;
        store_split(yh, yl, row0 + n, o[nt][0] * i0, o[nt][1] * i0);
        store_split(yh, yl, row1 + n, o[nt][2] * i1, o[nt][3] * i1);
    }
}

// ---------------------------------------------------------------------------
extern "C" void kernel_launch(void* const* d_in, const int* in_sizes, int n_in,
                              void* d_out, int out_size)
{
    const float* x      = (const float*)d_in[0];
    const float* W_attn = (const float*)d_in[1];
    const float* b_attn = (const float*)d_in[2];
    const float* W_proj = (const float*)d_in[3];
    const float* b_proj = (const float*)d_in[4];
    float* out = (float*)d_out;

    __nv_bfloat16 *xh, *xl, *qkvh, *qkvl, *yh, *yl, *wah, *wal, *wph, *wpl;
    cudaGetSymbolAddress((void**)&xh, g_xh);
    cudaGetSymbolAddress((void**)&xl, g_xl);
    cudaGetSymbolAddress((void**)&qkvh, g_qkvh);
    cudaGetSymbolAddress((void**)&qkvl, g_qkvl);
    cudaGetSymbolAddress((void**)&yh, g_yh);
    cudaGetSymbolAddress((void**)&yl, g_yl);
    cudaGetSymbolAddress((void**)&wah, g_wah);
    cudaGetSymbolAddress((void**)&wal, g_wal);
    cudaGetSymbolAddress((void**)&wph, g_wph);
    cudaGetSymbolAddress((void**)&wpl, g_wpl);

    const int M = BB * TT;       // 4096
    const int N1 = 3 * CC;       // 3072
    const int N2 = CC;           // 1024
    const int K = CC;            // 1024

    cudaFuncSetAttribute(gemm_mma<true>,
                         cudaFuncAttributeMaxDynamicSharedMemorySize, GSMEM);
    cudaFuncSetAttribute(gemm_mma<false>,
                         cudaFuncAttributeMaxDynamicSharedMemorySize, GSMEM);
    cudaFuncSetAttribute(attn_mma,
                         cudaFuncAttributeMaxDynamicSharedMemorySize, ATT_SMEM);

    // Prep: split x, transpose+split weights
    cvt_split<<<(M * K / 2 + 255) / 256, 256>>>(x, xh, xl, M * K / 2);
    {
        dim3 grid(N1 / 32, K / 32), blk(32, 8);
        cvt_split_t<<<grid, blk>>>(W_attn, wah, wal, K, N1);
    }
    {
        dim3 grid(N2 / 32, K / 32), blk(32, 8);
        cvt_split_t<<<grid, blk>>>(W_proj, wph, wpl, K, N2);
    }

    // 1) qkv(h/l) = split(x @ W_attn + b_attn)
    {
        dim3 grid(N1 / 128, M / 128);
        gemm_mma<true><<<grid, 256, GSMEM>>>(xh, xl, wah, wal, b_attn,
                                             nullptr, qkvh, qkvl, N1, K);
    }

    // 2) Flash attention -> y(h/l)
    {
        dim3 grid(TT / 64, HH, BB);
        attn_mma<<<grid, 128, ATT_SMEM>>>(qkvh, qkvl, yh, yl);
    }

    // 3) out = y @ W_proj + b_proj (fp32)
    {
        dim3 grid(N2 / 128, M / 128);
        gemm_mma<false><<<grid, 256, GSMEM>>>(yh, yl, wph, wpl, b_proj,
                                              out, nullptr, nullptr, N2, K);
    }
}

// round 6
// speedup vs baseline: 4.6932x; 1.4360x over previous
#include <cuda_runtime.h>
#include <cuda_fp16.h>
#include <math_constants.h>
#include <cstdint>

// Problem constants
#define TT 2048
#define CC 1024
#define HH 16
#define DH 64
#define BB 2

#define SW(off) ((uint32_t)(off) ^ ((((uint32_t)(off)) >> 3) & 0x70u))

// ---------------------------------------------------------------------------
// PTX helpers (base-target safe)
// ---------------------------------------------------------------------------
__device__ __forceinline__ uint32_t smem_u32(const void* p) {
    uint32_t a;
    asm("{ .reg .u64 t; cvta.to.shared.u64 t, %1; cvt.u32.u64 %0, t; }"
        : "=r"(a) : "l"(p));
    return a;
}
__device__ __forceinline__ void ldsm_x4(uint32_t addr, uint32_t &r0, uint32_t &r1,
                                        uint32_t &r2, uint32_t &r3) {
    asm volatile("ldmatrix.sync.aligned.m8n8.x4.shared.b16 {%0,%1,%2,%3}, [%4];"
                 : "=r"(r0), "=r"(r1), "=r"(r2), "=r"(r3) : "r"(addr));
}
__device__ __forceinline__ void ldsm_x4t(uint32_t addr, uint32_t &r0, uint32_t &r1,
                                         uint32_t &r2, uint32_t &r3) {
    asm volatile("ldmatrix.sync.aligned.m8n8.x4.trans.shared.b16 {%0,%1,%2,%3}, [%4];"
                 : "=r"(r0), "=r"(r1), "=r"(r2), "=r"(r3) : "r"(addr));
}
__device__ __forceinline__ void mma_f16(float* c, uint32_t a0, uint32_t a1,
                                        uint32_t a2, uint32_t a3,
                                        uint32_t b0, uint32_t b1) {
    asm volatile("mma.sync.aligned.m16n8k16.row.col.f32.f16.f16.f32 "
                 "{%0,%1,%2,%3}, {%4,%5,%6,%7}, {%8,%9}, {%0,%1,%2,%3};"
                 : "+f"(c[0]), "+f"(c[1]), "+f"(c[2]), "+f"(c[3])
                 : "r"(a0), "r"(a1), "r"(a2), "r"(a3), "r"(b0), "r"(b1));
}
__device__ __forceinline__ void cp_async16(uint32_t dst, const void* src) {
    asm volatile("cp.async.cg.shared.global [%0], [%1], 16;"
                 :: "r"(dst), "l"(src) : "memory");
}
#define CP_COMMIT() asm volatile("cp.async.commit_group;" ::: "memory")
#define CP_WAIT0()  asm volatile("cp.async.wait_group 0;" ::: "memory")
#define CP_WAIT1()  asm volatile("cp.async.wait_group 1;" ::: "memory")

__device__ __forceinline__ uint32_t pack_f16x2(float lo, float hi) {
    uint32_t d;
    asm("cvt.rn.f16x2.f32 %0, %1, %2;" : "=r"(d) : "f"(hi), "f"(lo));
    return d;
}

// ---------------------------------------------------------------------------
// Scratch
// ---------------------------------------------------------------------------
__device__ __half g_xh[(size_t)BB * TT * CC];
__device__ __half g_qkvh[(size_t)BB * TT * 3 * CC];
__device__ __half g_qkvl[(size_t)BB * TT * 3 * CC];   // only K,V region used
__device__ __half g_yh[(size_t)BB * TT * CC];
__device__ __half g_wah[(size_t)3 * CC * CC];          // W_attn^T [3C, C]
__device__ __half g_wal[(size_t)3 * CC * CC];
__device__ __half g_wph[(size_t)CC * CC];              // W_proj^T [C, C]
__device__ __half g_wpl[(size_t)CC * CC];

// ---------------------------------------------------------------------------
// fp32 -> fp16 convert (hi only)
// ---------------------------------------------------------------------------
__global__ __launch_bounds__(256) void cvt_half(
    const float* __restrict__ in, __half* __restrict__ h, int n2)
{
    int i = blockIdx.x * 256 + threadIdx.x;
    if (i >= n2) return;
    float2 v = ((const float2*)in)[i];
    ((half2*)h)[i] = __floats2half2_rn(v.x, v.y);
}

// ---------------------------------------------------------------------------
// fp32 [K,N] -> fp16 hi/lo transposed [N,K]
// ---------------------------------------------------------------------------
__global__ __launch_bounds__(256) void cvt_split_t(
    const float* __restrict__ in, __half* __restrict__ h,
    __half* __restrict__ l, int K, int N)
{
    __shared__ float ts[32][33];
    int tx = threadIdx.x, ty = threadIdx.y;   // (32, 8)
    int bx = blockIdx.x, by = blockIdx.y;
    #pragma unroll
    for (int j = 0; j < 4; j++) {
        int k = by * 32 + ty + j * 8;
        ts[ty + j * 8][tx] = in[(size_t)k * N + bx * 32 + tx];
    }
    __syncthreads();
    #pragma unroll
    for (int j = 0; j < 4; j++) {
        int nrow = bx * 32 + ty + j * 8;
        float v = ts[tx][ty + j * 8];
        __half hv = __float2half(v);
        __half lv = __float2half(v - __half2float(hv));
        h[(size_t)nrow * K + by * 32 + tx] = hv;
        l[(size_t)nrow * K + by * 32 + tx] = lv;
    }
}

// ---------------------------------------------------------------------------
// Tensor-core GEMM, fp16 2-combo: C = Ah @ (Bh + Bl)^T + bias
// CTA 128x128, 8 warps (64x32), k64 chunks, 2-stage cp.async, 2 CTAs/SM.
// Stage (48KB): A 16KB @0 | Bh 16KB @16384 | Bl 16KB @32768 (128B rows, SW128)
// ---------------------------------------------------------------------------
#define STG_BYTES 49152
#define GSMEM (2 * STG_BYTES + 1024)

template<bool SPLIT>
__global__ __launch_bounds__(256, 2) void gemm_mma(
    const __half* __restrict__ Ah,
    const __half* __restrict__ Bh, const __half* __restrict__ Bl,
    const float* __restrict__ bias, float* __restrict__ Cf,
    __half* __restrict__ Ch, __half* __restrict__ Cl,
    int Ncols, int K, int lo_min_col)
{
    extern __shared__ char dsm[];
    const uint32_t sb = (smem_u32(dsm) + 1023u) & ~1023u;

    const int tid = threadIdx.x;
    const int lid = tid & 31;
    const int wid = tid >> 5;
    const int wm = (wid >> 2) * 64;
    const int wn = (wid & 3) * 32;
    const int bm = blockIdx.y * 128;
    const int bn = blockIdx.x * 128;

    float c[4][4][4];
    #pragma unroll
    for (int mt = 0; mt < 4; mt++)
        #pragma unroll
        for (int nt = 0; nt < 4; nt++)
            #pragma unroll
            for (int e = 0; e < 4; e++) c[mt][nt][e] = 0.f;

    // one k64 chunk = 3072 x 16B: reg 0=A, 1=Bh, 2=Bl; 12 cp.async/thread
    auto load_chunk = [&](int ch, int stg) {
        const int k0 = ch << 6;
        const uint32_t base = sb + (uint32_t)(stg * STG_BYTES);
        #pragma unroll
        for (int j = 0; j < 12; j++) {
            int idx = tid + j * 256;
            int reg = idx >> 10;
            int row = (idx >> 3) & 127;
            int c16 = idx & 7;
            uint32_t dst = base + (uint32_t)(reg << 14) + SW(row * 128 + c16 * 16);
            int kc = k0 + c16 * 8;
            const __half* src;
            if (reg == 0)      src = Ah + (size_t)(bm + row) * K + kc;
            else if (reg == 1) src = Bh + (size_t)(bn + row) * K + kc;
            else               src = Bl + (size_t)(bn + row) * K + kc;
            cp_async16(dst, src);
        }
    };

    auto compute = [&](int stg) {
        const uint32_t tb = sb + (uint32_t)(stg * STG_BYTES);
        #pragma unroll
        for (int ks = 0; ks < 4; ks++) {
            uint32_t ah[4][4];
            #pragma unroll
            for (int mt = 0; mt < 4; mt++) {
                int row = wm + mt * 16 + (lid & 15);
                ldsm_x4(tb + SW(row * 128 + ks * 32 + ((lid >> 4) << 4)),
                        ah[mt][0], ah[mt][1], ah[mt][2], ah[mt][3]);
            }
            #pragma unroll
            for (int ntp = 0; ntp < 2; ntp++) {
                int rowb = wn + ntp * 16 + ((lid >> 4) << 3) + (lid & 7);
                uint32_t offb = SW(rowb * 128 + ks * 32 + (((lid >> 3) & 1) << 4));
                uint32_t bh[4], bl[4];
                ldsm_x4(tb + 16384 + offb, bh[0], bh[1], bh[2], bh[3]);
                ldsm_x4(tb + 32768 + offb, bl[0], bl[1], bl[2], bl[3]);
                #pragma unroll
                for (int half = 0; half < 2; half++) {
                    int nt = ntp * 2 + half;
                    #pragma unroll
                    for (int mt = 0; mt < 4; mt++) {
                        mma_f16(c[mt][nt], ah[mt][0], ah[mt][1], ah[mt][2], ah[mt][3],
                                bh[half * 2], bh[half * 2 + 1]);
                        mma_f16(c[mt][nt], ah[mt][0], ah[mt][1], ah[mt][2], ah[mt][3],
                                bl[half * 2], bl[half * 2 + 1]);
                    }
                }
            }
        }
    };

    const int nch = K >> 6;                 // 16 chunks for K=1024
    load_chunk(0, 0); CP_COMMIT();

    int stg = 0;
    for (int ch = 0; ch < nch; ch++) {
        __syncthreads();                     // buffer stg^1 free (computed ch-1)
        if (ch + 1 < nch) { load_chunk(ch + 1, stg ^ 1); CP_COMMIT(); }
        if (ch + 1 < nch) CP_WAIT1(); else CP_WAIT0();
        __syncthreads();
        compute(stg);
        stg ^= 1;
    }

    // Epilogue
    #pragma unroll
    for (int mt = 0; mt < 4; mt++) {
        #pragma unroll
        for (int nt = 0; nt < 4; nt++) {
            int m0 = bm + wm + mt * 16 + (lid >> 2);
            int n  = bn + wn + nt * 8 + ((lid & 3) << 1);
            float b0 = bias[n], b1 = bias[n + 1];
            float v00 = c[mt][nt][0] + b0, v01 = c[mt][nt][1] + b1;
            float v10 = c[mt][nt][2] + b0, v11 = c[mt][nt][3] + b1;
            if (SPLIT) {
                __half h00 = __float2half(v00), h01 = __float2half(v01);
                __half h10 = __float2half(v10), h11 = __float2half(v11);
                *(half2*)(Ch + (size_t)m0 * Ncols + n) = __halves2half2(h00, h01);
                *(half2*)(Ch + (size_t)(m0 + 8) * Ncols + n) = __halves2half2(h10, h11);
                if (n >= lo_min_col) {
                    *(half2*)(Cl + (size_t)m0 * Ncols + n) = __halves2half2(
                        __float2half(v00 - __half2float(h00)),
                        __float2half(v01 - __half2float(h01)));
                    *(half2*)(Cl + (size_t)(m0 + 8) * Ncols + n) = __halves2half2(
                        __float2half(v10 - __half2float(h10)),
                        __float2half(v11 - __half2float(h11)));
                }
            } else {
                float2 p0 = {v00, v01}, p1 = {v10, v11};
                *(float2*)(Cf + (size_t)m0 * Ncols + n) = p0;
                *(float2*)(Cf + (size_t)(m0 + 8) * Ncols + n) = p1;
            }
        }
    }
}

// ---------------------------------------------------------------------------
// Flash attention (causal), fp16 2-combo.
// Block = (b, h, q-tile 128). 8 warps, warp w owns q rows w*16..w*16+15.
// S = Qh (Kh+Kl)^T; PV: O += Ph (Vh+Vl). Output fp16 hi.
// kv buffer (32KB): Kh 0 | Kl 8K | Vh 16K | Vl 24K. Double buffered.
// ---------------------------------------------------------------------------
#define ATT_SMEM (1024 + 2 * 32768)

__global__ __launch_bounds__(256, 2) void attn_mma(
    const __half* __restrict__ qkvh, const __half* __restrict__ qkvl,
    __half* __restrict__ yh)
{
    extern __shared__ char asm_[];
    const uint32_t sb = (smem_u32(asm_) + 1023u) & ~1023u;

    const int tid = threadIdx.x;
    const int lid = tid & 31;
    const int w = tid >> 5;
    const int qt = gridDim.x - 1 - blockIdx.x;    // longest first
    const int h = blockIdx.y;
    const int b = blockIdx.z;
    const size_t bT = (size_t)b * TT;
    const int RS = 3 * CC;

    // ---- stage Q hi (128 x 64 fp16 = 16KB) into buffer0, extract fragments
    {
        const __half* qg = qkvh + (bT + qt * 128) * RS + h * DH;
        #pragma unroll
        for (int j = 0; j < 4; j++) {
            int idx = tid + j * 256;              // 0..1023
            int row = idx >> 3, c16 = idx & 7;
            cp_async16(sb + SW(row * 128 + c16 * 16),
                       qg + (size_t)row * RS + c16 * 8);
        }
    }
    CP_COMMIT(); CP_WAIT0();
    __syncthreads();
    uint32_t qh[4][4];
    #pragma unroll
    for (int ks = 0; ks < 4; ks++) {
        int row = w * 16 + (lid & 15);
        ldsm_x4(sb + SW(row * 128 + ks * 32 + ((lid >> 4) << 4)),
                qh[ks][0], qh[ks][1], qh[ks][2], qh[ks][3]);
    }
    __syncthreads();

    auto load_kv = [&](int kt, int buf) {
        const __half* kh_g = qkvh + (bT + kt * 64) * RS + CC + h * DH;
        const __half* kl_g = qkvl + (bT + kt * 64) * RS + CC + h * DH;
        const __half* vh_g = kh_g + CC;
        const __half* vl_g = kl_g + CC;
        const uint32_t base = sb + (uint32_t)(buf * 32768);
        #pragma unroll
        for (int j = 0; j < 2; j++) {
            int idx = tid + j * 256;              // 0..511
            int row = idx >> 3, c16 = idx & 7;
            uint32_t sw = SW(row * 128 + c16 * 16);
            size_t g = (size_t)row * RS + c16 * 8;
            cp_async16(base + sw,         kh_g + g);
            cp_async16(base + 8192 + sw,  kl_g + g);
            cp_async16(base + 16384 + sw, vh_g + g);
            cp_async16(base + 24576 + sw, vl_g + g);
        }
    };

    float o[8][4];
    #pragma unroll
    for (int nt = 0; nt < 8; nt++)
        #pragma unroll
        for (int e = 0; e < 4; e++) o[nt][e] = 0.f;
    float m0 = -CUDART_INF_F, m1 = -CUDART_INF_F, l0 = 0.f, l1 = 0.f;
    const int gr0 = qt * 128 + w * 16;            // warp's first global q row
    const int r0 = (lid >> 2);                    // in-warp row (second = +8)
    const int cbase = (lid & 3) << 1;

    const int kt_max = 2 * qt + 1;
    load_kv(0, 0); CP_COMMIT();

    for (int kt = 0; kt <= kt_max; kt++) {
        const int buf = kt & 1;
        const uint32_t tb = sb + (uint32_t)(buf * 32768);
        CP_WAIT0();
        __syncthreads();
        if (kt < kt_max) { load_kv(kt + 1, buf ^ 1); CP_COMMIT(); }

        if (kt * 64 <= gr0 + 15) {                // tile not fully masked
            // S = Qh (Kh+Kl)^T
            float s[8][4];
            #pragma unroll
            for (int nt = 0; nt < 8; nt++)
                #pragma unroll
                for (int e = 0; e < 4; e++) s[nt][e] = 0.f;

            #pragma unroll
            for (int ks = 0; ks < 4; ks++) {
                #pragma unroll
                for (int ntp = 0; ntp < 4; ntp++) {
                    int rowb = ntp * 16 + ((lid >> 4) << 3) + (lid & 7);
                    uint32_t offb = SW(rowb * 128 + ks * 32 + (((lid >> 3) & 1) << 4));
                    uint32_t kh[4], kl[4];
                    ldsm_x4(tb + offb, kh[0], kh[1], kh[2], kh[3]);
                    ldsm_x4(tb + 8192 + offb, kl[0], kl[1], kl[2], kl[3]);
                    #pragma unroll
                    for (int half = 0; half < 2; half++) {
                        int nt = ntp * 2 + half;
                        mma_f16(s[nt], qh[ks][0], qh[ks][1], qh[ks][2], qh[ks][3],
                                kh[half * 2], kh[half * 2 + 1]);
                        mma_f16(s[nt], qh[ks][0], qh[ks][1], qh[ks][2], qh[ks][3],
                                kl[half * 2], kl[half * 2 + 1]);
                    }
                }
            }

            // scale + causal mask
            #pragma unroll
            for (int nt = 0; nt < 8; nt++)
                #pragma unroll
                for (int e = 0; e < 4; e++) s[nt][e] *= 0.125f;
            if (kt * 64 + 63 > gr0) {             // tile overlaps diagonal
                #pragma unroll
                for (int nt = 0; nt < 8; nt++) {
                    int gc = kt * 64 + nt * 8 + cbase;
                    int gr = gr0 + r0;
                    if (gc     > gr)     s[nt][0] = -CUDART_INF_F;
                    if (gc + 1 > gr)     s[nt][1] = -CUDART_INF_F;
                    if (gc     > gr + 8) s[nt][2] = -CUDART_INF_F;
                    if (gc + 1 > gr + 8) s[nt][3] = -CUDART_INF_F;
                }
            }

            // online softmax (quad of 4 lanes shares a row)
            float mx0 = -CUDART_INF_F, mx1 = -CUDART_INF_F;
            #pragma unroll
            for (int nt = 0; nt < 8; nt++) {
                mx0 = fmaxf(mx0, fmaxf(s[nt][0], s[nt][1]));
                mx1 = fmaxf(mx1, fmaxf(s[nt][2], s[nt][3]));
            }
            mx0 = fmaxf(mx0, __shfl_xor_sync(0xffffffffu, mx0, 1));
            mx0 = fmaxf(mx0, __shfl_xor_sync(0xffffffffu, mx0, 2));
            mx1 = fmaxf(mx1, __shfl_xor_sync(0xffffffffu, mx1, 1));
            mx1 = fmaxf(mx1, __shfl_xor_sync(0xffffffffu, mx1, 2));
            float mn0 = fmaxf(m0, mx0), mn1 = fmaxf(m1, mx1);
            float a0 = __expf(m0 - mn0), a1 = __expf(m1 - mn1);
            float su0 = 0.f, su1 = 0.f;
            #pragma unroll
            for (int nt = 0; nt < 8; nt++) {
                s[nt][0] = __expf(s[nt][0] - mn0);
                s[nt][1] = __expf(s[nt][1] - mn0);
                s[nt][2] = __expf(s[nt][2] - mn1);
                s[nt][3] = __expf(s[nt][3] - mn1);
                su0 += s[nt][0] + s[nt][1];
                su1 += s[nt][2] + s[nt][3];
            }
            su0 += __shfl_xor_sync(0xffffffffu, su0, 1);
            su0 += __shfl_xor_sync(0xffffffffu, su0, 2);
            su1 += __shfl_xor_sync(0xffffffffu, su1, 1);
            su1 += __shfl_xor_sync(0xffffffffu, su1, 2);
            l0 = l0 * a0 + su0;  l1 = l1 * a1 + su1;
            m0 = mn0;  m1 = mn1;
            #pragma unroll
            for (int nt = 0; nt < 8; nt++) {
                o[nt][0] *= a0; o[nt][1] *= a0;
                o[nt][2] *= a1; o[nt][3] *= a1;
            }

            // PV: P hi only; V hi/lo via ldmatrix.x4.trans
            #pragma unroll
            for (int ks = 0; ks < 4; ks++) {
                const int t0 = ks * 2, t1 = ks * 2 + 1;
                uint32_t ph0 = pack_f16x2(s[t0][0], s[t0][1]);
                uint32_t ph1 = pack_f16x2(s[t0][2], s[t0][3]);
                uint32_t ph2 = pack_f16x2(s[t1][0], s[t1][1]);
                uint32_t ph3 = pack_f16x2(s[t1][2], s[t1][3]);
                int rowv = ks * 16 + (lid & 15);
                #pragma unroll
                for (int nt2 = 0; nt2 < 4; nt2++) {
                    uint32_t offv = SW(rowv * 128 + nt2 * 32 + ((lid >> 4) << 4));
                    uint32_t vh[4], vl[4];
                    ldsm_x4t(tb + 16384 + offv, vh[0], vh[1], vh[2], vh[3]);
                    ldsm_x4t(tb + 24576 + offv, vl[0], vl[1], vl[2], vl[3]);
                    mma_f16(o[nt2 * 2],     ph0, ph1, ph2, ph3, vh[0], vh[1]);
                    mma_f16(o[nt2 * 2],     ph0, ph1, ph2, ph3, vl[0], vl[1]);
                    mma_f16(o[nt2 * 2 + 1], ph0, ph1, ph2, ph3, vh[2], vh[3]);
                    mma_f16(o[nt2 * 2 + 1], ph0, ph1, ph2, ph3, vl[2], vl[3]);
                }
            }
        }
        __syncthreads();
    }

    // Epilogue: normalize, fp16 hi out
    float i0 = 1.f / l0, i1 = 1.f / l1;
    size_t row0 = (bT + (size_t)qt * 128 + w * 16 + r0) * CC + h * DH;
    size_t row1 = row0 + (size_t)8 * CC;
    #pragma unroll
    for (int nt = 0; nt < 8; nt++) {
        int n = nt * 8 + cbase;
        *(half2*)(yh + row0 + n) =
            __floats2half2_rn(o[nt][0] * i0, o[nt][1] * i0);
        *(half2*)(yh + row1 + n) =
            __floats2half2_rn(o[nt][2] * i1, o[nt][3] * i1);
    }
}

// ---------------------------------------------------------------------------
extern "C" void kernel_launch(void* const* d_in, const int* in_sizes, int n_in,
                              void* d_out, int out_size)
{
    const float* x      = (const float*)d_in[0];
    const float* W_attn = (const float*)d_in[1];
    const float* b_attn = (const float*)d_in[2];
    const float* W_proj = (const float*)d_in[3];
    const float* b_proj = (const float*)d_in[4];
    float* out = (float*)d_out;

    __half *xh, *qkvh, *qkvl, *yh, *wah, *wal, *wph, *wpl;
    cudaGetSymbolAddress((void**)&xh, g_xh);
    cudaGetSymbolAddress((void**)&qkvh, g_qkvh);
    cudaGetSymbolAddress((void**)&qkvl, g_qkvl);
    cudaGetSymbolAddress((void**)&yh, g_yh);
    cudaGetSymbolAddress((void**)&wah, g_wah);
    cudaGetSymbolAddress((void**)&wal, g_wal);
    cudaGetSymbolAddress((void**)&wph, g_wph);
    cudaGetSymbolAddress((void**)&wpl, g_wpl);

    const int M = BB * TT;       // 4096
    const int N1 = 3 * CC;       // 3072
    const int N2 = CC;           // 1024
    const int K = CC;            // 1024

    cudaFuncSetAttribute(gemm_mma<true>,
                         cudaFuncAttributeMaxDynamicSharedMemorySize, GSMEM);
    cudaFuncSetAttribute(gemm_mma<false>,
                         cudaFuncAttributeMaxDynamicSharedMemorySize, GSMEM);
    cudaFuncSetAttribute(attn_mma,
                         cudaFuncAttributeMaxDynamicSharedMemorySize, ATT_SMEM);

    // Prep: x -> fp16 hi; weights -> transposed fp16 hi/lo
    cvt_half<<<(M * K / 2 + 255) / 256, 256>>>(x, xh, M * K / 2);
    {
        dim3 grid(N1 / 32, K / 32), blk(32, 8);
        cvt_split_t<<<grid, blk>>>(W_attn, wah, wal, K, N1);
    }
    {
        dim3 grid(N2 / 32, K / 32), blk(32, 8);
        cvt_split_t<<<grid, blk>>>(W_proj, wph, wpl, K, N2);
    }

    // 1) qkv = x @ W_attn + b_attn  (hi always; lo only for K,V columns)
    {
        dim3 grid(N1 / 128, M / 128);
        gemm_mma<true><<<grid, 256, GSMEM>>>(xh, wah, wal, b_attn,
                                             nullptr, qkvh, qkvl, N1, K, CC);
    }

    // 2) Flash attention -> y (fp16 hi)
    {
        dim3 grid(TT / 128, HH, BB);
        attn_mma<<<grid, 256, ATT_SMEM>>>(qkvh, qkvl, yh);
    }

    // 3) out = y @ W_proj + b_proj (fp32)
    {
        dim3 grid(N2 / 128, M / 128);
        gemm_mma<false><<<grid, 256, GSMEM>>>(yh, wph, wpl, b_proj,
                                              out, nullptr, nullptr, N2, K, 0);
    }
}

// round 7
// speedup vs baseline: 5.9142x; 1.2602x over previous
#include <cuda_runtime.h>
#include <cuda_fp16.h>
#include <math_constants.h>
#include <cstdint>

// Problem constants
#define TT 2048
#define CC 1024
#define HH 16
#define DH 64
#define BB 2

#define SW(off) ((uint32_t)(off) ^ ((((uint32_t)(off)) >> 3) & 0x70u))

// ---------------------------------------------------------------------------
// PTX helpers (base-target safe)
// ---------------------------------------------------------------------------
__device__ __forceinline__ uint32_t smem_u32(const void* p) {
    uint32_t a;
    asm("{ .reg .u64 t; cvta.to.shared.u64 t, %1; cvt.u32.u64 %0, t; }"
        : "=r"(a) : "l"(p));
    return a;
}
__device__ __forceinline__ void ldsm_x4(uint32_t addr, uint32_t &r0, uint32_t &r1,
                                        uint32_t &r2, uint32_t &r3) {
    asm volatile("ldmatrix.sync.aligned.m8n8.x4.shared.b16 {%0,%1,%2,%3}, [%4];"
                 : "=r"(r0), "=r"(r1), "=r"(r2), "=r"(r3) : "r"(addr));
}
__device__ __forceinline__ void ldsm_x4t(uint32_t addr, uint32_t &r0, uint32_t &r1,
                                         uint32_t &r2, uint32_t &r3) {
    asm volatile("ldmatrix.sync.aligned.m8n8.x4.trans.shared.b16 {%0,%1,%2,%3}, [%4];"
                 : "=r"(r0), "=r"(r1), "=r"(r2), "=r"(r3) : "r"(addr));
}
__device__ __forceinline__ void mma_f16(float* c, uint32_t a0, uint32_t a1,
                                        uint32_t a2, uint32_t a3,
                                        uint32_t b0, uint32_t b1) {
    asm volatile("mma.sync.aligned.m16n8k16.row.col.f32.f16.f16.f32 "
                 "{%0,%1,%2,%3}, {%4,%5,%6,%7}, {%8,%9}, {%0,%1,%2,%3};"
                 : "+f"(c[0]), "+f"(c[1]), "+f"(c[2]), "+f"(c[3])
                 : "r"(a0), "r"(a1), "r"(a2), "r"(a3), "r"(b0), "r"(b1));
}
__device__ __forceinline__ void cp_async16(uint32_t dst, const void* src) {
    asm volatile("cp.async.cg.shared.global [%0], [%1], 16;"
                 :: "r"(dst), "l"(src) : "memory");
}
#define CP_COMMIT() asm volatile("cp.async.commit_group;" ::: "memory")
#define CP_WAIT0()  asm volatile("cp.async.wait_group 0;" ::: "memory")
#define CP_WAIT1()  asm volatile("cp.async.wait_group 1;" ::: "memory")

__device__ __forceinline__ uint32_t pack_f16x2(float lo, float hi) {
    uint32_t d;
    asm("cvt.rn.f16x2.f32 %0, %1, %2;" : "=r"(d) : "f"(hi), "f"(lo));
    return d;
}

// ---------------------------------------------------------------------------
// Scratch
// ---------------------------------------------------------------------------
__device__ __half g_xh[(size_t)BB * TT * CC];
__device__ __half g_qkvh[(size_t)BB * TT * 3 * CC];
__device__ __half g_qkvl[(size_t)BB * TT * 3 * CC];   // only K,V region used
__device__ __half g_yh[(size_t)BB * TT * CC];
__device__ __half g_wah[(size_t)3 * CC * CC];          // W_attn^T [3C, C] fp16
__device__ __half g_wph[(size_t)CC * CC];              // W_proj^T [C, C]  fp16

// ---------------------------------------------------------------------------
// fp32 -> fp16 convert (hi only)
// ---------------------------------------------------------------------------
__global__ __launch_bounds__(256) void cvt_half(
    const float* __restrict__ in, __half* __restrict__ h, int n2)
{
    int i = blockIdx.x * 256 + threadIdx.x;
    if (i >= n2) return;
    float2 v = ((const float2*)in)[i];
    ((half2*)h)[i] = __floats2half2_rn(v.x, v.y);
}

// ---------------------------------------------------------------------------
// fp32 [K,N] -> fp16 transposed [N,K] (hi only)
// ---------------------------------------------------------------------------
__global__ __launch_bounds__(256) void cvt_t(
    const float* __restrict__ in, __half* __restrict__ h, int K, int N)
{
    __shared__ float ts[32][33];
    int tx = threadIdx.x, ty = threadIdx.y;   // (32, 8)
    int bx = blockIdx.x, by = blockIdx.y;
    #pragma unroll
    for (int j = 0; j < 4; j++) {
        int k = by * 32 + ty + j * 8;
        ts[ty + j * 8][tx] = in[(size_t)k * N + bx * 32 + tx];
    }
    __syncthreads();
    #pragma unroll
    for (int j = 0; j < 4; j++) {
        int nrow = bx * 32 + ty + j * 8;
        h[(size_t)nrow * K + by * 32 + tx] = __float2half(ts[tx][ty + j * 8]);
    }
}

// ---------------------------------------------------------------------------
// Tensor-core GEMM, fp16 1-combo: C = Ah @ Bh^T + bias
// CTA 128x128, 8 warps (64x32), k64 chunks, 3-stage cp.async, 2 CTAs/SM.
// Stage (32KB): A 16KB @0 | B 16KB @16384 (128B rows, SW128)
// ---------------------------------------------------------------------------
#define STG_BYTES 32768
#define GSMEM (3 * STG_BYTES + 1024)

template<bool SPLIT>
__global__ __launch_bounds__(256, 2) void gemm_mma(
    const __half* __restrict__ Ah, const __half* __restrict__ Bh,
    const float* __restrict__ bias, float* __restrict__ Cf,
    __half* __restrict__ Ch, __half* __restrict__ Cl,
    int Ncols, int K, int lo_min_col)
{
    extern __shared__ char dsm[];
    const uint32_t sb = (smem_u32(dsm) + 1023u) & ~1023u;

    const int tid = threadIdx.x;
    const int lid = tid & 31;
    const int wid = tid >> 5;
    const int wm = (wid >> 2) * 64;
    const int wn = (wid & 3) * 32;
    const int bm = blockIdx.y * 128;
    const int bn = blockIdx.x * 128;

    float c[4][4][4];
    #pragma unroll
    for (int mt = 0; mt < 4; mt++)
        #pragma unroll
        for (int nt = 0; nt < 4; nt++)
            #pragma unroll
            for (int e = 0; e < 4; e++) c[mt][nt][e] = 0.f;

    // one k64 chunk = 2048 x 16B: reg 0=A, 1=B; 8 cp.async/thread
    auto load_chunk = [&](int ch, int stg) {
        const int k0 = ch << 6;
        const uint32_t base = sb + (uint32_t)(stg * STG_BYTES);
        #pragma unroll
        for (int j = 0; j < 8; j++) {
            int idx = tid + j * 256;
            int reg = idx >> 10;
            int row = (idx >> 3) & 127;
            int c16 = idx & 7;
            uint32_t dst = base + (uint32_t)(reg << 14) + SW(row * 128 + c16 * 16);
            int kc = k0 + c16 * 8;
            const __half* src = (reg == 0)
                ? Ah + (size_t)(bm + row) * K + kc
                : Bh + (size_t)(bn + row) * K + kc;
            cp_async16(dst, src);
        }
    };

    auto compute = [&](int stg) {
        const uint32_t tb = sb + (uint32_t)(stg * STG_BYTES);
        #pragma unroll
        for (int ks = 0; ks < 4; ks++) {
            uint32_t ah[4][4];
            #pragma unroll
            for (int mt = 0; mt < 4; mt++) {
                int row = wm + mt * 16 + (lid & 15);
                ldsm_x4(tb + SW(row * 128 + ks * 32 + ((lid >> 4) << 4)),
                        ah[mt][0], ah[mt][1], ah[mt][2], ah[mt][3]);
            }
            #pragma unroll
            for (int ntp = 0; ntp < 2; ntp++) {
                int rowb = wn + ntp * 16 + ((lid >> 4) << 3) + (lid & 7);
                uint32_t offb = SW(rowb * 128 + ks * 32 + (((lid >> 3) & 1) << 4));
                uint32_t bh[4];
                ldsm_x4(tb + 16384 + offb, bh[0], bh[1], bh[2], bh[3]);
                #pragma unroll
                for (int half = 0; half < 2; half++) {
                    int nt = ntp * 2 + half;
                    #pragma unroll
                    for (int mt = 0; mt < 4; mt++)
                        mma_f16(c[mt][nt], ah[mt][0], ah[mt][1], ah[mt][2], ah[mt][3],
                                bh[half * 2], bh[half * 2 + 1]);
                }
            }
        }
    };

    const int nch = K >> 6;                 // 16 chunks for K=1024
    load_chunk(0, 0); CP_COMMIT();
    load_chunk(1, 1); CP_COMMIT();

    int stg = 0;
    for (int ch = 0; ch < nch; ch++) {
        if (ch + 2 < nch) CP_WAIT1(); else CP_WAIT0();
        __syncthreads();
        if (ch + 2 < nch) { load_chunk(ch + 2, (stg + 2) % 3); CP_COMMIT(); }
        compute(stg);
        stg = (stg + 1) % 3;
    }

    // Epilogue
    #pragma unroll
    for (int mt = 0; mt < 4; mt++) {
        #pragma unroll
        for (int nt = 0; nt < 4; nt++) {
            int m0 = bm + wm + mt * 16 + (lid >> 2);
            int n  = bn + wn + nt * 8 + ((lid & 3) << 1);
            float b0 = bias[n], b1 = bias[n + 1];
            float v00 = c[mt][nt][0] + b0, v01 = c[mt][nt][1] + b1;
            float v10 = c[mt][nt][2] + b0, v11 = c[mt][nt][3] + b1;
            if (SPLIT) {
                __half h00 = __float2half(v00), h01 = __float2half(v01);
                __half h10 = __float2half(v10), h11 = __float2half(v11);
                *(half2*)(Ch + (size_t)m0 * Ncols + n) = __halves2half2(h00, h01);
                *(half2*)(Ch + (size_t)(m0 + 8) * Ncols + n) = __halves2half2(h10, h11);
                if (n >= lo_min_col) {
                    *(half2*)(Cl + (size_t)m0 * Ncols + n) = __halves2half2(
                        __float2half(v00 - __half2float(h00)),
                        __float2half(v01 - __half2float(h01)));
                    *(half2*)(Cl + (size_t)(m0 + 8) * Ncols + n) = __halves2half2(
                        __float2half(v10 - __half2float(h10)),
                        __float2half(v11 - __half2float(h11)));
                }
            } else {
                float2 p0 = {v00, v01}, p1 = {v10, v11};
                *(float2*)(Cf + (size_t)m0 * Ncols + n) = p0;
                *(float2*)(Cf + (size_t)(m0 + 8) * Ncols + n) = p1;
            }
        }
    }
}

// ---------------------------------------------------------------------------
// Flash attention (causal), fp16: S = Qh (Kh+Kl)^T; O += Ph (Vh+Vl).
// Block = (b, h, q-tile 128). 8 warps, 2 CTAs/SM, double-buffered K/V.
// kv buffer (32KB): Kh 0 | Kl 8K | Vh 16K | Vl 24K.
// ---------------------------------------------------------------------------
#define ATT_SMEM (1024 + 2 * 32768)

__global__ __launch_bounds__(256, 2) void attn_mma(
    const __half* __restrict__ qkvh, const __half* __restrict__ qkvl,
    __half* __restrict__ yh)
{
    extern __shared__ char asm_[];
    const uint32_t sb = (smem_u32(asm_) + 1023u) & ~1023u;

    const int tid = threadIdx.x;
    const int lid = tid & 31;
    const int w = tid >> 5;
    const int qt = gridDim.x - 1 - blockIdx.x;    // longest first
    const int h = blockIdx.y;
    const int b = blockIdx.z;
    const size_t bT = (size_t)b * TT;
    const int RS = 3 * CC;

    // ---- stage Q hi (128 x 64 fp16 = 16KB) into buffer0, extract fragments
    {
        const __half* qg = qkvh + (bT + qt * 128) * RS + h * DH;
        #pragma unroll
        for (int j = 0; j < 4; j++) {
            int idx = tid + j * 256;              // 0..1023
            int row = idx >> 3, c16 = idx & 7;
            cp_async16(sb + SW(row * 128 + c16 * 16),
                       qg + (size_t)row * RS + c16 * 8);
        }
    }
    CP_COMMIT(); CP_WAIT0();
    __syncthreads();
    uint32_t qh[4][4];
    #pragma unroll
    for (int ks = 0; ks < 4; ks++) {
        int row = w * 16 + (lid & 15);
        ldsm_x4(sb + SW(row * 128 + ks * 32 + ((lid >> 4) << 4)),
                qh[ks][0], qh[ks][1], qh[ks][2], qh[ks][3]);
    }
    __syncthreads();

    auto load_kv = [&](int kt, int buf) {
        const __half* kh_g = qkvh + (bT + kt * 64) * RS + CC + h * DH;
        const __half* kl_g = qkvl + (bT + kt * 64) * RS + CC + h * DH;
        const __half* vh_g = kh_g + CC;
        const __half* vl_g = kl_g + CC;
        const uint32_t base = sb + (uint32_t)(buf * 32768);
        #pragma unroll
        for (int j = 0; j < 2; j++) {
            int idx = tid + j * 256;              // 0..511
            int row = idx >> 3, c16 = idx & 7;
            uint32_t sw = SW(row * 128 + c16 * 16);
            size_t g = (size_t)row * RS + c16 * 8;
            cp_async16(base + sw,         kh_g + g);
            cp_async16(base + 8192 + sw,  kl_g + g);
            cp_async16(base + 16384 + sw, vh_g + g);
            cp_async16(base + 24576 + sw, vl_g + g);
        }
    };

    float o[8][4];
    #pragma unroll
    for (int nt = 0; nt < 8; nt++)
        #pragma unroll
        for (int e = 0; e < 4; e++) o[nt][e] = 0.f;
    float m0 = -CUDART_INF_F, m1 = -CUDART_INF_F, l0 = 0.f, l1 = 0.f;
    const int gr0 = qt * 128 + w * 16;            // warp's first global q row
    const int r0 = (lid >> 2);
    const int cbase = (lid & 3) << 1;

    const int kt_max = 2 * qt + 1;
    load_kv(0, 0); CP_COMMIT();

    for (int kt = 0; kt <= kt_max; kt++) {
        const int buf = kt & 1;
        const uint32_t tb = sb + (uint32_t)(buf * 32768);
        CP_WAIT0();
        __syncthreads();
        if (kt < kt_max) { load_kv(kt + 1, buf ^ 1); CP_COMMIT(); }

        if (kt * 64 <= gr0 + 15) {                // tile not fully masked
            // S = Qh (Kh+Kl)^T
            float s[8][4];
            #pragma unroll
            for (int nt = 0; nt < 8; nt++)
                #pragma unroll
                for (int e = 0; e < 4; e++) s[nt][e] = 0.f;

            #pragma unroll
            for (int ks = 0; ks < 4; ks++) {
                #pragma unroll
                for (int ntp = 0; ntp < 4; ntp++) {
                    int rowb = ntp * 16 + ((lid >> 4) << 3) + (lid & 7);
                    uint32_t offb = SW(rowb * 128 + ks * 32 + (((lid >> 3) & 1) << 4));
                    uint32_t kh[4], kl[4];
                    ldsm_x4(tb + offb, kh[0], kh[1], kh[2], kh[3]);
                    ldsm_x4(tb + 8192 + offb, kl[0], kl[1], kl[2], kl[3]);
                    #pragma unroll
                    for (int half = 0; half < 2; half++) {
                        int nt = ntp * 2 + half;
                        mma_f16(s[nt], qh[ks][0], qh[ks][1], qh[ks][2], qh[ks][3],
                                kh[half * 2], kh[half * 2 + 1]);
                        mma_f16(s[nt], qh[ks][0], qh[ks][1], qh[ks][2], qh[ks][3],
                                kl[half * 2], kl[half * 2 + 1]);
                    }
                }
            }

            // scale + causal mask
            #pragma unroll
            for (int nt = 0; nt < 8; nt++)
                #pragma unroll
                for (int e = 0; e < 4; e++) s[nt][e] *= 0.125f;
            if (kt * 64 + 63 > gr0) {
                #pragma unroll
                for (int nt = 0; nt < 8; nt++) {
                    int gc = kt * 64 + nt * 8 + cbase;
                    int gr = gr0 + r0;
                    if (gc     > gr)     s[nt][0] = -CUDART_INF_F;
                    if (gc + 1 > gr)     s[nt][1] = -CUDART_INF_F;
                    if (gc     > gr + 8) s[nt][2] = -CUDART_INF_F;
                    if (gc + 1 > gr + 8) s[nt][3] = -CUDART_INF_F;
                }
            }

            // online softmax
            float mx0 = -CUDART_INF_F, mx1 = -CUDART_INF_F;
            #pragma unroll
            for (int nt = 0; nt < 8; nt++) {
                mx0 = fmaxf(mx0, fmaxf(s[nt][0], s[nt][1]));
                mx1 = fmaxf(mx1, fmaxf(s[nt][2], s[nt][3]));
            }
            mx0 = fmaxf(mx0, __shfl_xor_sync(0xffffffffu, mx0, 1));
            mx0 = fmaxf(mx0, __shfl_xor_sync(0xffffffffu, mx0, 2));
            mx1 = fmaxf(mx1, __shfl_xor_sync(0xffffffffu, mx1, 1));
            mx1 = fmaxf(mx1, __shfl_xor_sync(0xffffffffu, mx1, 2));
            float mn0 = fmaxf(m0, mx0), mn1 = fmaxf(m1, mx1);
            float a0 = __expf(m0 - mn0), a1 = __expf(m1 - mn1);
            float su0 = 0.f, su1 = 0.f;
            #pragma unroll
            for (int nt = 0; nt < 8; nt++) {
                s[nt][0] = __expf(s[nt][0] - mn0);
                s[nt][1] = __expf(s[nt][1] - mn0);
                s[nt][2] = __expf(s[nt][2] - mn1);
                s[nt][3] = __expf(s[nt][3] - mn1);
                su0 += s[nt][0] + s[nt][1];
                su1 += s[nt][2] + s[nt][3];
            }
            su0 += __shfl_xor_sync(0xffffffffu, su0, 1);
            su0 += __shfl_xor_sync(0xffffffffu, su0, 2);
            su1 += __shfl_xor_sync(0xffffffffu, su1, 1);
            su1 += __shfl_xor_sync(0xffffffffu, su1, 2);
            l0 = l0 * a0 + su0;  l1 = l1 * a1 + su1;
            m0 = mn0;  m1 = mn1;
            #pragma unroll
            for (int nt = 0; nt < 8; nt++) {
                o[nt][0] *= a0; o[nt][1] *= a0;
                o[nt][2] *= a1; o[nt][3] *= a1;
            }

            // PV: P hi only; V hi/lo via ldmatrix.x4.trans
            #pragma unroll
            for (int ks = 0; ks < 4; ks++) {
                const int t0 = ks * 2, t1 = ks * 2 + 1;
                uint32_t ph0 = pack_f16x2(s[t0][0], s[t0][1]);
                uint32_t ph1 = pack_f16x2(s[t0][2], s[t0][3]);
                uint32_t ph2 = pack_f16x2(s[t1][0], s[t1][1]);
                uint32_t ph3 = pack_f16x2(s[t1][2], s[t1][3]);
                int rowv = ks * 16 + (lid & 15);
                #pragma unroll
                for (int nt2 = 0; nt2 < 4; nt2++) {
                    uint32_t offv = SW(rowv * 128 + nt2 * 32 + ((lid >> 4) << 4));
                    uint32_t vh[4], vl[4];
                    ldsm_x4t(tb + 16384 + offv, vh[0], vh[1], vh[2], vh[3]);
                    ldsm_x4t(tb + 24576 + offv, vl[0], vl[1], vl[2], vl[3]);
                    mma_f16(o[nt2 * 2],     ph0, ph1, ph2, ph3, vh[0], vh[1]);
                    mma_f16(o[nt2 * 2],     ph0, ph1, ph2, ph3, vl[0], vl[1]);
                    mma_f16(o[nt2 * 2 + 1], ph0, ph1, ph2, ph3, vh[2], vh[3]);
                    mma_f16(o[nt2 * 2 + 1], ph0, ph1, ph2, ph3, vl[2], vl[3]);
                }
            }
        }
        __syncthreads();
    }

    // Epilogue: normalize, fp16 hi out
    float i0 = 1.f / l0, i1 = 1.f / l1;
    size_t row0 = (bT + (size_t)qt * 128 + w * 16 + r0) * CC + h * DH;
    size_t row1 = row0 + (size_t)8 * CC;
    #pragma unroll
    for (int nt = 0; nt < 8; nt++) {
        int n = nt * 8 + cbase;
        *(half2*)(yh + row0 + n) =
            __floats2half2_rn(o[nt][0] * i0, o[nt][1] * i0);
        *(half2*)(yh + row1 + n) =
            __floats2half2_rn(o[nt][2] * i1, o[nt][3] * i1);
    }
}

// ---------------------------------------------------------------------------
extern "C" void kernel_launch(void* const* d_in, const int* in_sizes, int n_in,
                              void* d_out, int out_size)
{
    const float* x      = (const float*)d_in[0];
    const float* W_attn = (const float*)d_in[1];
    const float* b_attn = (const float*)d_in[2];
    const float* W_proj = (const float*)d_in[3];
    const float* b_proj = (const float*)d_in[4];
    float* out = (float*)d_out;

    __half *xh, *qkvh, *qkvl, *yh, *wah, *wph;
    cudaGetSymbolAddress((void**)&xh, g_xh);
    cudaGetSymbolAddress((void**)&qkvh, g_qkvh);
    cudaGetSymbolAddress((void**)&qkvl, g_qkvl);
    cudaGetSymbolAddress((void**)&yh, g_yh);
    cudaGetSymbolAddress((void**)&wah, g_wah);
    cudaGetSymbolAddress((void**)&wph, g_wph);

    const int M = BB * TT;       // 4096
    const int N1 = 3 * CC;       // 3072
    const int N2 = CC;           // 1024
    const int K = CC;            // 1024

    cudaFuncSetAttribute(gemm_mma<true>,
                         cudaFuncAttributeMaxDynamicSharedMemorySize, GSMEM);
    cudaFuncSetAttribute(gemm_mma<false>,
                         cudaFuncAttributeMaxDynamicSharedMemorySize, GSMEM);
    cudaFuncSetAttribute(attn_mma,
                         cudaFuncAttributeMaxDynamicSharedMemorySize, ATT_SMEM);

    // Prep: x -> fp16; weights -> transposed fp16
    cvt_half<<<(M * K / 2 + 255) / 256, 256>>>(x, xh, M * K / 2);
    {
        dim3 grid(N1 / 32, K / 32), blk(32, 8);
        cvt_t<<<grid, blk>>>(W_attn, wah, K, N1);
    }
    {
        dim3 grid(N2 / 32, K / 32), blk(32, 8);
        cvt_t<<<grid, blk>>>(W_proj, wph, K, N2);
    }

    // 1) qkv = x @ W_attn + b_attn  (hi always; lo only for K,V columns)
    {
        dim3 grid(N1 / 128, M / 128);
        gemm_mma<true><<<grid, 256, GSMEM>>>(xh, wah, b_attn,
                                             nullptr, qkvh, qkvl, N1, K, CC);
    }

    // 2) Flash attention -> y (fp16 hi)
    {
        dim3 grid(TT / 128, HH, BB);
        attn_mma<<<grid, 256, ATT_SMEM>>>(qkvh, qkvl, yh);
    }

    // 3) out = y @ W_proj + b_proj (fp32)
    {
        dim3 grid(N2 / 128, M / 128);
        gemm_mma<false><<<grid, 256, GSMEM>>>(yh, wph, b_proj,
                                              out, nullptr, nullptr, N2, K, 0);
    }
}

// round 8
// speedup vs baseline: 6.7985x; 1.1495x over previous
#include <cuda_runtime.h>
#include <cuda_fp16.h>
#include <math_constants.h>
#include <cstdint>

// Problem constants
#define TT 2048
#define CC 1024
#define HH 16
#define DH 64
#define BB 2

#define SW(off) ((uint32_t)(off) ^ ((((uint32_t)(off)) >> 3) & 0x70u))

// ---------------------------------------------------------------------------
// PTX helpers (base-target safe)
// ---------------------------------------------------------------------------
__device__ __forceinline__ uint32_t smem_u32(const void* p) {
    uint32_t a;
    asm("{ .reg .u64 t; cvta.to.shared.u64 t, %1; cvt.u32.u64 %0, t; }"
        : "=r"(a) : "l"(p));
    return a;
}
__device__ __forceinline__ void ldsm_x4(uint32_t addr, uint32_t &r0, uint32_t &r1,
                                        uint32_t &r2, uint32_t &r3) {
    asm volatile("ldmatrix.sync.aligned.m8n8.x4.shared.b16 {%0,%1,%2,%3}, [%4];"
                 : "=r"(r0), "=r"(r1), "=r"(r2), "=r"(r3) : "r"(addr));
}
__device__ __forceinline__ void ldsm_x4t(uint32_t addr, uint32_t &r0, uint32_t &r1,
                                         uint32_t &r2, uint32_t &r3) {
    asm volatile("ldmatrix.sync.aligned.m8n8.x4.trans.shared.b16 {%0,%1,%2,%3}, [%4];"
                 : "=r"(r0), "=r"(r1), "=r"(r2), "=r"(r3) : "r"(addr));
}
__device__ __forceinline__ void mma_f16(float* c, uint32_t a0, uint32_t a1,
                                        uint32_t a2, uint32_t a3,
                                        uint32_t b0, uint32_t b1) {
    asm volatile("mma.sync.aligned.m16n8k16.row.col.f32.f16.f16.f32 "
                 "{%0,%1,%2,%3}, {%4,%5,%6,%7}, {%8,%9}, {%0,%1,%2,%3};"
                 : "+f"(c[0]), "+f"(c[1]), "+f"(c[2]), "+f"(c[3])
                 : "r"(a0), "r"(a1), "r"(a2), "r"(a3), "r"(b0), "r"(b1));
}
__device__ __forceinline__ void cp_async16(uint32_t dst, const void* src) {
    asm volatile("cp.async.cg.shared.global [%0], [%1], 16;"
                 :: "r"(dst), "l"(src) : "memory");
}
#define CP_COMMIT() asm volatile("cp.async.commit_group;" ::: "memory")
#define CP_WAIT0()  asm volatile("cp.async.wait_group 0;" ::: "memory")
#define CP_WAIT1()  asm volatile("cp.async.wait_group 1;" ::: "memory")

__device__ __forceinline__ uint32_t pack_f16x2(float lo, float hi) {
    uint32_t d;
    asm("cvt.rn.f16x2.f32 %0, %1, %2;" : "=r"(d) : "f"(hi), "f"(lo));
    return d;
}

// ---------------------------------------------------------------------------
// Scratch
// ---------------------------------------------------------------------------
__device__ __half g_xh[(size_t)BB * TT * CC];
__device__ __half g_qkvh[(size_t)BB * TT * 3 * CC];
__device__ __half g_qkvl[(size_t)BB * TT * 3 * CC];   // only K region used
__device__ __half g_yh[(size_t)BB * TT * CC];
__device__ __half g_wah[(size_t)3 * CC * CC];          // W_attn^T [3C, C] fp16
__device__ __half g_wph[(size_t)CC * CC];              // W_proj^T [C, C]  fp16

// ---------------------------------------------------------------------------
// fp32 -> fp16 convert (hi only)
// ---------------------------------------------------------------------------
__global__ __launch_bounds__(256) void cvt_half(
    const float* __restrict__ in, __half* __restrict__ h, int n2)
{
    int i = blockIdx.x * 256 + threadIdx.x;
    if (i >= n2) return;
    float2 v = ((const float2*)in)[i];
    ((half2*)h)[i] = __floats2half2_rn(v.x, v.y);
}

// ---------------------------------------------------------------------------
// fp32 [K,N] -> fp16 transposed [N,K] (hi only)
// ---------------------------------------------------------------------------
__global__ __launch_bounds__(256) void cvt_t(
    const float* __restrict__ in, __half* __restrict__ h, int K, int N)
{
    __shared__ float ts[32][33];
    int tx = threadIdx.x, ty = threadIdx.y;   // (32, 8)
    int bx = blockIdx.x, by = blockIdx.y;
    #pragma unroll
    for (int j = 0; j < 4; j++) {
        int k = by * 32 + ty + j * 8;
        ts[ty + j * 8][tx] = in[(size_t)k * N + bx * 32 + tx];
    }
    __syncthreads();
    #pragma unroll
    for (int j = 0; j < 4; j++) {
        int nrow = bx * 32 + ty + j * 8;
        h[(size_t)nrow * K + by * 32 + tx] = __float2half(ts[tx][ty + j * 8]);
    }
}

// ---------------------------------------------------------------------------
// Tensor-core GEMM, fp16 1-combo: C = Ah @ Bh^T + bias
// CTA 128x128, 8 warps (64x32), k64 chunks, 3-stage cp.async, 2 CTAs/SM.
// Stage (32KB): A 16KB @0 | B 16KB @16384 (128B rows, SW128)
// lo residual written only for columns in [lo_min_col, lo_max_col).
// ---------------------------------------------------------------------------
#define STG_BYTES 32768
#define GSMEM (3 * STG_BYTES + 1024)

template<bool SPLIT>
__global__ __launch_bounds__(256, 2) void gemm_mma(
    const __half* __restrict__ Ah, const __half* __restrict__ Bh,
    const float* __restrict__ bias, float* __restrict__ Cf,
    __half* __restrict__ Ch, __half* __restrict__ Cl,
    int Ncols, int K, int lo_min_col, int lo_max_col)
{
    extern __shared__ char dsm[];
    const uint32_t sb = (smem_u32(dsm) + 1023u) & ~1023u;

    const int tid = threadIdx.x;
    const int lid = tid & 31;
    const int wid = tid >> 5;
    const int wm = (wid >> 2) * 64;
    const int wn = (wid & 3) * 32;
    const int bm = blockIdx.y * 128;
    const int bn = blockIdx.x * 128;

    float c[4][4][4];
    #pragma unroll
    for (int mt = 0; mt < 4; mt++)
        #pragma unroll
        for (int nt = 0; nt < 4; nt++)
            #pragma unroll
            for (int e = 0; e < 4; e++) c[mt][nt][e] = 0.f;

    auto load_chunk = [&](int ch, int stg) {
        const int k0 = ch << 6;
        const uint32_t base = sb + (uint32_t)(stg * STG_BYTES);
        #pragma unroll
        for (int j = 0; j < 8; j++) {
            int idx = tid + j * 256;
            int reg = idx >> 10;
            int row = (idx >> 3) & 127;
            int c16 = idx & 7;
            uint32_t dst = base + (uint32_t)(reg << 14) + SW(row * 128 + c16 * 16);
            int kc = k0 + c16 * 8;
            const __half* src = (reg == 0)
                ? Ah + (size_t)(bm + row) * K + kc
                : Bh + (size_t)(bn + row) * K + kc;
            cp_async16(dst, src);
        }
    };

    auto compute = [&](int stg) {
        const uint32_t tb = sb + (uint32_t)(stg * STG_BYTES);
        #pragma unroll
        for (int ks = 0; ks < 4; ks++) {
            uint32_t ah[4][4];
            #pragma unroll
            for (int mt = 0; mt < 4; mt++) {
                int row = wm + mt * 16 + (lid & 15);
                ldsm_x4(tb + SW(row * 128 + ks * 32 + ((lid >> 4) << 4)),
                        ah[mt][0], ah[mt][1], ah[mt][2], ah[mt][3]);
            }
            #pragma unroll
            for (int ntp = 0; ntp < 2; ntp++) {
                int rowb = wn + ntp * 16 + ((lid >> 4) << 3) + (lid & 7);
                uint32_t offb = SW(rowb * 128 + ks * 32 + (((lid >> 3) & 1) << 4));
                uint32_t bh[4];
                ldsm_x4(tb + 16384 + offb, bh[0], bh[1], bh[2], bh[3]);
                #pragma unroll
                for (int half = 0; half < 2; half++) {
                    int nt = ntp * 2 + half;
                    #pragma unroll
                    for (int mt = 0; mt < 4; mt++)
                        mma_f16(c[mt][nt], ah[mt][0], ah[mt][1], ah[mt][2], ah[mt][3],
                                bh[half * 2], bh[half * 2 + 1]);
                }
            }
        }
    };

    const int nch = K >> 6;                 // 16 chunks for K=1024
    load_chunk(0, 0); CP_COMMIT();
    load_chunk(1, 1); CP_COMMIT();

    int stg = 0;
    for (int ch = 0; ch < nch; ch++) {
        if (ch + 2 < nch) CP_WAIT1(); else CP_WAIT0();
        __syncthreads();
        if (ch + 2 < nch) { load_chunk(ch + 2, (stg + 2) % 3); CP_COMMIT(); }
        compute(stg);
        stg = (stg + 1) % 3;
    }

    // Epilogue
    #pragma unroll
    for (int mt = 0; mt < 4; mt++) {
        #pragma unroll
        for (int nt = 0; nt < 4; nt++) {
            int m0 = bm + wm + mt * 16 + (lid >> 2);
            int n  = bn + wn + nt * 8 + ((lid & 3) << 1);
            float b0 = bias[n], b1 = bias[n + 1];
            float v00 = c[mt][nt][0] + b0, v01 = c[mt][nt][1] + b1;
            float v10 = c[mt][nt][2] + b0, v11 = c[mt][nt][3] + b1;
            if (SPLIT) {
                __half h00 = __float2half(v00), h01 = __float2half(v01);
                __half h10 = __float2half(v10), h11 = __float2half(v11);
                *(half2*)(Ch + (size_t)m0 * Ncols + n) = __halves2half2(h00, h01);
                *(half2*)(Ch + (size_t)(m0 + 8) * Ncols + n) = __halves2half2(h10, h11);
                if (n >= lo_min_col && n < lo_max_col) {
                    *(half2*)(Cl + (size_t)m0 * Ncols + n) = __halves2half2(
                        __float2half(v00 - __half2float(h00)),
                        __float2half(v01 - __half2float(h01)));
                    *(half2*)(Cl + (size_t)(m0 + 8) * Ncols + n) = __halves2half2(
                        __float2half(v10 - __half2float(h10)),
                        __float2half(v11 - __half2float(h11)));
                }
            } else {
                float2 p0 = {v00, v01}, p1 = {v10, v11};
                *(float2*)(Cf + (size_t)m0 * Ncols + n) = p0;
                *(float2*)(Cf + (size_t)(m0 + 8) * Ncols + n) = p1;
            }
        }
    }
}

// ---------------------------------------------------------------------------
// Flash attention (causal), fp16: S = Qh (Kh+Kl)^T; O += Ph Vh.
// Block = (b, h, q-tile 128). 8 warps, 2 CTAs/SM, double-buffered K/V.
// kv buffer (24KB): Kh 0 | Kl 8K | Vh 16K.
// ---------------------------------------------------------------------------
#define KVBUF 24576
#define ATT_SMEM (1024 + 2 * KVBUF)

__global__ __launch_bounds__(256, 2) void attn_mma(
    const __half* __restrict__ qkvh, const __half* __restrict__ qkvl,
    __half* __restrict__ yh)
{
    extern __shared__ char asm_[];
    const uint32_t sb = (smem_u32(asm_) + 1023u) & ~1023u;

    const int tid = threadIdx.x;
    const int lid = tid & 31;
    const int w = tid >> 5;
    const int qt = gridDim.x - 1 - blockIdx.x;    // longest first
    const int h = blockIdx.y;
    const int b = blockIdx.z;
    const size_t bT = (size_t)b * TT;
    const int RS = 3 * CC;

    // ---- stage Q hi (128 x 64 fp16 = 16KB) into buffer0, extract fragments
    {
        const __half* qg = qkvh + (bT + qt * 128) * RS + h * DH;
        #pragma unroll
        for (int j = 0; j < 4; j++) {
            int idx = tid + j * 256;              // 0..1023
            int row = idx >> 3, c16 = idx & 7;
            cp_async16(sb + SW(row * 128 + c16 * 16),
                       qg + (size_t)row * RS + c16 * 8);
        }
    }
    CP_COMMIT(); CP_WAIT0();
    __syncthreads();
    uint32_t qh[4][4];
    #pragma unroll
    for (int ks = 0; ks < 4; ks++) {
        int row = w * 16 + (lid & 15);
        ldsm_x4(sb + SW(row * 128 + ks * 32 + ((lid >> 4) << 4)),
                qh[ks][0], qh[ks][1], qh[ks][2], qh[ks][3]);
    }
    __syncthreads();

    auto load_kv = [&](int kt, int buf) {
        const __half* kh_g = qkvh + (bT + kt * 64) * RS + CC + h * DH;
        const __half* kl_g = qkvl + (bT + kt * 64) * RS + CC + h * DH;
        const __half* vh_g = kh_g + CC;
        const uint32_t base = sb + (uint32_t)(buf * KVBUF);
        #pragma unroll
        for (int j = 0; j < 2; j++) {
            int idx = tid + j * 256;              // 0..511
            int row = idx >> 3, c16 = idx & 7;
            uint32_t sw = SW(row * 128 + c16 * 16);
            size_t g = (size_t)row * RS + c16 * 8;
            cp_async16(base + sw,         kh_g + g);
            cp_async16(base + 8192 + sw,  kl_g + g);
            cp_async16(base + 16384 + sw, vh_g + g);
        }
    };

    float o[8][4];
    #pragma unroll
    for (int nt = 0; nt < 8; nt++)
        #pragma unroll
        for (int e = 0; e < 4; e++) o[nt][e] = 0.f;
    float m0 = -CUDART_INF_F, m1 = -CUDART_INF_F, l0 = 0.f, l1 = 0.f;
    const int gr0 = qt * 128 + w * 16;            // warp's first global q row
    const int r0 = (lid >> 2);
    const int cbase = (lid & 3) << 1;

    const int kt_max = 2 * qt + 1;
    load_kv(0, 0); CP_COMMIT();

    for (int kt = 0; kt <= kt_max; kt++) {
        const int buf = kt & 1;
        const uint32_t tb = sb + (uint32_t)(buf * KVBUF);
        CP_WAIT0();
        __syncthreads();
        if (kt < kt_max) { load_kv(kt + 1, buf ^ 1); CP_COMMIT(); }

        if (kt * 64 <= gr0 + 15) {                // tile not fully masked
            // S = Qh (Kh+Kl)^T
            float s[8][4];
            #pragma unroll
            for (int nt = 0; nt < 8; nt++)
                #pragma unroll
                for (int e = 0; e < 4; e++) s[nt][e] = 0.f;

            #pragma unroll
            for (int ks = 0; ks < 4; ks++) {
                #pragma unroll
                for (int ntp = 0; ntp < 4; ntp++) {
                    int rowb = ntp * 16 + ((lid >> 4) << 3) + (lid & 7);
                    uint32_t offb = SW(rowb * 128 + ks * 32 + (((lid >> 3) & 1) << 4));
                    uint32_t kh[4], kl[4];
                    ldsm_x4(tb + offb, kh[0], kh[1], kh[2], kh[3]);
                    ldsm_x4(tb + 8192 + offb, kl[0], kl[1], kl[2], kl[3]);
                    #pragma unroll
                    for (int half = 0; half < 2; half++) {
                        int nt = ntp * 2 + half;
                        mma_f16(s[nt], qh[ks][0], qh[ks][1], qh[ks][2], qh[ks][3],
                                kh[half * 2], kh[half * 2 + 1]);
                        mma_f16(s[nt], qh[ks][0], qh[ks][1], qh[ks][2], qh[ks][3],
                                kl[half * 2], kl[half * 2 + 1]);
                    }
                }
            }

            // scale + causal mask
            #pragma unroll
            for (int nt = 0; nt < 8; nt++)
                #pragma unroll
                for (int e = 0; e < 4; e++) s[nt][e] *= 0.125f;
            if (kt * 64 + 63 > gr0) {
                #pragma unroll
                for (int nt = 0; nt < 8; nt++) {
                    int gc = kt * 64 + nt * 8 + cbase;
                    int gr = gr0 + r0;
                    if (gc     > gr)     s[nt][0] = -CUDART_INF_F;
                    if (gc + 1 > gr)     s[nt][1] = -CUDART_INF_F;
                    if (gc     > gr + 8) s[nt][2] = -CUDART_INF_F;
                    if (gc + 1 > gr + 8) s[nt][3] = -CUDART_INF_F;
                }
            }

            // online softmax
            float mx0 = -CUDART_INF_F, mx1 = -CUDART_INF_F;
            #pragma unroll
            for (int nt = 0; nt < 8; nt++) {
                mx0 = fmaxf(mx0, fmaxf(s[nt][0], s[nt][1]));
                mx1 = fmaxf(mx1, fmaxf(s[nt][2], s[nt][3]));
            }
            mx0 = fmaxf(mx0, __shfl_xor_sync(0xffffffffu, mx0, 1));
            mx0 = fmaxf(mx0, __shfl_xor_sync(0xffffffffu, mx0, 2));
            mx1 = fmaxf(mx1, __shfl_xor_sync(0xffffffffu, mx1, 1));
            mx1 = fmaxf(mx1, __shfl_xor_sync(0xffffffffu, mx1, 2));
            float mn0 = fmaxf(m0, mx0), mn1 = fmaxf(m1, mx1);
            float a0 = __expf(m0 - mn0), a1 = __expf(m1 - mn1);
            float su0 = 0.f, su1 = 0.f;
            #pragma unroll
            for (int nt = 0; nt < 8; nt++) {
                s[nt][0] = __expf(s[nt][0] - mn0);
                s[nt][1] = __expf(s[nt][1] - mn0);
                s[nt][2] = __expf(s[nt][2] - mn1);
                s[nt][3] = __expf(s[nt][3] - mn1);
                su0 += s[nt][0] + s[nt][1];
                su1 += s[nt][2] + s[nt][3];
            }
            su0 += __shfl_xor_sync(0xffffffffu, su0, 1);
            su0 += __shfl_xor_sync(0xffffffffu, su0, 2);
            su1 += __shfl_xor_sync(0xffffffffu, su1, 1);
            su1 += __shfl_xor_sync(0xffffffffu, su1, 2);
            l0 = l0 * a0 + su0;  l1 = l1 * a1 + su1;
            m0 = mn0;  m1 = mn1;
            #pragma unroll
            for (int nt = 0; nt < 8; nt++) {
                o[nt][0] *= a0; o[nt][1] *= a0;
                o[nt][2] *= a1; o[nt][3] *= a1;
            }

            // PV: P hi only; V hi via ldmatrix.x4.trans (1-combo)
            #pragma unroll
            for (int ks = 0; ks < 4; ks++) {
                const int t0 = ks * 2, t1 = ks * 2 + 1;
                uint32_t ph0 = pack_f16x2(s[t0][0], s[t0][1]);
                uint32_t ph1 = pack_f16x2(s[t0][2], s[t0][3]);
                uint32_t ph2 = pack_f16x2(s[t1][0], s[t1][1]);
                uint32_t ph3 = pack_f16x2(s[t1][2], s[t1][3]);
                int rowv = ks * 16 + (lid & 15);
                #pragma unroll
                for (int nt2 = 0; nt2 < 4; nt2++) {
                    uint32_t offv = SW(rowv * 128 + nt2 * 32 + ((lid >> 4) << 4));
                    uint32_t vh[4];
                    ldsm_x4t(tb + 16384 + offv, vh[0], vh[1], vh[2], vh[3]);
                    mma_f16(o[nt2 * 2],     ph0, ph1, ph2, ph3, vh[0], vh[1]);
                    mma_f16(o[nt2 * 2 + 1], ph0, ph1, ph2, ph3, vh[2], vh[3]);
                }
            }
        }
        __syncthreads();
    }

    // Epilogue: normalize, fp16 hi out
    float i0 = 1.f / l0, i1 = 1.f / l1;
    size_t row0 = (bT + (size_t)qt * 128 + w * 16 + r0) * CC + h * DH;
    size_t row1 = row0 + (size_t)8 * CC;
    #pragma unroll
    for (int nt = 0; nt < 8; nt++) {
        int n = nt * 8 + cbase;
        *(half2*)(yh + row0 + n) =
            __floats2half2_rn(o[nt][0] * i0, o[nt][1] * i0);
        *(half2*)(yh + row1 + n) =
            __floats2half2_rn(o[nt][2] * i1, o[nt][3] * i1);
    }
}

// ---------------------------------------------------------------------------
extern "C" void kernel_launch(void* const* d_in, const int* in_sizes, int n_in,
                              void* d_out, int out_size)
{
    const float* x      = (const float*)d_in[0];
    const float* W_attn = (const float*)d_in[1];
    const float* b_attn = (const float*)d_in[2];
    const float* W_proj = (const float*)d_in[3];
    const float* b_proj = (const float*)d_in[4];
    float* out = (float*)d_out;

    __half *xh, *qkvh, *qkvl, *yh, *wah, *wph;
    cudaGetSymbolAddress((void**)&xh, g_xh);
    cudaGetSymbolAddress((void**)&qkvh, g_qkvh);
    cudaGetSymbolAddress((void**)&qkvl, g_qkvl);
    cudaGetSymbolAddress((void**)&yh, g_yh);
    cudaGetSymbolAddress((void**)&wah, g_wah);
    cudaGetSymbolAddress((void**)&wph, g_wph);

    const int M = BB * TT;       // 4096
    const int N1 = 3 * CC;       // 3072
    const int N2 = CC;           // 1024
    const int K = CC;            // 1024

    cudaFuncSetAttribute(gemm_mma<true>,
                         cudaFuncAttributeMaxDynamicSharedMemorySize, GSMEM);
    cudaFuncSetAttribute(gemm_mma<false>,
                         cudaFuncAttributeMaxDynamicSharedMemorySize, GSMEM);
    cudaFuncSetAttribute(attn_mma,
                         cudaFuncAttributeMaxDynamicSharedMemorySize, ATT_SMEM);

    // Prep: x -> fp16; weights -> transposed fp16
    cvt_half<<<(M * K / 2 + 255) / 256, 256>>>(x, xh, M * K / 2);
    {
        dim3 grid(N1 / 32, K / 32), blk(32, 8);
        cvt_t<<<grid, blk>>>(W_attn, wah, K, N1);
    }
    {
        dim3 grid(N2 / 32, K / 32), blk(32, 8);
        cvt_t<<<grid, blk>>>(W_proj, wph, K, N2);
    }

    // 1) qkv = x @ W_attn + b_attn  (hi always; lo only for K columns)
    {
        dim3 grid(N1 / 128, M / 128);
        gemm_mma<true><<<grid, 256, GSMEM>>>(xh, wah, b_attn,
                                             nullptr, qkvh, qkvl, N1, K,
                                             CC, 2 * CC);
    }

    // 2) Flash attention -> y (fp16 hi)
    {
        dim3 grid(TT / 128, HH, BB);
        attn_mma<<<grid, 256, ATT_SMEM>>>(qkvh, qkvl, yh);
    }

    // 3) out = y @ W_proj + b_proj (fp32)
    {
        dim3 grid(N2 / 128, M / 128);
        gemm_mma<false><<<grid, 256, GSMEM>>>(yh, wph, b_proj,
                                              out, nullptr, nullptr, N2, K,
                                              0, 0);
    }
}

// round 9
// speedup vs baseline: 7.6484x; 1.1250x over previous
#include <cuda_runtime.h>
#include <cuda_fp16.h>
#include <math_constants.h>
#include <cstdint>

// Problem constants
#define TT 2048
#define CC 1024
#define HH 16
#define DH 64
#define BB 2

#define SW(off) ((uint32_t)(off) ^ ((((uint32_t)(off)) >> 3) & 0x70u))

// ---------------------------------------------------------------------------
// PTX helpers (base-target safe)
// ---------------------------------------------------------------------------
__device__ __forceinline__ uint32_t smem_u32(const void* p) {
    uint32_t a;
    asm("{ .reg .u64 t; cvta.to.shared.u64 t, %1; cvt.u32.u64 %0, t; }"
        : "=r"(a) : "l"(p));
    return a;
}
__device__ __forceinline__ void ldsm_x4(uint32_t addr, uint32_t &r0, uint32_t &r1,
                                        uint32_t &r2, uint32_t &r3) {
    asm volatile("ldmatrix.sync.aligned.m8n8.x4.shared.b16 {%0,%1,%2,%3}, [%4];"
                 : "=r"(r0), "=r"(r1), "=r"(r2), "=r"(r3) : "r"(addr));
}
__device__ __forceinline__ void ldsm_x4t(uint32_t addr, uint32_t &r0, uint32_t &r1,
                                         uint32_t &r2, uint32_t &r3) {
    asm volatile("ldmatrix.sync.aligned.m8n8.x4.trans.shared.b16 {%0,%1,%2,%3}, [%4];"
                 : "=r"(r0), "=r"(r1), "=r"(r2), "=r"(r3) : "r"(addr));
}
__device__ __forceinline__ void mma_f16(float* c, uint32_t a0, uint32_t a1,
                                        uint32_t a2, uint32_t a3,
                                        uint32_t b0, uint32_t b1) {
    asm volatile("mma.sync.aligned.m16n8k16.row.col.f32.f16.f16.f32 "
                 "{%0,%1,%2,%3}, {%4,%5,%6,%7}, {%8,%9}, {%0,%1,%2,%3};"
                 : "+f"(c[0]), "+f"(c[1]), "+f"(c[2]), "+f"(c[3])
                 : "r"(a0), "r"(a1), "r"(a2), "r"(a3), "r"(b0), "r"(b1));
}
__device__ __forceinline__ void cp_async16(uint32_t dst, const void* src) {
    asm volatile("cp.async.cg.shared.global [%0], [%1], 16;"
                 :: "r"(dst), "l"(src) : "memory");
}
#define CP_COMMIT() asm volatile("cp.async.commit_group;" ::: "memory")
#define CP_WAIT0()  asm volatile("cp.async.wait_group 0;" ::: "memory")
#define CP_WAIT1()  asm volatile("cp.async.wait_group 1;" ::: "memory")

__device__ __forceinline__ uint32_t pack_f16x2(float lo, float hi) {
    uint32_t d;
    asm("cvt.rn.f16x2.f32 %0, %1, %2;" : "=r"(d) : "f"(hi), "f"(lo));
    return d;
}

// ---------------------------------------------------------------------------
// Scratch
// ---------------------------------------------------------------------------
__device__ __half g_xh[(size_t)BB * TT * CC];
__device__ __half g_qkvh[(size_t)BB * TT * 3 * CC];
__device__ __half g_yh[(size_t)BB * TT * CC];
__device__ __half g_wah[(size_t)3 * CC * CC];          // W_attn^T [3C, C] fp16
__device__ __half g_wph[(size_t)CC * CC];              // W_proj^T [C, C]  fp16

// ---------------------------------------------------------------------------
// fp32 -> fp16 convert (hi only)
// ---------------------------------------------------------------------------
__global__ __launch_bounds__(256) void cvt_half(
    const float* __restrict__ in, __half* __restrict__ h, int n2)
{
    int i = blockIdx.x * 256 + threadIdx.x;
    if (i >= n2) return;
    float2 v = ((const float2*)in)[i];
    ((half2*)h)[i] = __floats2half2_rn(v.x, v.y);
}

// ---------------------------------------------------------------------------
// fp32 [K,N] -> fp16 transposed [N,K]
// ---------------------------------------------------------------------------
__global__ __launch_bounds__(256) void cvt_t(
    const float* __restrict__ in, __half* __restrict__ h, int K, int N)
{
    __shared__ float ts[32][33];
    int tx = threadIdx.x, ty = threadIdx.y;   // (32, 8)
    int bx = blockIdx.x, by = blockIdx.y;
    #pragma unroll
    for (int j = 0; j < 4; j++) {
        int k = by * 32 + ty + j * 8;
        ts[ty + j * 8][tx] = in[(size_t)k * N + bx * 32 + tx];
    }
    __syncthreads();
    #pragma unroll
    for (int j = 0; j < 4; j++) {
        int nrow = bx * 32 + ty + j * 8;
        h[(size_t)nrow * K + by * 32 + tx] = __float2half(ts[tx][ty + j * 8]);
    }
}

// ---------------------------------------------------------------------------
// Tensor-core GEMM, fp16 1-combo: C = Ah @ Bh^T + bias
// CTA 128x128, 8 warps (64x32), k64 chunks, 3-stage cp.async, 2 CTAs/SM.
// HALF_OUT: write fp16; else fp32.
// ---------------------------------------------------------------------------
#define STG_BYTES 32768
#define GSMEM (3 * STG_BYTES + 1024)

template<bool HALF_OUT>
__global__ __launch_bounds__(256, 2) void gemm_mma(
    const __half* __restrict__ Ah, const __half* __restrict__ Bh,
    const float* __restrict__ bias, float* __restrict__ Cf,
    __half* __restrict__ Ch, int Ncols, int K)
{
    extern __shared__ char dsm[];
    const uint32_t sb = (smem_u32(dsm) + 1023u) & ~1023u;

    const int tid = threadIdx.x;
    const int lid = tid & 31;
    const int wid = tid >> 5;
    const int wm = (wid >> 2) * 64;
    const int wn = (wid & 3) * 32;
    const int bm = blockIdx.y * 128;
    const int bn = blockIdx.x * 128;

    float c[4][4][4];
    #pragma unroll
    for (int mt = 0; mt < 4; mt++)
        #pragma unroll
        for (int nt = 0; nt < 4; nt++)
            #pragma unroll
            for (int e = 0; e < 4; e++) c[mt][nt][e] = 0.f;

    auto load_chunk = [&](int ch, int stg) {
        const int k0 = ch << 6;
        const uint32_t base = sb + (uint32_t)(stg * STG_BYTES);
        #pragma unroll
        for (int j = 0; j < 8; j++) {
            int idx = tid + j * 256;
            int reg = idx >> 10;
            int row = (idx >> 3) & 127;
            int c16 = idx & 7;
            uint32_t dst = base + (uint32_t)(reg << 14) + SW(row * 128 + c16 * 16);
            int kc = k0 + c16 * 8;
            const __half* src = (reg == 0)
                ? Ah + (size_t)(bm + row) * K + kc
                : Bh + (size_t)(bn + row) * K + kc;
            cp_async16(dst, src);
        }
    };

    auto compute = [&](int stg) {
        const uint32_t tb = sb + (uint32_t)(stg * STG_BYTES);
        #pragma unroll
        for (int ks = 0; ks < 4; ks++) {
            uint32_t ah[4][4];
            #pragma unroll
            for (int mt = 0; mt < 4; mt++) {
                int row = wm + mt * 16 + (lid & 15);
                ldsm_x4(tb + SW(row * 128 + ks * 32 + ((lid >> 4) << 4)),
                        ah[mt][0], ah[mt][1], ah[mt][2], ah[mt][3]);
            }
            #pragma unroll
            for (int ntp = 0; ntp < 2; ntp++) {
                int rowb = wn + ntp * 16 + ((lid >> 4) << 3) + (lid & 7);
                uint32_t offb = SW(rowb * 128 + ks * 32 + (((lid >> 3) & 1) << 4));
                uint32_t bh[4];
                ldsm_x4(tb + 16384 + offb, bh[0], bh[1], bh[2], bh[3]);
                #pragma unroll
                for (int half = 0; half < 2; half++) {
                    int nt = ntp * 2 + half;
                    #pragma unroll
                    for (int mt = 0; mt < 4; mt++)
                        mma_f16(c[mt][nt], ah[mt][0], ah[mt][1], ah[mt][2], ah[mt][3],
                                bh[half * 2], bh[half * 2 + 1]);
                }
            }
        }
    };

    const int nch = K >> 6;                 // 16 chunks for K=1024
    load_chunk(0, 0); CP_COMMIT();
    load_chunk(1, 1); CP_COMMIT();

    int stg = 0;
    for (int ch = 0; ch < nch; ch++) {
        if (ch + 2 < nch) CP_WAIT1(); else CP_WAIT0();
        __syncthreads();
        if (ch + 2 < nch) { load_chunk(ch + 2, (stg + 2) % 3); CP_COMMIT(); }
        compute(stg);
        stg = (stg + 1) % 3;
    }

    // Epilogue
    #pragma unroll
    for (int mt = 0; mt < 4; mt++) {
        #pragma unroll
        for (int nt = 0; nt < 4; nt++) {
            int m0 = bm + wm + mt * 16 + (lid >> 2);
            int n  = bn + wn + nt * 8 + ((lid & 3) << 1);
            float b0 = bias[n], b1 = bias[n + 1];
            float v00 = c[mt][nt][0] + b0, v01 = c[mt][nt][1] + b1;
            float v10 = c[mt][nt][2] + b0, v11 = c[mt][nt][3] + b1;
            if (HALF_OUT) {
                *(half2*)(Ch + (size_t)m0 * Ncols + n) =
                    __floats2half2_rn(v00, v01);
                *(half2*)(Ch + (size_t)(m0 + 8) * Ncols + n) =
                    __floats2half2_rn(v10, v11);
            } else {
                float2 p0 = {v00, v01}, p1 = {v10, v11};
                *(float2*)(Cf + (size_t)m0 * Ncols + n) = p0;
                *(float2*)(Cf + (size_t)(m0 + 8) * Ncols + n) = p1;
            }
        }
    }
}

// ---------------------------------------------------------------------------
// Flash attention (causal), fp16 1-combo: S = Qh Kh^T; O += Ph Vh.
// Block = (b, h, q-tile 128). 8 warps, 2 CTAs/SM, double-buffered K/V.
// kv buffer (16KB): Kh 0 | Vh 8K. Softmax in log2 domain (exp2f).
// ---------------------------------------------------------------------------
#define KVBUF 16384
#define ATT_SMEM (1024 + 2 * KVBUF)

__global__ __launch_bounds__(256, 2) void attn_mma(
    const __half* __restrict__ qkvh, __half* __restrict__ yh)
{
    extern __shared__ char asm_[];
    const uint32_t sb = (smem_u32(asm_) + 1023u) & ~1023u;

    const int tid = threadIdx.x;
    const int lid = tid & 31;
    const int w = tid >> 5;
    const int qt = gridDim.x - 1 - blockIdx.x;    // longest first
    const int h = blockIdx.y;
    const int b = blockIdx.z;
    const size_t bT = (size_t)b * TT;
    const int RS = 3 * CC;
    const float SCL = 0.18033688f;                // 0.125 * log2(e)

    // ---- stage Q hi (128 x 64 fp16 = 16KB) into buffer0, extract fragments
    {
        const __half* qg = qkvh + (bT + qt * 128) * RS + h * DH;
        #pragma unroll
        for (int j = 0; j < 4; j++) {
            int idx = tid + j * 256;              // 0..1023
            int row = idx >> 3, c16 = idx & 7;
            cp_async16(sb + SW(row * 128 + c16 * 16),
                       qg + (size_t)row * RS + c16 * 8);
        }
    }
    CP_COMMIT(); CP_WAIT0();
    __syncthreads();
    uint32_t qh[4][4];
    #pragma unroll
    for (int ks = 0; ks < 4; ks++) {
        int row = w * 16 + (lid & 15);
        ldsm_x4(sb + SW(row * 128 + ks * 32 + ((lid >> 4) << 4)),
                qh[ks][0], qh[ks][1], qh[ks][2], qh[ks][3]);
    }
    __syncthreads();

    auto load_kv = [&](int kt, int buf) {
        const __half* kh_g = qkvh + (bT + kt * 64) * RS + CC + h * DH;
        const __half* vh_g = kh_g + CC;
        const uint32_t base = sb + (uint32_t)(buf * KVBUF);
        #pragma unroll
        for (int j = 0; j < 2; j++) {
            int idx = tid + j * 256;              // 0..511
            int row = idx >> 3, c16 = idx & 7;
            uint32_t sw = SW(row * 128 + c16 * 16);
            size_t g = (size_t)row * RS + c16 * 8;
            cp_async16(base + sw,        kh_g + g);
            cp_async16(base + 8192 + sw, vh_g + g);
        }
    };

    float o[8][4];
    #pragma unroll
    for (int nt = 0; nt < 8; nt++)
        #pragma unroll
        for (int e = 0; e < 4; e++) o[nt][e] = 0.f;
    float m0 = -CUDART_INF_F, m1 = -CUDART_INF_F, l0 = 0.f, l1 = 0.f;
    const int gr0 = qt * 128 + w * 16;            // warp's first global q row
    const int r0 = (lid >> 2);
    const int cbase = (lid & 3) << 1;

    const int kt_max = 2 * qt + 1;
    load_kv(0, 0); CP_COMMIT();

    for (int kt = 0; kt <= kt_max; kt++) {
        const int buf = kt & 1;
        const uint32_t tb = sb + (uint32_t)(buf * KVBUF);
        CP_WAIT0();
        __syncthreads();
        if (kt < kt_max) { load_kv(kt + 1, buf ^ 1); CP_COMMIT(); }

        if (kt * 64 <= gr0 + 15) {                // tile not fully masked
            // S = Qh Kh^T (1-combo)
            float s[8][4];
            #pragma unroll
            for (int nt = 0; nt < 8; nt++)
                #pragma unroll
                for (int e = 0; e < 4; e++) s[nt][e] = 0.f;

            #pragma unroll
            for (int ks = 0; ks < 4; ks++) {
                #pragma unroll
                for (int ntp = 0; ntp < 4; ntp++) {
                    int rowb = ntp * 16 + ((lid >> 4) << 3) + (lid & 7);
                    uint32_t offb = SW(rowb * 128 + ks * 32 + (((lid >> 3) & 1) << 4));
                    uint32_t kh[4];
                    ldsm_x4(tb + offb, kh[0], kh[1], kh[2], kh[3]);
                    mma_f16(s[ntp * 2],     qh[ks][0], qh[ks][1], qh[ks][2], qh[ks][3],
                            kh[0], kh[1]);
                    mma_f16(s[ntp * 2 + 1], qh[ks][0], qh[ks][1], qh[ks][2], qh[ks][3],
                            kh[2], kh[3]);
                }
            }

            // scale to log2 domain + causal mask
            #pragma unroll
            for (int nt = 0; nt < 8; nt++)
                #pragma unroll
                for (int e = 0; e < 4; e++) s[nt][e] *= SCL;
            if (kt * 64 + 63 > gr0) {
                #pragma unroll
                for (int nt = 0; nt < 8; nt++) {
                    int gc = kt * 64 + nt * 8 + cbase;
                    int gr = gr0 + r0;
                    if (gc     > gr)     s[nt][0] = -CUDART_INF_F;
                    if (gc + 1 > gr)     s[nt][1] = -CUDART_INF_F;
                    if (gc     > gr + 8) s[nt][2] = -CUDART_INF_F;
                    if (gc + 1 > gr + 8) s[nt][3] = -CUDART_INF_F;
                }
            }

            // online softmax (log2 domain; quad of 4 lanes shares a row)
            float mx0 = -CUDART_INF_F, mx1 = -CUDART_INF_F;
            #pragma unroll
            for (int nt = 0; nt < 8; nt++) {
                mx0 = fmaxf(mx0, fmaxf(s[nt][0], s[nt][1]));
                mx1 = fmaxf(mx1, fmaxf(s[nt][2], s[nt][3]));
            }
            mx0 = fmaxf(mx0, __shfl_xor_sync(0xffffffffu, mx0, 1));
            mx0 = fmaxf(mx0, __shfl_xor_sync(0xffffffffu, mx0, 2));
            mx1 = fmaxf(mx1, __shfl_xor_sync(0xffffffffu, mx1, 1));
            mx1 = fmaxf(mx1, __shfl_xor_sync(0xffffffffu, mx1, 2));
            float mn0 = fmaxf(m0, mx0), mn1 = fmaxf(m1, mx1);
            float a0 = exp2f(m0 - mn0), a1 = exp2f(m1 - mn1);
            float su0 = 0.f, su1 = 0.f;
            #pragma unroll
            for (int nt = 0; nt < 8; nt++) {
                s[nt][0] = exp2f(s[nt][0] - mn0);
                s[nt][1] = exp2f(s[nt][1] - mn0);
                s[nt][2] = exp2f(s[nt][2] - mn1);
                s[nt][3] = exp2f(s[nt][3] - mn1);
                su0 += s[nt][0] + s[nt][1];
                su1 += s[nt][2] + s[nt][3];
            }
            su0 += __shfl_xor_sync(0xffffffffu, su0, 1);
            su0 += __shfl_xor_sync(0xffffffffu, su0, 2);
            su1 += __shfl_xor_sync(0xffffffffu, su1, 1);
            su1 += __shfl_xor_sync(0xffffffffu, su1, 2);
            l0 = l0 * a0 + su0;  l1 = l1 * a1 + su1;
            m0 = mn0;  m1 = mn1;
            #pragma unroll
            for (int nt = 0; nt < 8; nt++) {
                o[nt][0] *= a0; o[nt][1] *= a0;
                o[nt][2] *= a1; o[nt][3] *= a1;
            }

            // PV: P hi; V hi via ldmatrix.x4.trans (1-combo)
            #pragma unroll
            for (int ks = 0; ks < 4; ks++) {
                const int t0 = ks * 2, t1 = ks * 2 + 1;
                uint32_t ph0 = pack_f16x2(s[t0][0], s[t0][1]);
                uint32_t ph1 = pack_f16x2(s[t0][2], s[t0][3]);
                uint32_t ph2 = pack_f16x2(s[t1][0], s[t1][1]);
                uint32_t ph3 = pack_f16x2(s[t1][2], s[t1][3]);
                int rowv = ks * 16 + (lid & 15);
                #pragma unroll
                for (int nt2 = 0; nt2 < 4; nt2++) {
                    uint32_t offv = SW(rowv * 128 + nt2 * 32 + ((lid >> 4) << 4));
                    uint32_t vh[4];
                    ldsm_x4t(tb + 8192 + offv, vh[0], vh[1], vh[2], vh[3]);
                    mma_f16(o[nt2 * 2],     ph0, ph1, ph2, ph3, vh[0], vh[1]);
                    mma_f16(o[nt2 * 2 + 1], ph0, ph1, ph2, ph3, vh[2], vh[3]);
                }
            }
        }
        __syncthreads();
    }

    // Epilogue: normalize, fp16 hi out
    float i0 = 1.f / l0, i1 = 1.f / l1;
    size_t row0 = (bT + (size_t)qt * 128 + w * 16 + r0) * CC + h * DH;
    size_t row1 = row0 + (size_t)8 * CC;
    #pragma unroll
    for (int nt = 0; nt < 8; nt++) {
        int n = nt * 8 + cbase;
        *(half2*)(yh + row0 + n) =
            __floats2half2_rn(o[nt][0] * i0, o[nt][1] * i0);
        *(half2*)(yh + row1 + n) =
            __floats2half2_rn(o[nt][2] * i1, o[nt][3] * i1);
    }
}

// ---------------------------------------------------------------------------
extern "C" void kernel_launch(void* const* d_in, const int* in_sizes, int n_in,
                              void* d_out, int out_size)
{
    const float* x      = (const float*)d_in[0];
    const float* W_attn = (const float*)d_in[1];
    const float* b_attn = (const float*)d_in[2];
    const float* W_proj = (const float*)d_in[3];
    const float* b_proj = (const float*)d_in[4];
    float* out = (float*)d_out;

    __half *xh, *qkvh, *yh, *wah, *wph;
    cudaGetSymbolAddress((void**)&xh, g_xh);
    cudaGetSymbolAddress((void**)&qkvh, g_qkvh);
    cudaGetSymbolAddress((void**)&yh, g_yh);
    cudaGetSymbolAddress((void**)&wah, g_wah);
    cudaGetSymbolAddress((void**)&wph, g_wph);

    const int M = BB * TT;       // 4096
    const int N1 = 3 * CC;       // 3072
    const int N2 = CC;           // 1024
    const int K = CC;            // 1024

    cudaFuncSetAttribute(gemm_mma<true>,
                         cudaFuncAttributeMaxDynamicSharedMemorySize, GSMEM);
    cudaFuncSetAttribute(gemm_mma<false>,
                         cudaFuncAttributeMaxDynamicSharedMemorySize, GSMEM);
    cudaFuncSetAttribute(attn_mma,
                         cudaFuncAttributeMaxDynamicSharedMemorySize, ATT_SMEM);

    // Prep: x -> fp16; weights -> transposed fp16
    cvt_half<<<(M * K / 2 + 255) / 256, 256>>>(x, xh, M * K / 2);
    {
        dim3 grid(N1 / 32, K / 32), blk(32, 8);
        cvt_t<<<grid, blk>>>(W_attn, wah, K, N1);
    }
    {
        dim3 grid(N2 / 32, K / 32), blk(32, 8);
        cvt_t<<<grid, blk>>>(W_proj, wph, K, N2);
    }

    // 1) qkv = x @ W_attn + b_attn  (fp16)
    {
        dim3 grid(N1 / 128, M / 128);
        gemm_mma<true><<<grid, 256, GSMEM>>>(xh, wah, b_attn,
                                             nullptr, qkvh, N1, K);
    }

    // 2) Flash attention -> y (fp16)
    {
        dim3 grid(TT / 128, HH, BB);
        attn_mma<<<grid, 256, ATT_SMEM>>>(qkvh, yh);
    }

    // 3) out = y @ W_proj + b_proj (fp32)
    {
        dim3 grid(N2 / 128, M / 128);
        gemm_mma<false><<<grid, 256, GSMEM>>>(yh, wph, b_proj,
                                              out, nullptr, N2, K);
    }
}

// round 10
// speedup vs baseline: 7.9538x; 1.0399x over previous
#include <cuda_runtime.h>
#include <cuda_fp16.h>
#include <math_constants.h>
#include <cstdint>

// Problem constants
#define TT 2048
#define CC 1024
#define HH 16
#define DH 64
#define BB 2

#define SW(off) ((uint32_t)(off) ^ ((((uint32_t)(off)) >> 3) & 0x70u))

// ---------------------------------------------------------------------------
// PTX helpers (base-target safe)
// ---------------------------------------------------------------------------
__device__ __forceinline__ uint32_t smem_u32(const void* p) {
    uint32_t a;
    asm("{ .reg .u64 t; cvta.to.shared.u64 t, %1; cvt.u32.u64 %0, t; }"
        : "=r"(a) : "l"(p));
    return a;
}
__device__ __forceinline__ void ldsm_x4(uint32_t addr, uint32_t &r0, uint32_t &r1,
                                        uint32_t &r2, uint32_t &r3) {
    asm volatile("ldmatrix.sync.aligned.m8n8.x4.shared.b16 {%0,%1,%2,%3}, [%4];"
                 : "=r"(r0), "=r"(r1), "=r"(r2), "=r"(r3) : "r"(addr));
}
__device__ __forceinline__ void ldsm_x4t(uint32_t addr, uint32_t &r0, uint32_t &r1,
                                         uint32_t &r2, uint32_t &r3) {
    asm volatile("ldmatrix.sync.aligned.m8n8.x4.trans.shared.b16 {%0,%1,%2,%3}, [%4];"
                 : "=r"(r0), "=r"(r1), "=r"(r2), "=r"(r3) : "r"(addr));
}
__device__ __forceinline__ void mma_f16(float* c, uint32_t a0, uint32_t a1,
                                        uint32_t a2, uint32_t a3,
                                        uint32_t b0, uint32_t b1) {
    asm volatile("mma.sync.aligned.m16n8k16.row.col.f32.f16.f16.f32 "
                 "{%0,%1,%2,%3}, {%4,%5,%6,%7}, {%8,%9}, {%0,%1,%2,%3};"
                 : "+f"(c[0]), "+f"(c[1]), "+f"(c[2]), "+f"(c[3])
                 : "r"(a0), "r"(a1), "r"(a2), "r"(a3), "r"(b0), "r"(b1));
}
__device__ __forceinline__ void cp_async16(uint32_t dst, const void* src) {
    asm volatile("cp.async.cg.shared.global [%0], [%1], 16;"
                 :: "r"(dst), "l"(src) : "memory");
}
#define CP_COMMIT() asm volatile("cp.async.commit_group;" ::: "memory")
#define CP_WAIT0()  asm volatile("cp.async.wait_group 0;" ::: "memory")
#define CP_WAIT1()  asm volatile("cp.async.wait_group 1;" ::: "memory")

__device__ __forceinline__ uint32_t pack_f16x2(float lo, float hi) {
    uint32_t d;
    asm("cvt.rn.f16x2.f32 %0, %1, %2;" : "=r"(d) : "f"(hi), "f"(lo));
    return d;
}

// ---------------------------------------------------------------------------
// Scratch
// ---------------------------------------------------------------------------
__device__ __half g_xh[(size_t)BB * TT * CC];
__device__ __half g_qkvh[(size_t)BB * TT * 3 * CC];
__device__ __half g_yh[(size_t)BB * TT * CC];
__device__ __half g_wah[(size_t)3 * CC * CC];          // W_attn^T [3C, C] fp16
__device__ __half g_wph[(size_t)CC * CC];              // W_proj^T [C, C]  fp16

// ---------------------------------------------------------------------------
// fp32 -> fp16 convert
// ---------------------------------------------------------------------------
__global__ __launch_bounds__(256) void cvt_half(
    const float* __restrict__ in, __half* __restrict__ h, int n2)
{
    int i = blockIdx.x * 256 + threadIdx.x;
    if (i >= n2) return;
    float2 v = ((const float2*)in)[i];
    ((half2*)h)[i] = __floats2half2_rn(v.x, v.y);
}

// ---------------------------------------------------------------------------
// fp32 [K,N] -> fp16 transposed [N,K]
// ---------------------------------------------------------------------------
__global__ __launch_bounds__(256) void cvt_t(
    const float* __restrict__ in, __half* __restrict__ h, int K, int N)
{
    __shared__ float ts[32][33];
    int tx = threadIdx.x, ty = threadIdx.y;   // (32, 8)
    int bx = blockIdx.x, by = blockIdx.y;
    #pragma unroll
    for (int j = 0; j < 4; j++) {
        int k = by * 32 + ty + j * 8;
        ts[ty + j * 8][tx] = in[(size_t)k * N + bx * 32 + tx];
    }
    __syncthreads();
    #pragma unroll
    for (int j = 0; j < 4; j++) {
        int nrow = bx * 32 + ty + j * 8;
        h[(size_t)nrow * K + by * 32 + tx] = __float2half(ts[tx][ty + j * 8]);
    }
}

// ---------------------------------------------------------------------------
// Tensor-core GEMM, fp16: C = Ah @ Bh^T + bias
// CTA 128x256, 8 warps of 64x64, k64 chunks, 3-stage cp.async, 1 CTA/SM.
// Stage (48KB): A 16KB @0 | B 32KB @16384 (128B rows, SW128)
// ---------------------------------------------------------------------------
#define STG_BYTES 49152
#define GSMEM (3 * STG_BYTES + 1024)

template<bool HALF_OUT>
__global__ __launch_bounds__(256, 1) void gemm_mma(
    const __half* __restrict__ Ah, const __half* __restrict__ Bh,
    const float* __restrict__ bias, float* __restrict__ Cf,
    __half* __restrict__ Ch, int Ncols, int K)
{
    extern __shared__ char dsm[];
    const uint32_t sb = (smem_u32(dsm) + 1023u) & ~1023u;

    const int tid = threadIdx.x;
    const int lid = tid & 31;
    const int wid = tid >> 5;
    const int wm = (wid >> 2) * 64;   // 0 or 64
    const int wn = (wid & 3) * 64;    // 0..192
    const int bm = blockIdx.y * 128;
    const int bn = blockIdx.x * 256;

    float c[4][8][4];
    #pragma unroll
    for (int mt = 0; mt < 4; mt++)
        #pragma unroll
        for (int nt = 0; nt < 8; nt++)
            #pragma unroll
            for (int e = 0; e < 4; e++) c[mt][nt][e] = 0.f;

    // one k64 chunk: A 1024 x 16B, B 2048 x 16B
    auto load_chunk = [&](int ch, int stg) {
        const int k0 = ch << 6;
        const uint32_t base = sb + (uint32_t)(stg * STG_BYTES);
        #pragma unroll
        for (int j = 0; j < 4; j++) {          // A
            int idx = tid + j * 256;           // 0..1023
            int row = idx >> 3, c16 = idx & 7;
            cp_async16(base + SW(row * 128 + c16 * 16),
                       Ah + (size_t)(bm + row) * K + k0 + c16 * 8);
        }
        #pragma unroll
        for (int j = 0; j < 8; j++) {          // B
            int idx = tid + j * 256;           // 0..2047
            int row = idx >> 3, c16 = idx & 7;
            cp_async16(base + 16384 + SW(row * 128 + c16 * 16),
                       Bh + (size_t)(bn + row) * K + k0 + c16 * 8);
        }
    };

    auto compute = [&](int stg) {
        const uint32_t tb = sb + (uint32_t)(stg * STG_BYTES);
        #pragma unroll
        for (int ks = 0; ks < 4; ks++) {
            uint32_t ah[4][4];
            #pragma unroll
            for (int mt = 0; mt < 4; mt++) {
                int row = wm + mt * 16 + (lid & 15);
                ldsm_x4(tb + SW(row * 128 + ks * 32 + ((lid >> 4) << 4)),
                        ah[mt][0], ah[mt][1], ah[mt][2], ah[mt][3]);
            }
            #pragma unroll
            for (int ntp = 0; ntp < 4; ntp++) {
                int rowb = wn + ntp * 16 + ((lid >> 4) << 3) + (lid & 7);
                uint32_t offb = SW(rowb * 128 + ks * 32 + (((lid >> 3) & 1) << 4));
                uint32_t bh[4];
                ldsm_x4(tb + 16384 + offb, bh[0], bh[1], bh[2], bh[3]);
                #pragma unroll
                for (int half = 0; half < 2; half++) {
                    int nt = ntp * 2 + half;
                    #pragma unroll
                    for (int mt = 0; mt < 4; mt++)
                        mma_f16(c[mt][nt], ah[mt][0], ah[mt][1], ah[mt][2], ah[mt][3],
                                bh[half * 2], bh[half * 2 + 1]);
                }
            }
        }
    };

    const int nch = K >> 6;                 // 16 chunks for K=1024
    load_chunk(0, 0); CP_COMMIT();
    load_chunk(1, 1); CP_COMMIT();

    int stg = 0;
    for (int ch = 0; ch < nch; ch++) {
        if (ch + 2 < nch) CP_WAIT1(); else CP_WAIT0();
        __syncthreads();
        if (ch + 2 < nch) { load_chunk(ch + 2, (stg + 2) % 3); CP_COMMIT(); }
        compute(stg);
        stg = (stg + 1) % 3;
    }

    // Epilogue
    #pragma unroll
    for (int mt = 0; mt < 4; mt++) {
        #pragma unroll
        for (int nt = 0; nt < 8; nt++) {
            int m0 = bm + wm + mt * 16 + (lid >> 2);
            int n  = bn + wn + nt * 8 + ((lid & 3) << 1);
            float b0 = bias[n], b1 = bias[n + 1];
            float v00 = c[mt][nt][0] + b0, v01 = c[mt][nt][1] + b1;
            float v10 = c[mt][nt][2] + b0, v11 = c[mt][nt][3] + b1;
            if (HALF_OUT) {
                *(half2*)(Ch + (size_t)m0 * Ncols + n) =
                    __floats2half2_rn(v00, v01);
                *(half2*)(Ch + (size_t)(m0 + 8) * Ncols + n) =
                    __floats2half2_rn(v10, v11);
            } else {
                float2 p0 = {v00, v01}, p1 = {v10, v11};
                *(float2*)(Cf + (size_t)m0 * Ncols + n) = p0;
                *(float2*)(Cf + (size_t)(m0 + 8) * Ncols + n) = p1;
            }
        }
    }
}

// ---------------------------------------------------------------------------
// Flash attention (causal), fp16 1-combo: S = Qh Kh^T; O += Ph Vh.
// Block = (b, h, q-tile 128). 4 warps of 32 q-rows, 2 CTAs/SM,
// double-buffered K/V (16KB each: Kh 0 | Vh 8K). Softmax via exp2f.
// ---------------------------------------------------------------------------
#define KVBUF 16384
#define ATT_SMEM (1024 + 2 * KVBUF)

__global__ __launch_bounds__(128, 2) void attn_mma(
    const __half* __restrict__ qkvh, __half* __restrict__ yh)
{
    extern __shared__ char asm_[];
    const uint32_t sb = (smem_u32(asm_) + 1023u) & ~1023u;

    const int tid = threadIdx.x;
    const int lid = tid & 31;
    const int w = tid >> 5;                       // 0..3
    const int qt = gridDim.x - 1 - blockIdx.x;    // longest first
    const int h = blockIdx.y;
    const int b = blockIdx.z;
    const size_t bT = (size_t)b * TT;
    const int RS = 3 * CC;
    const float SCL = 0.18033688f;                // 0.125 * log2(e)

    // ---- stage Q hi (128 x 64 fp16 = 16KB) into buffer0, extract fragments
    {
        const __half* qg = qkvh + (bT + qt * 128) * RS + h * DH;
        #pragma unroll
        for (int j = 0; j < 8; j++) {
            int idx = tid + j * 128;              // 0..1023
            int row = idx >> 3, c16 = idx & 7;
            cp_async16(sb + SW(row * 128 + c16 * 16),
                       qg + (size_t)row * RS + c16 * 8);
        }
    }
    CP_COMMIT(); CP_WAIT0();
    __syncthreads();
    uint32_t qh[2][4][4];                          // [mt][ks][frag]
    #pragma unroll
    for (int mt = 0; mt < 2; mt++)
        #pragma unroll
        for (int ks = 0; ks < 4; ks++) {
            int row = w * 32 + mt * 16 + (lid & 15);
            ldsm_x4(sb + SW(row * 128 + ks * 32 + ((lid >> 4) << 4)),
                    qh[mt][ks][0], qh[mt][ks][1], qh[mt][ks][2], qh[mt][ks][3]);
        }
    __syncthreads();

    auto load_kv = [&](int kt, int buf) {
        const __half* kh_g = qkvh + (bT + kt * 64) * RS + CC + h * DH;
        const __half* vh_g = kh_g + CC;
        const uint32_t base = sb + (uint32_t)(buf * KVBUF);
        #pragma unroll
        for (int j = 0; j < 8; j++) {
            int idx = tid + j * 128;              // 0..1023
            int half = idx >> 9;                   // 0=K, 1=V
            int r = idx & 511;
            int row = r >> 3, c16 = r & 7;
            uint32_t sw = SW(row * 128 + c16 * 16);
            const __half* src = (half ? vh_g : kh_g) + (size_t)row * RS + c16 * 8;
            cp_async16(base + (uint32_t)(half << 13) + sw, src);
        }
    };

    float o[2][8][4];
    #pragma unroll
    for (int mt = 0; mt < 2; mt++)
        #pragma unroll
        for (int nt = 0; nt < 8; nt++)
            #pragma unroll
            for (int e = 0; e < 4; e++) o[mt][nt][e] = 0.f;
    float m[2][2], l[2][2];
    #pragma unroll
    for (int mt = 0; mt < 2; mt++) {
        m[mt][0] = -CUDART_INF_F; m[mt][1] = -CUDART_INF_F;
        l[mt][0] = 0.f; l[mt][1] = 0.f;
    }
    const int gr0 = qt * 128 + w * 32;            // warp's first global q row
    const int r0 = (lid >> 2);
    const int cbase = (lid & 3) << 1;

    const int kt_max = 2 * qt + 1;
    load_kv(0, 0); CP_COMMIT();

    for (int kt = 0; kt <= kt_max; kt++) {
        const int buf = kt & 1;
        const uint32_t tb = sb + (uint32_t)(buf * KVBUF);
        CP_WAIT0();
        __syncthreads();
        if (kt < kt_max) { load_kv(kt + 1, buf ^ 1); CP_COMMIT(); }

        if (kt * 64 <= gr0 + 31) {                // tile not fully masked
            // S = Qh Kh^T  (32 x 64 per warp)
            float s[2][8][4];
            #pragma unroll
            for (int mt = 0; mt < 2; mt++)
                #pragma unroll
                for (int nt = 0; nt < 8; nt++)
                    #pragma unroll
                    for (int e = 0; e < 4; e++) s[mt][nt][e] = 0.f;

            #pragma unroll
            for (int ks = 0; ks < 4; ks++) {
                #pragma unroll
                for (int ntp = 0; ntp < 4; ntp++) {
                    int rowb = ntp * 16 + ((lid >> 4) << 3) + (lid & 7);
                    uint32_t offb = SW(rowb * 128 + ks * 32 + (((lid >> 3) & 1) << 4));
                    uint32_t kh[4];
                    ldsm_x4(tb + offb, kh[0], kh[1], kh[2], kh[3]);
                    #pragma unroll
                    for (int half = 0; half < 2; half++) {
                        int nt = ntp * 2 + half;
                        #pragma unroll
                        for (int mt = 0; mt < 2; mt++)
                            mma_f16(s[mt][nt],
                                    qh[mt][ks][0], qh[mt][ks][1],
                                    qh[mt][ks][2], qh[mt][ks][3],
                                    kh[half * 2], kh[half * 2 + 1]);
                    }
                }
            }

            // scale to log2 domain + causal mask
            #pragma unroll
            for (int mt = 0; mt < 2; mt++)
                #pragma unroll
                for (int nt = 0; nt < 8; nt++)
                    #pragma unroll
                    for (int e = 0; e < 4; e++) s[mt][nt][e] *= SCL;
            if (kt * 64 + 63 > gr0) {
                #pragma unroll
                for (int mt = 0; mt < 2; mt++) {
                    int gr = gr0 + mt * 16 + r0;
                    #pragma unroll
                    for (int nt = 0; nt < 8; nt++) {
                        int gc = kt * 64 + nt * 8 + cbase;
                        if (gc     > gr)     s[mt][nt][0] = -CUDART_INF_F;
                        if (gc + 1 > gr)     s[mt][nt][1] = -CUDART_INF_F;
                        if (gc     > gr + 8) s[mt][nt][2] = -CUDART_INF_F;
                        if (gc + 1 > gr + 8) s[mt][nt][3] = -CUDART_INF_F;
                    }
                }
            }

            // online softmax (log2 domain; quad of 4 lanes shares a row)
            #pragma unroll
            for (int mt = 0; mt < 2; mt++) {
                float mx0 = -CUDART_INF_F, mx1 = -CUDART_INF_F;
                #pragma unroll
                for (int nt = 0; nt < 8; nt++) {
                    mx0 = fmaxf(mx0, fmaxf(s[mt][nt][0], s[mt][nt][1]));
                    mx1 = fmaxf(mx1, fmaxf(s[mt][nt][2], s[mt][nt][3]));
                }
                mx0 = fmaxf(mx0, __shfl_xor_sync(0xffffffffu, mx0, 1));
                mx0 = fmaxf(mx0, __shfl_xor_sync(0xffffffffu, mx0, 2));
                mx1 = fmaxf(mx1, __shfl_xor_sync(0xffffffffu, mx1, 1));
                mx1 = fmaxf(mx1, __shfl_xor_sync(0xffffffffu, mx1, 2));
                float mn0 = fmaxf(m[mt][0], mx0), mn1 = fmaxf(m[mt][1], mx1);
                float a0 = exp2f(m[mt][0] - mn0), a1 = exp2f(m[mt][1] - mn1);
                float su0 = 0.f, su1 = 0.f;
                #pragma unroll
                for (int nt = 0; nt < 8; nt++) {
                    s[mt][nt][0] = exp2f(s[mt][nt][0] - mn0);
                    s[mt][nt][1] = exp2f(s[mt][nt][1] - mn0);
                    s[mt][nt][2] = exp2f(s[mt][nt][2] - mn1);
                    s[mt][nt][3] = exp2f(s[mt][nt][3] - mn1);
                    su0 += s[mt][nt][0] + s[mt][nt][1];
                    su1 += s[mt][nt][2] + s[mt][nt][3];
                }
                su0 += __shfl_xor_sync(0xffffffffu, su0, 1);
                su0 += __shfl_xor_sync(0xffffffffu, su0, 2);
                su1 += __shfl_xor_sync(0xffffffffu, su1, 1);
                su1 += __shfl_xor_sync(0xffffffffu, su1, 2);
                l[mt][0] = l[mt][0] * a0 + su0;
                l[mt][1] = l[mt][1] * a1 + su1;
                m[mt][0] = mn0;  m[mt][1] = mn1;
                #pragma unroll
                for (int nt = 0; nt < 8; nt++) {
                    o[mt][nt][0] *= a0; o[mt][nt][1] *= a0;
                    o[mt][nt][2] *= a1; o[mt][nt][3] *= a1;
                }
            }

            // PV: P from S regs; V via ldmatrix.x4.trans, shared across mt
            #pragma unroll
            for (int ks = 0; ks < 4; ks++) {
                uint32_t ph[2][4];
                #pragma unroll
                for (int mt = 0; mt < 2; mt++) {
                    const int t0 = ks * 2, t1 = ks * 2 + 1;
                    ph[mt][0] = pack_f16x2(s[mt][t0][0], s[mt][t0][1]);
                    ph[mt][1] = pack_f16x2(s[mt][t0][2], s[mt][t0][3]);
                    ph[mt][2] = pack_f16x2(s[mt][t1][0], s[mt][t1][1]);
                    ph[mt][3] = pack_f16x2(s[mt][t1][2], s[mt][t1][3]);
                }
                int rowv = ks * 16 + (lid & 15);
                #pragma unroll
                for (int nt2 = 0; nt2 < 4; nt2++) {
                    uint32_t offv = SW(rowv * 128 + nt2 * 32 + ((lid >> 4) << 4));
                    uint32_t vh[4];
                    ldsm_x4t(tb + 8192 + offv, vh[0], vh[1], vh[2], vh[3]);
                    #pragma unroll
                    for (int mt = 0; mt < 2; mt++) {
                        mma_f16(o[mt][nt2 * 2],     ph[mt][0], ph[mt][1],
                                ph[mt][2], ph[mt][3], vh[0], vh[1]);
                        mma_f16(o[mt][nt2 * 2 + 1], ph[mt][0], ph[mt][1],
                                ph[mt][2], ph[mt][3], vh[2], vh[3]);
                    }
                }
            }
        }
        __syncthreads();
    }

    // Epilogue: normalize, fp16 out
    #pragma unroll
    for (int mt = 0; mt < 2; mt++) {
        float i0 = 1.f / l[mt][0], i1 = 1.f / l[mt][1];
        size_t row0 = (bT + (size_t)(qt * 128 + w * 32 + mt * 16 + r0)) * CC + h * DH;
        size_t row1 = row0 + (size_t)8 * CC;
        #pragma unroll
        for (int nt = 0; nt < 8; nt++) {
            int n = nt * 8 + cbase;
            *(half2*)(yh + row0 + n) =
                __floats2half2_rn(o[mt][nt][0] * i0, o[mt][nt][1] * i0);
            *(half2*)(yh + row1 + n) =
                __floats2half2_rn(o[mt][nt][2] * i1, o[mt][nt][3] * i1);
        }
    }
}

// ---------------------------------------------------------------------------
extern "C" void kernel_launch(void* const* d_in, const int* in_sizes, int n_in,
                              void* d_out, int out_size)
{
    const float* x      = (const float*)d_in[0];
    const float* W_attn = (const float*)d_in[1];
    const float* b_attn = (const float*)d_in[2];
    const float* W_proj = (const float*)d_in[3];
    const float* b_proj = (const float*)d_in[4];
    float* out = (float*)d_out;

    __half *xh, *qkvh, *yh, *wah, *wph;
    cudaGetSymbolAddress((void**)&xh, g_xh);
    cudaGetSymbolAddress((void**)&qkvh, g_qkvh);
    cudaGetSymbolAddress((void**)&yh, g_yh);
    cudaGetSymbolAddress((void**)&wah, g_wah);
    cudaGetSymbolAddress((void**)&wph, g_wph);

    const int M = BB * TT;       // 4096
    const int N1 = 3 * CC;       // 3072
    const int N2 = CC;           // 1024
    const int K = CC;            // 1024

    cudaFuncSetAttribute(gemm_mma<true>,
                         cudaFuncAttributeMaxDynamicSharedMemorySize, GSMEM);
    cudaFuncSetAttribute(gemm_mma<false>,
                         cudaFuncAttributeMaxDynamicSharedMemorySize, GSMEM);
    cudaFuncSetAttribute(attn_mma,
                         cudaFuncAttributeMaxDynamicSharedMemorySize, ATT_SMEM);

    // Prep: x -> fp16; weights -> transposed fp16
    cvt_half<<<(M * K / 2 + 255) / 256, 256>>>(x, xh, M * K / 2);
    {
        dim3 grid(N1 / 32, K / 32), blk(32, 8);
        cvt_t<<<grid, blk>>>(W_attn, wah, K, N1);
    }
    {
        dim3 grid(N2 / 32, K / 32), blk(32, 8);
        cvt_t<<<grid, blk>>>(W_proj, wph, K, N2);
    }

    // 1) qkv = x @ W_attn + b_attn  (fp16)
    {
        dim3 grid(N1 / 256, M / 128);
        gemm_mma<true><<<grid, 256, GSMEM>>>(xh, wah, b_attn,
                                             nullptr, qkvh, N1, K);
    }

    // 2) Flash attention -> y (fp16)
    {
        dim3 grid(TT / 128, HH, BB);
        attn_mma<<<grid, 128, ATT_SMEM>>>(qkvh, yh);
    }

    // 3) out = y @ W_proj + b_proj (fp32)
    {
        dim3 grid(N2 / 256, M / 128);
        gemm_mma<false><<<grid, 256, GSMEM>>>(yh, wph, b_proj,
                                              out, nullptr, N2, K);
    }
}

// round 11
// speedup vs baseline: 8.5234x; 1.0716x over previous
#include <cuda_runtime.h>
#include <cuda_fp16.h>
#include <math_constants.h>
#include <cstdint>

// Problem constants
#define TT 2048
#define CC 1024
#define HH 16
#define DH 64
#define BB 2

#define SW(off) ((uint32_t)(off) ^ ((((uint32_t)(off)) >> 3) & 0x70u))

// ---------------------------------------------------------------------------
// PTX helpers (base-target safe)
// ---------------------------------------------------------------------------
__device__ __forceinline__ uint32_t smem_u32(const void* p) {
    uint32_t a;
    asm("{ .reg .u64 t; cvta.to.shared.u64 t, %1; cvt.u32.u64 %0, t; }"
        : "=r"(a) : "l"(p));
    return a;
}
__device__ __forceinline__ void ldsm_x4(uint32_t addr, uint32_t &r0, uint32_t &r1,
                                        uint32_t &r2, uint32_t &r3) {
    asm volatile("ldmatrix.sync.aligned.m8n8.x4.shared.b16 {%0,%1,%2,%3}, [%4];"
                 : "=r"(r0), "=r"(r1), "=r"(r2), "=r"(r3) : "r"(addr));
}
__device__ __forceinline__ void ldsm_x4t(uint32_t addr, uint32_t &r0, uint32_t &r1,
                                         uint32_t &r2, uint32_t &r3) {
    asm volatile("ldmatrix.sync.aligned.m8n8.x4.trans.shared.b16 {%0,%1,%2,%3}, [%4];"
                 : "=r"(r0), "=r"(r1), "=r"(r2), "=r"(r3) : "r"(addr));
}
__device__ __forceinline__ void mma_f16(float* c, uint32_t a0, uint32_t a1,
                                        uint32_t a2, uint32_t a3,
                                        uint32_t b0, uint32_t b1) {
    asm volatile("mma.sync.aligned.m16n8k16.row.col.f32.f16.f16.f32 "
                 "{%0,%1,%2,%3}, {%4,%5,%6,%7}, {%8,%9}, {%0,%1,%2,%3};"
                 : "+f"(c[0]), "+f"(c[1]), "+f"(c[2]), "+f"(c[3])
                 : "r"(a0), "r"(a1), "r"(a2), "r"(a3), "r"(b0), "r"(b1));
}
__device__ __forceinline__ void cp_async16(uint32_t dst, const void* src) {
    asm volatile("cp.async.cg.shared.global [%0], [%1], 16;"
                 :: "r"(dst), "l"(src) : "memory");
}
#define CP_COMMIT() asm volatile("cp.async.commit_group;" ::: "memory")
#define CP_WAIT0()  asm volatile("cp.async.wait_group 0;" ::: "memory")
#define CP_WAIT1()  asm volatile("cp.async.wait_group 1;" ::: "memory")

__device__ __forceinline__ uint32_t pack_f16x2(float lo, float hi) {
    uint32_t d;
    asm("cvt.rn.f16x2.f32 %0, %1, %2;" : "=r"(d) : "f"(hi), "f"(lo));
    return d;
}
__device__ __forceinline__ uint32_t ex2_f16x2(uint32_t a) {
    uint32_t d;
    asm("ex2.approx.f16x2 %0, %1;" : "=r"(d) : "r"(a));
    return d;
}

// ---------------------------------------------------------------------------
// Scratch
// ---------------------------------------------------------------------------
__device__ __half g_xh[(size_t)BB * TT * CC];
__device__ __half g_qkvh[(size_t)BB * TT * 3 * CC];
__device__ __half g_yh[(size_t)BB * TT * CC];
__device__ __half g_wah[(size_t)3 * CC * CC];          // W_attn^T [3C, C] fp16
__device__ __half g_wph[(size_t)CC * CC];              // W_proj^T [C, C]  fp16

// ---------------------------------------------------------------------------
// fp32 -> fp16 convert
// ---------------------------------------------------------------------------
__global__ __launch_bounds__(256) void cvt_half(
    const float* __restrict__ in, __half* __restrict__ h, int n2)
{
    int i = blockIdx.x * 256 + threadIdx.x;
    if (i >= n2) return;
    float2 v = ((const float2*)in)[i];
    ((half2*)h)[i] = __floats2half2_rn(v.x, v.y);
}

// ---------------------------------------------------------------------------
// fp32 [K,N] -> fp16 transposed [N,K]
// ---------------------------------------------------------------------------
__global__ __launch_bounds__(256) void cvt_t(
    const float* __restrict__ in, __half* __restrict__ h, int K, int N)
{
    __shared__ float ts[32][33];
    int tx = threadIdx.x, ty = threadIdx.y;   // (32, 8)
    int bx = blockIdx.x, by = blockIdx.y;
    #pragma unroll
    for (int j = 0; j < 4; j++) {
        int k = by * 32 + ty + j * 8;
        ts[ty + j * 8][tx] = in[(size_t)k * N + bx * 32 + tx];
    }
    __syncthreads();
    #pragma unroll
    for (int j = 0; j < 4; j++) {
        int nrow = bx * 32 + ty + j * 8;
        h[(size_t)nrow * K + by * 32 + tx] = __float2half(ts[tx][ty + j * 8]);
    }
}

// ---------------------------------------------------------------------------
// Tensor-core GEMM, fp16: C = Ah @ Bh^T + bias
// CTA 128x256, 8 warps of 64x64, k64 chunks, 3-stage cp.async, 1 CTA/SM.
// ---------------------------------------------------------------------------
#define STG_BYTES 49152
#define GSMEM (3 * STG_BYTES + 1024)

template<bool HALF_OUT>
__global__ __launch_bounds__(256, 1) void gemm_mma(
    const __half* __restrict__ Ah, const __half* __restrict__ Bh,
    const float* __restrict__ bias, float* __restrict__ Cf,
    __half* __restrict__ Ch, int Ncols, int K)
{
    extern __shared__ char dsm[];
    const uint32_t sb = (smem_u32(dsm) + 1023u) & ~1023u;

    const int tid = threadIdx.x;
    const int lid = tid & 31;
    const int wid = tid >> 5;
    const int wm = (wid >> 2) * 64;
    const int wn = (wid & 3) * 64;
    const int bm = blockIdx.y * 128;
    const int bn = blockIdx.x * 256;

    float c[4][8][4];
    #pragma unroll
    for (int mt = 0; mt < 4; mt++)
        #pragma unroll
        for (int nt = 0; nt < 8; nt++)
            #pragma unroll
            for (int e = 0; e < 4; e++) c[mt][nt][e] = 0.f;

    auto load_chunk = [&](int ch, int stg) {
        const int k0 = ch << 6;
        const uint32_t base = sb + (uint32_t)(stg * STG_BYTES);
        #pragma unroll
        for (int j = 0; j < 4; j++) {          // A
            int idx = tid + j * 256;
            int row = idx >> 3, c16 = idx & 7;
            cp_async16(base + SW(row * 128 + c16 * 16),
                       Ah + (size_t)(bm + row) * K + k0 + c16 * 8);
        }
        #pragma unroll
        for (int j = 0; j < 8; j++) {          // B
            int idx = tid + j * 256;
            int row = idx >> 3, c16 = idx & 7;
            cp_async16(base + 16384 + SW(row * 128 + c16 * 16),
                       Bh + (size_t)(bn + row) * K + k0 + c16 * 8);
        }
    };

    auto compute = [&](int stg) {
        const uint32_t tb = sb + (uint32_t)(stg * STG_BYTES);
        #pragma unroll
        for (int ks = 0; ks < 4; ks++) {
            uint32_t ah[4][4];
            #pragma unroll
            for (int mt = 0; mt < 4; mt++) {
                int row = wm + mt * 16 + (lid & 15);
                ldsm_x4(tb + SW(row * 128 + ks * 32 + ((lid >> 4) << 4)),
                        ah[mt][0], ah[mt][1], ah[mt][2], ah[mt][3]);
            }
            #pragma unroll
            for (int ntp = 0; ntp < 4; ntp++) {
                int rowb = wn + ntp * 16 + ((lid >> 4) << 3) + (lid & 7);
                uint32_t offb = SW(rowb * 128 + ks * 32 + (((lid >> 3) & 1) << 4));
                uint32_t bh[4];
                ldsm_x4(tb + 16384 + offb, bh[0], bh[1], bh[2], bh[3]);
                #pragma unroll
                for (int half = 0; half < 2; half++) {
                    int nt = ntp * 2 + half;
                    #pragma unroll
                    for (int mt = 0; mt < 4; mt++)
                        mma_f16(c[mt][nt], ah[mt][0], ah[mt][1], ah[mt][2], ah[mt][3],
                                bh[half * 2], bh[half * 2 + 1]);
                }
            }
        }
    };

    const int nch = K >> 6;
    load_chunk(0, 0); CP_COMMIT();
    load_chunk(1, 1); CP_COMMIT();

    int stg = 0;
    for (int ch = 0; ch < nch; ch++) {
        if (ch + 2 < nch) CP_WAIT1(); else CP_WAIT0();
        __syncthreads();
        if (ch + 2 < nch) { load_chunk(ch + 2, (stg + 2) % 3); CP_COMMIT(); }
        compute(stg);
        stg = (stg + 1) % 3;
    }

    #pragma unroll
    for (int mt = 0; mt < 4; mt++) {
        #pragma unroll
        for (int nt = 0; nt < 8; nt++) {
            int m0 = bm + wm + mt * 16 + (lid >> 2);
            int n  = bn + wn + nt * 8 + ((lid & 3) << 1);
            float b0 = bias[n], b1 = bias[n + 1];
            float v00 = c[mt][nt][0] + b0, v01 = c[mt][nt][1] + b1;
            float v10 = c[mt][nt][2] + b0, v11 = c[mt][nt][3] + b1;
            if (HALF_OUT) {
                *(half2*)(Ch + (size_t)m0 * Ncols + n) =
                    __floats2half2_rn(v00, v01);
                *(half2*)(Ch + (size_t)(m0 + 8) * Ncols + n) =
                    __floats2half2_rn(v10, v11);
            } else {
                float2 p0 = {v00, v01}, p1 = {v10, v11};
                *(float2*)(Cf + (size_t)m0 * Ncols + n) = p0;
                *(float2*)(Cf + (size_t)(m0 + 8) * Ncols + n) = p1;
            }
        }
    }
}

// ---------------------------------------------------------------------------
// Flash attention (causal), fp16: S = Qh Kh^T; O += P Vh.
// Block = (b, h, q-tile 128). 4 warps of 32 q-rows, 2 CTAs/SM.
// 3-stage KV pipeline (16KB each: Kh 0 | Vh 8K).
// Softmax: P = ex2.approx.f16x2(pack(s*SCL - mn)); row-sums via ones-mma.
// ---------------------------------------------------------------------------
#define KVBUF 16384
#define ATT_SMEM (1024 + 3 * KVBUF)
#define ONES_F16X2 0x3C003C00u

__global__ __launch_bounds__(128, 2) void attn_mma(
    const __half* __restrict__ qkvh, __half* __restrict__ yh)
{
    extern __shared__ char asm_[];
    const uint32_t sb = (smem_u32(asm_) + 1023u) & ~1023u;

    const int tid = threadIdx.x;
    const int lid = tid & 31;
    const int w = tid >> 5;
    const int qt = gridDim.x - 1 - blockIdx.x;    // longest first
    const int h = blockIdx.y;
    const int b = blockIdx.z;
    const size_t bT = (size_t)b * TT;
    const int RS = 3 * CC;
    const float SCL = 0.18033688f;                // 0.125 * log2(e)

    // ---- stage Q (128 x 64 fp16 = 16KB) into buffer0, extract fragments
    {
        const __half* qg = qkvh + (bT + qt * 128) * RS + h * DH;
        #pragma unroll
        for (int j = 0; j < 8; j++) {
            int idx = tid + j * 128;
            int row = idx >> 3, c16 = idx & 7;
            cp_async16(sb + SW(row * 128 + c16 * 16),
                       qg + (size_t)row * RS + c16 * 8);
        }
    }
    CP_COMMIT(); CP_WAIT0();
    __syncthreads();
    uint32_t qh[2][4][4];
    #pragma unroll
    for (int mt = 0; mt < 2; mt++)
        #pragma unroll
        for (int ks = 0; ks < 4; ks++) {
            int row = w * 32 + mt * 16 + (lid & 15);
            ldsm_x4(sb + SW(row * 128 + ks * 32 + ((lid >> 4) << 4)),
                    qh[mt][ks][0], qh[mt][ks][1], qh[mt][ks][2], qh[mt][ks][3]);
        }
    __syncthreads();

    auto load_kv = [&](int kt, int buf) {
        const __half* kh_g = qkvh + (bT + kt * 64) * RS + CC + h * DH;
        const __half* vh_g = kh_g + CC;
        const uint32_t base = sb + (uint32_t)(buf * KVBUF);
        #pragma unroll
        for (int j = 0; j < 8; j++) {
            int idx = tid + j * 128;
            int half = idx >> 9;
            int r = idx & 511;
            int row = r >> 3, c16 = r & 7;
            uint32_t sw = SW(row * 128 + c16 * 16);
            const __half* src = (half ? vh_g : kh_g) + (size_t)row * RS + c16 * 8;
            cp_async16(base + (uint32_t)(half << 13) + sw, src);
        }
    };

    float o[2][8][4];
    #pragma unroll
    for (int mt = 0; mt < 2; mt++)
        #pragma unroll
        for (int nt = 0; nt < 8; nt++)
            #pragma unroll
            for (int e = 0; e < 4; e++) o[mt][nt][e] = 0.f;
    float m[2][2], l[2][2];
    #pragma unroll
    for (int mt = 0; mt < 2; mt++) {
        m[mt][0] = -CUDART_INF_F; m[mt][1] = -CUDART_INF_F;
        l[mt][0] = 0.f; l[mt][1] = 0.f;
    }
    const int gr0 = qt * 128 + w * 32;
    const int r0 = (lid >> 2);
    const int cbase = (lid & 3) << 1;

    const int kt_max = 2 * qt + 1;
    load_kv(0, 0); CP_COMMIT();
    if (kt_max >= 1) { load_kv(1, 1); CP_COMMIT(); }

    for (int kt = 0; kt <= kt_max; kt++) {
        const int buf = kt % 3;
        const uint32_t tb = sb + (uint32_t)(buf * KVBUF);
        if (kt + 1 <= kt_max) CP_WAIT1(); else CP_WAIT0();
        __syncthreads();
        if (kt + 2 <= kt_max) { load_kv(kt + 2, (kt + 2) % 3); CP_COMMIT(); }

        if (kt * 64 <= gr0 + 31) {                // tile not fully masked
            // S_raw = Qh Kh^T  (32 x 64 per warp)
            float s[2][8][4];
            #pragma unroll
            for (int mt = 0; mt < 2; mt++)
                #pragma unroll
                for (int nt = 0; nt < 8; nt++)
                    #pragma unroll
                    for (int e = 0; e < 4; e++) s[mt][nt][e] = 0.f;

            #pragma unroll
            for (int ks = 0; ks < 4; ks++) {
                #pragma unroll
                for (int ntp = 0; ntp < 4; ntp++) {
                    int rowb = ntp * 16 + ((lid >> 4) << 3) + (lid & 7);
                    uint32_t offb = SW(rowb * 128 + ks * 32 + (((lid >> 3) & 1) << 4));
                    uint32_t kh[4];
                    ldsm_x4(tb + offb, kh[0], kh[1], kh[2], kh[3]);
                    #pragma unroll
                    for (int half = 0; half < 2; half++) {
                        int nt = ntp * 2 + half;
                        #pragma unroll
                        for (int mt = 0; mt < 2; mt++)
                            mma_f16(s[mt][nt],
                                    qh[mt][ks][0], qh[mt][ks][1],
                                    qh[mt][ks][2], qh[mt][ks][3],
                                    kh[half * 2], kh[half * 2 + 1]);
                    }
                }
            }

            // causal mask on raw scores (diagonal-overlapping tiles only)
            if (kt * 64 + 63 > gr0) {
                #pragma unroll
                for (int mt = 0; mt < 2; mt++) {
                    int gr = gr0 + mt * 16 + r0;
                    #pragma unroll
                    for (int nt = 0; nt < 8; nt++) {
                        int gc = kt * 64 + nt * 8 + cbase;
                        if (gc     > gr)     s[mt][nt][0] = -CUDART_INF_F;
                        if (gc + 1 > gr)     s[mt][nt][1] = -CUDART_INF_F;
                        if (gc     > gr + 8) s[mt][nt][2] = -CUDART_INF_F;
                        if (gc + 1 > gr + 8) s[mt][nt][3] = -CUDART_INF_F;
                    }
                }
            }

            // row max (raw), new running max (log2 domain), alpha, o-rescale
            float mn[2][2], al[2][2];
            #pragma unroll
            for (int mt = 0; mt < 2; mt++) {
                float mx0 = -CUDART_INF_F, mx1 = -CUDART_INF_F;
                #pragma unroll
                for (int nt = 0; nt < 8; nt++) {
                    mx0 = fmaxf(mx0, fmaxf(s[mt][nt][0], s[mt][nt][1]));
                    mx1 = fmaxf(mx1, fmaxf(s[mt][nt][2], s[mt][nt][3]));
                }
                mx0 = fmaxf(mx0, __shfl_xor_sync(0xffffffffu, mx0, 1));
                mx0 = fmaxf(mx0, __shfl_xor_sync(0xffffffffu, mx0, 2));
                mx1 = fmaxf(mx1, __shfl_xor_sync(0xffffffffu, mx1, 1));
                mx1 = fmaxf(mx1, __shfl_xor_sync(0xffffffffu, mx1, 2));
                mn[mt][0] = fmaxf(m[mt][0], mx0 * SCL);
                mn[mt][1] = fmaxf(m[mt][1], mx1 * SCL);
                al[mt][0] = exp2f(m[mt][0] - mn[mt][0]);
                al[mt][1] = exp2f(m[mt][1] - mn[mt][1]);
                m[mt][0] = mn[mt][0];  m[mt][1] = mn[mt][1];
                #pragma unroll
                for (int nt = 0; nt < 8; nt++) {
                    o[mt][nt][0] *= al[mt][0]; o[mt][nt][1] *= al[mt][0];
                    o[mt][nt][2] *= al[mt][1]; o[mt][nt][3] *= al[mt][1];
                }
            }

            // PV with inline P = ex2(pack(s*SCL - mn)); row sums via ones-mma
            float ssum[2][4];
            #pragma unroll
            for (int mt = 0; mt < 2; mt++)
                #pragma unroll
                for (int e = 0; e < 4; e++) ssum[mt][e] = 0.f;

            #pragma unroll
            for (int ks = 0; ks < 4; ks++) {
                uint32_t ph[2][4];
                #pragma unroll
                for (int mt = 0; mt < 2; mt++) {
                    const int t0 = ks * 2, t1 = ks * 2 + 1;
                    float n0 = mn[mt][0], n1 = mn[mt][1];
                    ph[mt][0] = ex2_f16x2(pack_f16x2(
                        fmaf(s[mt][t0][0], SCL, -n0), fmaf(s[mt][t0][1], SCL, -n0)));
                    ph[mt][1] = ex2_f16x2(pack_f16x2(
                        fmaf(s[mt][t0][2], SCL, -n1), fmaf(s[mt][t0][3], SCL, -n1)));
                    ph[mt][2] = ex2_f16x2(pack_f16x2(
                        fmaf(s[mt][t1][0], SCL, -n0), fmaf(s[mt][t1][1], SCL, -n0)));
                    ph[mt][3] = ex2_f16x2(pack_f16x2(
                        fmaf(s[mt][t1][2], SCL, -n1), fmaf(s[mt][t1][3], SCL, -n1)));
                    // row sums: P x ones (fp32 accum, HW cross-lane reduce)
                    mma_f16(ssum[mt], ph[mt][0], ph[mt][1], ph[mt][2], ph[mt][3],
                            ONES_F16X2, ONES_F16X2);
                }
                int rowv = ks * 16 + (lid & 15);
                #pragma unroll
                for (int nt2 = 0; nt2 < 4; nt2++) {
                    uint32_t offv = SW(rowv * 128 + nt2 * 32 + ((lid >> 4) << 4));
                    uint32_t vh[4];
                    ldsm_x4t(tb + 8192 + offv, vh[0], vh[1], vh[2], vh[3]);
                    #pragma unroll
                    for (int mt = 0; mt < 2; mt++) {
                        mma_f16(o[mt][nt2 * 2],     ph[mt][0], ph[mt][1],
                                ph[mt][2], ph[mt][3], vh[0], vh[1]);
                        mma_f16(o[mt][nt2 * 2 + 1], ph[mt][0], ph[mt][1],
                                ph[mt][2], ph[mt][3], vh[2], vh[3]);
                    }
                }
            }

            // l update from mma row sums (d[0]=row r0 sum, d[2]=row r0+8 sum)
            #pragma unroll
            for (int mt = 0; mt < 2; mt++) {
                l[mt][0] = l[mt][0] * al[mt][0] + ssum[mt][0];
                l[mt][1] = l[mt][1] * al[mt][1] + ssum[mt][2];
            }
        }
        __syncthreads();
    }

    // Epilogue: normalize, fp16 out
    #pragma unroll
    for (int mt = 0; mt < 2; mt++) {
        float i0 = 1.f / l[mt][0], i1 = 1.f / l[mt][1];
        size_t row0 = (bT + (size_t)(qt * 128 + w * 32 + mt * 16 + r0)) * CC + h * DH;
        size_t row1 = row0 + (size_t)8 * CC;
        #pragma unroll
        for (int nt = 0; nt < 8; nt++) {
            int n = nt * 8 + cbase;
            *(half2*)(yh + row0 + n) =
                __floats2half2_rn(o[mt][nt][0] * i0, o[mt][nt][1] * i0);
            *(half2*)(yh + row1 + n) =
                __floats2half2_rn(o[mt][nt][2] * i1, o[mt][nt][3] * i1);
        }
    }
}

// ---------------------------------------------------------------------------
extern "C" void kernel_launch(void* const* d_in, const int* in_sizes, int n_in,
                              void* d_out, int out_size)
{
    const float* x      = (const float*)d_in[0];
    const float* W_attn = (const float*)d_in[1];
    const float* b_attn = (const float*)d_in[2];
    const float* W_proj = (const float*)d_in[3];
    const float* b_proj = (const float*)d_in[4];
    float* out = (float*)d_out;

    __half *xh, *qkvh, *yh, *wah, *wph;
    cudaGetSymbolAddress((void**)&xh, g_xh);
    cudaGetSymbolAddress((void**)&qkvh, g_qkvh);
    cudaGetSymbolAddress((void**)&yh, g_yh);
    cudaGetSymbolAddress((void**)&wah, g_wah);
    cudaGetSymbolAddress((void**)&wph, g_wph);

    const int M = BB * TT;       // 4096
    const int N1 = 3 * CC;       // 3072
    const int N2 = CC;           // 1024
    const int K = CC;            // 1024

    cudaFuncSetAttribute(gemm_mma<true>,
                         cudaFuncAttributeMaxDynamicSharedMemorySize, GSMEM);
    cudaFuncSetAttribute(gemm_mma<false>,
                         cudaFuncAttributeMaxDynamicSharedMemorySize, GSMEM);
    cudaFuncSetAttribute(attn_mma,
                         cudaFuncAttributeMaxDynamicSharedMemorySize, ATT_SMEM);

    // Prep: x -> fp16; weights -> transposed fp16
    cvt_half<<<(M * K / 2 + 255) / 256, 256>>>(x, xh, M * K / 2);
    {
        dim3 grid(N1 / 32, K / 32), blk(32, 8);
        cvt_t<<<grid, blk>>>(W_attn, wah, K, N1);
    }
    {
        dim3 grid(N2 / 32, K / 32), blk(32, 8);
        cvt_t<<<grid, blk>>>(W_proj, wph, K, N2);
    }

    // 1) qkv = x @ W_attn + b_attn  (fp16)
    {
        dim3 grid(N1 / 256, M / 128);
        gemm_mma<true><<<grid, 256, GSMEM>>>(xh, wah, b_attn,
                                             nullptr, qkvh, N1, K);
    }

    // 2) Flash attention -> y (fp16)
    {
        dim3 grid(TT / 128, HH, BB);
        attn_mma<<<grid, 128, ATT_SMEM>>>(qkvh, yh);
    }

    // 3) out = y @ W_proj + b_proj (fp32)
    {
        dim3 grid(N2 / 256, M / 128);
        gemm_mma<false><<<grid, 256, GSMEM>>>(yh, wph, b_proj,
                                              out, nullptr, N2, K);
    }
}

// round 12
// speedup vs baseline: 8.6131x; 1.0105x over previous
#include <cuda_runtime.h>
#include <cuda_fp16.h>
#include <math_constants.h>
#include <cstdint>

// Problem constants
#define TT 2048
#define CC 1024
#define HH 16
#define DH 64
#define BB 2

#define SW(off) ((uint32_t)(off) ^ ((((uint32_t)(off)) >> 3) & 0x70u))

// ---------------------------------------------------------------------------
// PTX helpers (base-target safe)
// ---------------------------------------------------------------------------
__device__ __forceinline__ uint32_t smem_u32(const void* p) {
    uint32_t a;
    asm("{ .reg .u64 t; cvta.to.shared.u64 t, %1; cvt.u32.u64 %0, t; }"
        : "=r"(a) : "l"(p));
    return a;
}
__device__ __forceinline__ void ldsm_x4(uint32_t addr, uint32_t &r0, uint32_t &r1,
                                        uint32_t &r2, uint32_t &r3) {
    asm volatile("ldmatrix.sync.aligned.m8n8.x4.shared.b16 {%0,%1,%2,%3}, [%4];"
                 : "=r"(r0), "=r"(r1), "=r"(r2), "=r"(r3) : "r"(addr));
}
__device__ __forceinline__ void ldsm_x4t(uint32_t addr, uint32_t &r0, uint32_t &r1,
                                         uint32_t &r2, uint32_t &r3) {
    asm volatile("ldmatrix.sync.aligned.m8n8.x4.trans.shared.b16 {%0,%1,%2,%3}, [%4];"
                 : "=r"(r0), "=r"(r1), "=r"(r2), "=r"(r3) : "r"(addr));
}
__device__ __forceinline__ void mma_f16(float* c, uint32_t a0, uint32_t a1,
                                        uint32_t a2, uint32_t a3,
                                        uint32_t b0, uint32_t b1) {
    asm volatile("mma.sync.aligned.m16n8k16.row.col.f32.f16.f16.f32 "
                 "{%0,%1,%2,%3}, {%4,%5,%6,%7}, {%8,%9}, {%0,%1,%2,%3};"
                 : "+f"(c[0]), "+f"(c[1]), "+f"(c[2]), "+f"(c[3])
                 : "r"(a0), "r"(a1), "r"(a2), "r"(a3), "r"(b0), "r"(b1));
}
__device__ __forceinline__ void cp_async16(uint32_t dst, const void* src) {
    asm volatile("cp.async.cg.shared.global [%0], [%1], 16;"
                 :: "r"(dst), "l"(src) : "memory");
}
#define CP_COMMIT() asm volatile("cp.async.commit_group;" ::: "memory")
#define CP_WAIT0()  asm volatile("cp.async.wait_group 0;" ::: "memory")
#define CP_WAIT1()  asm volatile("cp.async.wait_group 1;" ::: "memory")

__device__ __forceinline__ uint32_t pack_f16x2(float lo, float hi) {
    uint32_t d;
    asm("cvt.rn.f16x2.f32 %0, %1, %2;" : "=r"(d) : "f"(hi), "f"(lo));
    return d;
}
__device__ __forceinline__ uint32_t ex2_f16x2(uint32_t a) {
    uint32_t d;
    asm("ex2.approx.f16x2 %0, %1;" : "=r"(d) : "r"(a));
    return d;
}

// ---------------------------------------------------------------------------
// Scratch
// ---------------------------------------------------------------------------
__device__ __half g_xh[(size_t)BB * TT * CC];
__device__ __half g_qkvh[(size_t)BB * TT * 3 * CC];
__device__ __half g_yh[(size_t)BB * TT * CC];
__device__ __half g_wah[(size_t)3 * CC * CC];          // W_attn^T [3C, C] fp16
__device__ __half g_wph[(size_t)CC * CC];              // W_proj^T [C, C]  fp16

// ---------------------------------------------------------------------------
// fp32 -> fp16 convert
// ---------------------------------------------------------------------------
__global__ __launch_bounds__(256) void cvt_half(
    const float* __restrict__ in, __half* __restrict__ h, int n2)
{
    int i = blockIdx.x * 256 + threadIdx.x;
    if (i >= n2) return;
    float2 v = ((const float2*)in)[i];
    ((half2*)h)[i] = __floats2half2_rn(v.x, v.y);
}

// ---------------------------------------------------------------------------
// Both weights: fp32 [K,N] -> fp16 transposed [N,K], single launch.
// grid (96+32, 32), block (32,8). bx<96 -> W_attn; else W_proj.
// ---------------------------------------------------------------------------
__global__ __launch_bounds__(256) void cvt_t2(
    const float* __restrict__ Wa, __half* __restrict__ wah,
    const float* __restrict__ Wp, __half* __restrict__ wph)
{
    __shared__ float ts[32][33];
    int tx = threadIdx.x, ty = threadIdx.y;
    int bx = blockIdx.x, by = blockIdx.y;
    const float* in;
    __half* out;
    int N;
    if (bx < 96) { in = Wa; out = wah; N = 3 * CC; }
    else         { in = Wp; out = wph; N = CC; bx -= 96; }
    const int K = CC;
    #pragma unroll
    for (int j = 0; j < 4; j++) {
        int k = by * 32 + ty + j * 8;
        ts[ty + j * 8][tx] = in[(size_t)k * N + bx * 32 + tx];
    }
    __syncthreads();
    #pragma unroll
    for (int j = 0; j < 4; j++) {
        int nrow = bx * 32 + ty + j * 8;
        out[(size_t)nrow * K + by * 32 + tx] = __float2half(ts[tx][ty + j * 8]);
    }
}

// ---------------------------------------------------------------------------
// Tensor-core GEMM, fp16: C = Ah @ Bh^T + bias
// CTA 128x256, 8 warps of 64x64, k128 chunks (two 64-k sub-tiles each),
// 2-stage cp.async, 1 CTA/SM.
// Stage (96KB): A sub0 16K @0 | A sub1 @16K | B sub0 32K @32K | B sub1 @64K
// ---------------------------------------------------------------------------
#define STG_BYTES 98304
#define GSMEM (2 * STG_BYTES + 1024)

template<bool HALF_OUT>
__global__ __launch_bounds__(256, 1) void gemm_mma(
    const __half* __restrict__ Ah, const __half* __restrict__ Bh,
    const float* __restrict__ bias, float* __restrict__ Cf,
    __half* __restrict__ Ch, int Ncols, int K)
{
    extern __shared__ char dsm[];
    const uint32_t sb = (smem_u32(dsm) + 1023u) & ~1023u;

    const int tid = threadIdx.x;
    const int lid = tid & 31;
    const int wid = tid >> 5;
    const int wm = (wid >> 2) * 64;
    const int wn = (wid & 3) * 64;
    const int bm = blockIdx.y * 128;
    const int bn = blockIdx.x * 256;

    float c[4][8][4];
    #pragma unroll
    for (int mt = 0; mt < 4; mt++)
        #pragma unroll
        for (int nt = 0; nt < 8; nt++)
            #pragma unroll
            for (int e = 0; e < 4; e++) c[mt][nt][e] = 0.f;

    // one k128 chunk: A 128x128 (2048 x 16B), B 256x128 (4096 x 16B)
    auto load_chunk = [&](int ch, int stg) {
        const int k0 = ch << 7;
        const uint32_t base = sb + (uint32_t)(stg * STG_BYTES);
        #pragma unroll
        for (int j = 0; j < 8; j++) {          // A
            int idx = tid + j * 256;           // 0..2047
            int row = idx >> 4;
            int c16f = idx & 15;
            int sub = c16f >> 3, c16 = c16f & 7;
            cp_async16(base + (uint32_t)(sub << 14) + SW(row * 128 + c16 * 16),
                       Ah + (size_t)(bm + row) * K + k0 + sub * 64 + c16 * 8);
        }
        #pragma unroll
        for (int j = 0; j < 16; j++) {         // B
            int idx = tid + j * 256;           // 0..4095
            int row = idx >> 4;
            int c16f = idx & 15;
            int sub = c16f >> 3, c16 = c16f & 7;
            cp_async16(base + 32768u + (uint32_t)(sub << 15) + SW(row * 128 + c16 * 16),
                       Bh + (size_t)(bn + row) * K + k0 + sub * 64 + c16 * 8);
        }
    };

    auto compute = [&](int stg) {
        const uint32_t tb = sb + (uint32_t)(stg * STG_BYTES);
        #pragma unroll
        for (int ks = 0; ks < 8; ks++) {
            const int sub = ks >> 2, ksl = ks & 3;
            const uint32_t abase = tb + (uint32_t)(sub << 14);
            const uint32_t bbase = tb + 32768u + (uint32_t)(sub << 15);
            uint32_t ah[4][4];
            #pragma unroll
            for (int mt = 0; mt < 4; mt++) {
                int row = wm + mt * 16 + (lid & 15);
                ldsm_x4(abase + SW(row * 128 + ksl * 32 + ((lid >> 4) << 4)),
                        ah[mt][0], ah[mt][1], ah[mt][2], ah[mt][3]);
            }
            #pragma unroll
            for (int ntp = 0; ntp < 4; ntp++) {
                int rowb = wn + ntp * 16 + ((lid >> 4) << 3) + (lid & 7);
                uint32_t offb = SW(rowb * 128 + ksl * 32 + (((lid >> 3) & 1) << 4));
                uint32_t bh[4];
                ldsm_x4(bbase + offb, bh[0], bh[1], bh[2], bh[3]);
                #pragma unroll
                for (int half = 0; half < 2; half++) {
                    int nt = ntp * 2 + half;
                    #pragma unroll
                    for (int mt = 0; mt < 4; mt++)
                        mma_f16(c[mt][nt], ah[mt][0], ah[mt][1], ah[mt][2], ah[mt][3],
                                bh[half * 2], bh[half * 2 + 1]);
                }
            }
        }
    };

    const int nch = K >> 7;                 // 8 chunks for K=1024
    load_chunk(0, 0); CP_COMMIT();

    for (int ch = 0; ch < nch; ch++) {
        CP_WAIT0();
        __syncthreads();                     // all warps done with compute(ch-1)
        if (ch + 1 < nch) { load_chunk(ch + 1, (ch + 1) & 1); CP_COMMIT(); }
        compute(ch & 1);
    }

    // Epilogue
    #pragma unroll
    for (int mt = 0; mt < 4; mt++) {
        #pragma unroll
        for (int nt = 0; nt < 8; nt++) {
            int m0 = bm + wm + mt * 16 + (lid >> 2);
            int n  = bn + wn + nt * 8 + ((lid & 3) << 1);
            float b0 = bias[n], b1 = bias[n + 1];
            float v00 = c[mt][nt][0] + b0, v01 = c[mt][nt][1] + b1;
            float v10 = c[mt][nt][2] + b0, v11 = c[mt][nt][3] + b1;
            if (HALF_OUT) {
                *(half2*)(Ch + (size_t)m0 * Ncols + n) =
                    __floats2half2_rn(v00, v01);
                *(half2*)(Ch + (size_t)(m0 + 8) * Ncols + n) =
                    __floats2half2_rn(v10, v11);
            } else {
                float2 p0 = {v00, v01}, p1 = {v10, v11};
                *(float2*)(Cf + (size_t)m0 * Ncols + n) = p0;
                *(float2*)(Cf + (size_t)(m0 + 8) * Ncols + n) = p1;
            }
        }
    }
}

// ---------------------------------------------------------------------------
// Flash attention (causal), fp16: S = Qh Kh^T; O += P Vh.
// Block = (b, h, q-tile 128). 4 warps of 32 q-rows, 2 CTAs/SM.
// 3-stage KV pipeline (16KB each: Kh 0 | Vh 8K).
// Softmax: P = ex2.approx.f16x2(pack(s*SCL - mn)); row-sums via ones-mma.
// ---------------------------------------------------------------------------
#define KVBUF 16384
#define ATT_SMEM (1024 + 3 * KVBUF)
#define ONES_F16X2 0x3C003C00u

__global__ __launch_bounds__(128, 2) void attn_mma(
    const __half* __restrict__ qkvh, __half* __restrict__ yh)
{
    extern __shared__ char asm_[];
    const uint32_t sb = (smem_u32(asm_) + 1023u) & ~1023u;

    const int tid = threadIdx.x;
    const int lid = tid & 31;
    const int w = tid >> 5;
    const int qt = gridDim.x - 1 - blockIdx.x;    // longest first
    const int h = blockIdx.y;
    const int b = blockIdx.z;
    const size_t bT = (size_t)b * TT;
    const int RS = 3 * CC;
    const float SCL = 0.18033688f;                // 0.125 * log2(e)

    // ---- stage Q (128 x 64 fp16 = 16KB) into buffer0, extract fragments
    {
        const __half* qg = qkvh + (bT + qt * 128) * RS + h * DH;
        #pragma unroll
        for (int j = 0; j < 8; j++) {
            int idx = tid + j * 128;
            int row = idx >> 3, c16 = idx & 7;
            cp_async16(sb + SW(row * 128 + c16 * 16),
                       qg + (size_t)row * RS + c16 * 8);
        }
    }
    CP_COMMIT(); CP_WAIT0();
    __syncthreads();
    uint32_t qh[2][4][4];
    #pragma unroll
    for (int mt = 0; mt < 2; mt++)
        #pragma unroll
        for (int ks = 0; ks < 4; ks++) {
            int row = w * 32 + mt * 16 + (lid & 15);
            ldsm_x4(sb + SW(row * 128 + ks * 32 + ((lid >> 4) << 4)),
                    qh[mt][ks][0], qh[mt][ks][1], qh[mt][ks][2], qh[mt][ks][3]);
        }
    __syncthreads();

    auto load_kv = [&](int kt, int buf) {
        const __half* kh_g = qkvh + (bT + kt * 64) * RS + CC + h * DH;
        const __half* vh_g = kh_g + CC;
        const uint32_t base = sb + (uint32_t)(buf * KVBUF);
        #pragma unroll
        for (int j = 0; j < 8; j++) {
            int idx = tid + j * 128;
            int half = idx >> 9;
            int r = idx & 511;
            int row = r >> 3, c16 = r & 7;
            uint32_t sw = SW(row * 128 + c16 * 16);
            const __half* src = (half ? vh_g : kh_g) + (size_t)row * RS + c16 * 8;
            cp_async16(base + (uint32_t)(half << 13) + sw, src);
        }
    };

    float o[2][8][4];
    #pragma unroll
    for (int mt = 0; mt < 2; mt++)
        #pragma unroll
        for (int nt = 0; nt < 8; nt++)
            #pragma unroll
            for (int e = 0; e < 4; e++) o[mt][nt][e] = 0.f;
    float m[2][2], l[2][2];
    #pragma unroll
    for (int mt = 0; mt < 2; mt++) {
        m[mt][0] = -CUDART_INF_F; m[mt][1] = -CUDART_INF_F;
        l[mt][0] = 0.f; l[mt][1] = 0.f;
    }
    const int gr0 = qt * 128 + w * 32;
    const int r0 = (lid >> 2);
    const int cbase = (lid & 3) << 1;

    const int kt_max = 2 * qt + 1;
    load_kv(0, 0); CP_COMMIT();
    if (kt_max >= 1) { load_kv(1, 1); CP_COMMIT(); }

    for (int kt = 0; kt <= kt_max; kt++) {
        const int buf = kt % 3;
        const uint32_t tb = sb + (uint32_t)(buf * KVBUF);
        if (kt + 1 <= kt_max) CP_WAIT1(); else CP_WAIT0();
        __syncthreads();
        if (kt + 2 <= kt_max) { load_kv(kt + 2, (kt + 2) % 3); CP_COMMIT(); }

        if (kt * 64 <= gr0 + 31) {                // tile not fully masked
            // S_raw = Qh Kh^T  (32 x 64 per warp)
            float s[2][8][4];
            #pragma unroll
            for (int mt = 0; mt < 2; mt++)
                #pragma unroll
                for (int nt = 0; nt < 8; nt++)
                    #pragma unroll
                    for (int e = 0; e < 4; e++) s[mt][nt][e] = 0.f;

            #pragma unroll
            for (int ks = 0; ks < 4; ks++) {
                #pragma unroll
                for (int ntp = 0; ntp < 4; ntp++) {
                    int rowb = ntp * 16 + ((lid >> 4) << 3) + (lid & 7);
                    uint32_t offb = SW(rowb * 128 + ks * 32 + (((lid >> 3) & 1) << 4));
                    uint32_t kh[4];
                    ldsm_x4(tb + offb, kh[0], kh[1], kh[2], kh[3]);
                    #pragma unroll
                    for (int half = 0; half < 2; half++) {
                        int nt = ntp * 2 + half;
                        #pragma unroll
                        for (int mt = 0; mt < 2; mt++)
                            mma_f16(s[mt][nt],
                                    qh[mt][ks][0], qh[mt][ks][1],
                                    qh[mt][ks][2], qh[mt][ks][3],
                                    kh[half * 2], kh[half * 2 + 1]);
                    }
                }
            }

            // causal mask on raw scores (diagonal-overlapping tiles only)
            if (kt * 64 + 63 > gr0) {
                #pragma unroll
                for (int mt = 0; mt < 2; mt++) {
                    int gr = gr0 + mt * 16 + r0;
                    #pragma unroll
                    for (int nt = 0; nt < 8; nt++) {
                        int gc = kt * 64 + nt * 8 + cbase;
                        if (gc     > gr)     s[mt][nt][0] = -CUDART_INF_F;
                        if (gc + 1 > gr)     s[mt][nt][1] = -CUDART_INF_F;
                        if (gc     > gr + 8) s[mt][nt][2] = -CUDART_INF_F;
                        if (gc + 1 > gr + 8) s[mt][nt][3] = -CUDART_INF_F;
                    }
                }
            }

            // row max (raw), running max (log2 domain), alpha, o-rescale
            float mn[2][2], al[2][2];
            #pragma unroll
            for (int mt = 0; mt < 2; mt++) {
                float mx0 = -CUDART_INF_F, mx1 = -CUDART_INF_F;
                #pragma unroll
                for (int nt = 0; nt < 8; nt++) {
                    mx0 = fmaxf(mx0, fmaxf(s[mt][nt][0], s[mt][nt][1]));
                    mx1 = fmaxf(mx1, fmaxf(s[mt][nt][2], s[mt][nt][3]));
                }
                mx0 = fmaxf(mx0, __shfl_xor_sync(0xffffffffu, mx0, 1));
                mx0 = fmaxf(mx0, __shfl_xor_sync(0xffffffffu, mx0, 2));
                mx1 = fmaxf(mx1, __shfl_xor_sync(0xffffffffu, mx1, 1));
                mx1 = fmaxf(mx1, __shfl_xor_sync(0xffffffffu, mx1, 2));
                mn[mt][0] = fmaxf(m[mt][0], mx0 * SCL);
                mn[mt][1] = fmaxf(m[mt][1], mx1 * SCL);
                al[mt][0] = exp2f(m[mt][0] - mn[mt][0]);
                al[mt][1] = exp2f(m[mt][1] - mn[mt][1]);
                m[mt][0] = mn[mt][0];  m[mt][1] = mn[mt][1];
                #pragma unroll
                for (int nt = 0; nt < 8; nt++) {
                    o[mt][nt][0] *= al[mt][0]; o[mt][nt][1] *= al[mt][0];
                    o[mt][nt][2] *= al[mt][1]; o[mt][nt][3] *= al[mt][1];
                }
            }

            // PV with inline P = ex2(pack(s*SCL - mn)); row sums via ones-mma
            float ssum[2][4];
            #pragma unroll
            for (int mt = 0; mt < 2; mt++)
                #pragma unroll
                for (int e = 0; e < 4; e++) ssum[mt][e] = 0.f;

            #pragma unroll
            for (int ks = 0; ks < 4; ks++) {
                uint32_t ph[2][4];
                #pragma unroll
                for (int mt = 0; mt < 2; mt++) {
                    const int t0 = ks * 2, t1 = ks * 2 + 1;
                    float n0 = mn[mt][0], n1 = mn[mt][1];
                    ph[mt][0] = ex2_f16x2(pack_f16x2(
                        fmaf(s[mt][t0][0], SCL, -n0), fmaf(s[mt][t0][1], SCL, -n0)));
                    ph[mt][1] = ex2_f16x2(pack_f16x2(
                        fmaf(s[mt][t0][2], SCL, -n1), fmaf(s[mt][t0][3], SCL, -n1)));
                    ph[mt][2] = ex2_f16x2(pack_f16x2(
                        fmaf(s[mt][t1][0], SCL, -n0), fmaf(s[mt][t1][1], SCL, -n0)));
                    ph[mt][3] = ex2_f16x2(pack_f16x2(
                        fmaf(s[mt][t1][2], SCL, -n1), fmaf(s[mt][t1][3], SCL, -n1)));
                    mma_f16(ssum[mt], ph[mt][0], ph[mt][1], ph[mt][2], ph[mt][3],
                            ONES_F16X2, ONES_F16X2);
                }
                int rowv = ks * 16 + (lid & 15);
                #pragma unroll
                for (int nt2 = 0; nt2 < 4; nt2++) {
                    uint32_t offv = SW(rowv * 128 + nt2 * 32 + ((lid >> 4) << 4));
                    uint32_t vh[4];
                    ldsm_x4t(tb + 8192 + offv, vh[0], vh[1], vh[2], vh[3]);
                    #pragma unroll
                    for (int mt = 0; mt < 2; mt++) {
                        mma_f16(o[mt][nt2 * 2],     ph[mt][0], ph[mt][1],
                                ph[mt][2], ph[mt][3], vh[0], vh[1]);
                        mma_f16(o[mt][nt2 * 2 + 1], ph[mt][0], ph[mt][1],
                                ph[mt][2], ph[mt][3], vh[2], vh[3]);
                    }
                }
            }

            #pragma unroll
            for (int mt = 0; mt < 2; mt++) {
                l[mt][0] = l[mt][0] * al[mt][0] + ssum[mt][0];
                l[mt][1] = l[mt][1] * al[mt][1] + ssum[mt][2];
            }
        }
        __syncthreads();
    }

    // Epilogue: normalize, fp16 out
    #pragma unroll
    for (int mt = 0; mt < 2; mt++) {
        float i0 = 1.f / l[mt][0], i1 = 1.f / l[mt][1];
        size_t row0 = (bT + (size_t)(qt * 128 + w * 32 + mt * 16 + r0)) * CC + h * DH;
        size_t row1 = row0 + (size_t)8 * CC;
        #pragma unroll
        for (int nt = 0; nt < 8; nt++) {
            int n = nt * 8 + cbase;
            *(half2*)(yh + row0 + n) =
                __floats2half2_rn(o[mt][nt][0] * i0, o[mt][nt][1] * i0);
            *(half2*)(yh + row1 + n) =
                __floats2half2_rn(o[mt][nt][2] * i1, o[mt][nt][3] * i1);
        }
    }
}

// ---------------------------------------------------------------------------
extern "C" void kernel_launch(void* const* d_in, const int* in_sizes, int n_in,
                              void* d_out, int out_size)
{
    const float* x      = (const float*)d_in[0];
    const float* W_attn = (const float*)d_in[1];
    const float* b_attn = (const float*)d_in[2];
    const float* W_proj = (const float*)d_in[3];
    const float* b_proj = (const float*)d_in[4];
    float* out = (float*)d_out;

    __half *xh, *qkvh, *yh, *wah, *wph;
    cudaGetSymbolAddress((void**)&xh, g_xh);
    cudaGetSymbolAddress((void**)&qkvh, g_qkvh);
    cudaGetSymbolAddress((void**)&yh, g_yh);
    cudaGetSymbolAddress((void**)&wah, g_wah);
    cudaGetSymbolAddress((void**)&wph, g_wph);

    const int M = BB * TT;       // 4096
    const int N1 = 3 * CC;       // 3072
    const int N2 = CC;           // 1024
    const int K = CC;            // 1024

    cudaFuncSetAttribute(gemm_mma<true>,
                         cudaFuncAttributeMaxDynamicSharedMemorySize, GSMEM);
    cudaFuncSetAttribute(gemm_mma<false>,
                         cudaFuncAttributeMaxDynamicSharedMemorySize, GSMEM);
    cudaFuncSetAttribute(attn_mma,
                         cudaFuncAttributeMaxDynamicSharedMemorySize, ATT_SMEM);

    // Prep: x -> fp16; both weights -> transposed fp16 (single launch)
    cvt_half<<<(M * K / 2 + 255) / 256, 256>>>(x, xh, M * K / 2);
    {
        dim3 grid(96 + 32, 32), blk(32, 8);
        cvt_t2<<<grid, blk>>>(W_attn, wah, W_proj, wph);
    }

    // 1) qkv = x @ W_attn + b_attn  (fp16)
    {
        dim3 grid(N1 / 256, M / 128);
        gemm_mma<true><<<grid, 256, GSMEM>>>(xh, wah, b_attn,
                                             nullptr, qkvh, N1, K);
    }

    // 2) Flash attention -> y (fp16)
    {
        dim3 grid(TT / 128, HH, BB);
        attn_mma<<<grid, 128, ATT_SMEM>>>(qkvh, yh);
    }

    // 3) out = y @ W_proj + b_proj (fp32)
    {
        dim3 grid(N2 / 256, M / 128);
        gemm_mma<false><<<grid, 256, GSMEM>>>(yh, wph, b_proj,
                                              out, nullptr, N2, K);
    }
}